// round 7
// baseline (speedup 1.0000x reference)
#include <cuda_runtime.h>
#include <stdint.h>
#include <math.h>

#define Nn 50000
#define Ee 800000
#define Gg 16
#define Dd 64
#define Hh 128

// Scratch (allocation-free: __device__ globals)
__device__ float g_agg[Nn * Dd];      // attention-weighted edge aggregate per node
__device__ float g_nagg[Gg * Dd];     // node aggregate per graph
__device__ float g_eagg[Gg * Dd];     // edge aggregate per graph
__device__ float g_U1e[Gg * Hh];      // be1 + u @ We1[192:256]
__device__ float g_U1a[Gg * Hh];      // ba1 + u @ Wa1[192:256]
__device__ float g_U1n[Gg * Hh];      // bn1 + u @ Wn1[128:192]
__device__ float g_Xs[(size_t)Nn * 256];  // [x@We1[0:64] | x@Wa1[0:64]]
__device__ float g_Xd[(size_t)Nn * 256];  // [x@We1[64:128] | x@Wa1[64:128]]
__device__ float g_Xn[(size_t)Nn * 128];  // x@Wn1[0:64]

// ---------------------------------------------------------------------------
// Packed fp32x2 helpers
// ---------------------------------------------------------------------------
__device__ __forceinline__ void fma2(uint64_t& d, uint64_t a, uint64_t b) {
    asm("fma.rn.f32x2 %0, %1, %2, %0;" : "+l"(d) : "l"(a), "l"(b));
}
__device__ __forceinline__ uint64_t add2(uint64_t a, uint64_t b) {
    uint64_t r; asm("add.rn.f32x2 %0, %1, %2;" : "=l"(r) : "l"(a), "l"(b)); return r;
}
__device__ __forceinline__ uint64_t rep2(float x) {
    uint64_t r; asm("mov.b64 %0, {%1, %1};" : "=l"(r) : "f"(x)); return r;
}
__device__ __forceinline__ float2 unpack2(uint64_t v) {
    float2 r; asm("mov.b64 {%0, %1}, %2;" : "=f"(r.x), "=f"(r.y) : "l"(v)); return r;
}
__device__ __forceinline__ void red4(float* p, float a, float b, float c, float d) {
    asm volatile("red.global.add.v4.f32 [%0], {%1,%2,%3,%4};"
                 :: "l"(p), "f"(a), "f"(b), "f"(c), "f"(d) : "memory");
}
__device__ __forceinline__ void cp16(float* smem_dst, const float* gsrc) {
    uint32_t s = (uint32_t)__cvta_generic_to_shared(smem_dst);
    asm volatile("cp.async.cg.shared.global [%0], [%1], 16;" :: "r"(s), "l"(gsrc));
}
__device__ __forceinline__ void cp_commit() { asm volatile("cp.async.commit_group;"); }
template<int N> __device__ __forceinline__ void cp_wait() {
    asm volatile("cp.async.wait_group %0;" :: "n"(N));
}

// ===========================================================================
// 256-thread helpers (node / prep kernels, R5-proven)
// ===========================================================================
__device__ __forceinline__ void stage_w1(const float* __restrict__ Wg, int kt,
                                         float* __restrict__ dst, int t) {
    const float* src = Wg + (size_t)kt * 32 * 128;
#pragma unroll
    for (int i = 0; i < 4; i++) {
        int idx = t + i * 256;
        int r = idx >> 5, c4 = (idx & 31) << 2;
        cp16(dst + r * 128 + c4, src + r * 128 + c4);
    }
}
__device__ __forceinline__ void stage_w2(const float* __restrict__ Wg, int kt,
                                         float* __restrict__ dst, int t) {
    const float* src = Wg + (size_t)kt * 64 * 64;
#pragma unroll
    for (int i = 0; i < 4; i++) {
        int idx = t + i * 256;
        int r = idx >> 4, c4 = (idx & 15) << 2;
        cp16(dst + r * 64 + c4, src + r * 64 + c4);
    }
}

template<int KTOT>
__device__ __forceinline__ void gemm_h(const float* __restrict__ A,
                                       const float* __restrict__ Wg,
                                       const uint64_t (&ini)[4][4],
                                       float* __restrict__ Hs,
                                       float* __restrict__ sW, int t)
{
    const int tx = t & 15, ty = t >> 4;
    uint64_t acc[4][4];
#pragma unroll
    for (int i = 0; i < 4; i++)
#pragma unroll
        for (int p = 0; p < 4; p++) acc[i][p] = ini[i][p];
    constexpr int NT = KTOT / 32;
    stage_w1(Wg, 0, sW, t);
    cp_commit();
#pragma unroll
    for (int kt = 0; kt < NT; kt++) {
        if (kt + 1 < NT) {
            stage_w1(Wg, kt + 1, sW + ((kt + 1) & 1) * 4096, t);
            cp_commit();
            cp_wait<1>();
        } else cp_wait<0>();
        __syncthreads();
        const float* W = sW + (kt & 1) * 4096;
#pragma unroll
        for (int kk = 0; kk < 32; kk++) {
            int k = kt * 32 + kk;
            float4 a = *(const float4*)(A + k * 64 + ((ty ^ ((k >> 2) & 15)) << 2));
            ulonglong2 w01 = *(const ulonglong2*)(W + kk * 128 + tx * 8);
            ulonglong2 w23 = *(const ulonglong2*)(W + kk * 128 + tx * 8 + 4);
            uint64_t a0 = rep2(a.x), a1 = rep2(a.y), a2 = rep2(a.z), a3 = rep2(a.w);
            fma2(acc[0][0], a0, w01.x); fma2(acc[0][1], a0, w01.y);
            fma2(acc[0][2], a0, w23.x); fma2(acc[0][3], a0, w23.y);
            fma2(acc[1][0], a1, w01.x); fma2(acc[1][1], a1, w01.y);
            fma2(acc[1][2], a1, w23.x); fma2(acc[1][3], a1, w23.y);
            fma2(acc[2][0], a2, w01.x); fma2(acc[2][1], a2, w01.y);
            fma2(acc[2][2], a2, w23.x); fma2(acc[2][3], a2, w23.y);
            fma2(acc[3][0], a3, w01.x); fma2(acc[3][1], a3, w01.y);
            fma2(acc[3][2], a3, w23.x); fma2(acc[3][3], a3, w23.y);
        }
        __syncthreads();
    }
#pragma unroll
    for (int i = 0; i < 4; i++)
#pragma unroll
        for (int p = 0; p < 4; p++) {
            float2 v = unpack2(acc[i][p]);
            int h0 = tx * 8 + p * 2;
            int c = ((ty ^ ((h0 >> 2) & 15)) << 2) | i;
            Hs[h0 * 64 + c]       = fmaxf(v.x, 0.f);
            Hs[(h0 + 1) * 64 + c] = fmaxf(v.y, 0.f);
        }
    __syncthreads();
}

__device__ __forceinline__ void gemm_o(const float* __restrict__ Hs,
                                       const float* __restrict__ Wg,
                                       const float* __restrict__ b2,
                                       float* __restrict__ sW, int t,
                                       float o[4][4])
{
    const int tx = t & 15, ty = t >> 4;
    uint64_t b0 = *(const uint64_t*)(b2 + tx * 4);
    uint64_t b1 = *(const uint64_t*)(b2 + tx * 4 + 2);
    uint64_t acc[4][2];
#pragma unroll
    for (int i = 0; i < 4; i++) { acc[i][0] = b0; acc[i][1] = b1; }
    stage_w2(Wg, 0, sW, t);
    cp_commit();
#pragma unroll
    for (int kt = 0; kt < 2; kt++) {
        if (kt == 0) { stage_w2(Wg, 1, sW + 4096, t); cp_commit(); cp_wait<1>(); }
        else cp_wait<0>();
        __syncthreads();
        const float* W = sW + kt * 4096;
#pragma unroll 8
        for (int kk = 0; kk < 64; kk++) {
            int k = kt * 64 + kk;
            float4 a = *(const float4*)(Hs + k * 64 + ((ty ^ ((k >> 2) & 15)) << 2));
            ulonglong2 w = *(const ulonglong2*)(W + kk * 64 + tx * 4);
            uint64_t a0 = rep2(a.x), a1 = rep2(a.y), a2 = rep2(a.z), a3 = rep2(a.w);
            fma2(acc[0][0], a0, w.x); fma2(acc[0][1], a0, w.y);
            fma2(acc[1][0], a1, w.x); fma2(acc[1][1], a1, w.y);
            fma2(acc[2][0], a2, w.x); fma2(acc[2][1], a2, w.y);
            fma2(acc[3][0], a3, w.x); fma2(acc[3][1], a3, w.y);
        }
        __syncthreads();
    }
#pragma unroll
    for (int i = 0; i < 4; i++)
#pragma unroll
        for (int p = 0; p < 2; p++) {
            float2 v = unpack2(acc[i][p]);
            o[i][p * 2]     = v.x;
            o[i][p * 2 + 1] = v.y;
        }
}

// ===========================================================================
// 128-thread, 8-row edge microkernel (warp covers 16 M-rows -> half the W
// crossbar traffic per MAC; FMA-bound). 3 CTAs/SM.
// ===========================================================================
__device__ __forceinline__ void stage16x128(const float* __restrict__ src,
                                            float* __restrict__ dst, int t) {
#pragma unroll
    for (int i = 0; i < 4; i++) {
        int idx = t + i * 128;              // 0..511 float4s
        int r = idx >> 5, c4 = (idx & 31) << 2;
        cp16(dst + r * 128 + c4, src + r * 128 + c4);
    }
}
__device__ __forceinline__ void stage32x64(const float* __restrict__ src,
                                           float* __restrict__ dst, int t) {
#pragma unroll
    for (int i = 0; i < 4; i++) {
        int idx = t + i * 128;
        int r = idx >> 4, c4 = (idx & 15) << 2;
        cp16(dst + r * 64 + c4, src + r * 64 + c4);
    }
}

// GEMM1 (K=64): acc[8][4] pre-initialized; A 64x64 K-major swizzled.
__device__ __forceinline__ void gemm_h8(const float* __restrict__ A,
                                        const float* __restrict__ Wg,
                                        uint64_t (&acc)[8][4],
                                        float* __restrict__ Hs,
                                        float* __restrict__ sW, int t)
{
    const int tx = t & 15, tq = t >> 4;     // tq in 0..7 -> rows tq*8..tq*8+7
    stage16x128(Wg, sW, t);
    cp_commit();
#pragma unroll
    for (int kt = 0; kt < 4; kt++) {
        if (kt < 3) {
            stage16x128(Wg + (kt + 1) * 16 * 128, sW + ((kt + 1) & 1) * 2048, t);
            cp_commit();
            cp_wait<1>();
        } else cp_wait<0>();
        __syncthreads();
        const float* W = sW + (kt & 1) * 2048;
#pragma unroll
        for (int kk = 0; kk < 16; kk++) {
            int k = kt * 16 + kk;
            int kg = (k >> 2) & 15;
            float4 aA = *(const float4*)(A + k * 64 + ((((tq << 1)    ) ^ kg) << 2));
            float4 aB = *(const float4*)(A + k * 64 + ((((tq << 1) | 1) ^ kg) << 2));
            ulonglong2 w01 = *(const ulonglong2*)(W + kk * 128 + tx * 8);
            ulonglong2 w23 = *(const ulonglong2*)(W + kk * 128 + tx * 8 + 4);
            uint64_t a0 = rep2(aA.x), a1 = rep2(aA.y), a2 = rep2(aA.z), a3 = rep2(aA.w);
            uint64_t a4 = rep2(aB.x), a5 = rep2(aB.y), a6 = rep2(aB.z), a7 = rep2(aB.w);
            fma2(acc[0][0], a0, w01.x); fma2(acc[0][1], a0, w01.y);
            fma2(acc[0][2], a0, w23.x); fma2(acc[0][3], a0, w23.y);
            fma2(acc[1][0], a1, w01.x); fma2(acc[1][1], a1, w01.y);
            fma2(acc[1][2], a1, w23.x); fma2(acc[1][3], a1, w23.y);
            fma2(acc[2][0], a2, w01.x); fma2(acc[2][1], a2, w01.y);
            fma2(acc[2][2], a2, w23.x); fma2(acc[2][3], a2, w23.y);
            fma2(acc[3][0], a3, w01.x); fma2(acc[3][1], a3, w01.y);
            fma2(acc[3][2], a3, w23.x); fma2(acc[3][3], a3, w23.y);
            fma2(acc[4][0], a4, w01.x); fma2(acc[4][1], a4, w01.y);
            fma2(acc[4][2], a4, w23.x); fma2(acc[4][3], a4, w23.y);
            fma2(acc[5][0], a5, w01.x); fma2(acc[5][1], a5, w01.y);
            fma2(acc[5][2], a5, w23.x); fma2(acc[5][3], a5, w23.y);
            fma2(acc[6][0], a6, w01.x); fma2(acc[6][1], a6, w01.y);
            fma2(acc[6][2], a6, w23.x); fma2(acc[6][3], a6, w23.y);
            fma2(acc[7][0], a7, w01.x); fma2(acc[7][1], a7, w01.y);
            fma2(acc[7][2], a7, w23.x); fma2(acc[7][3], a7, w23.y);
        }
        __syncthreads();
    }
    // relu + swizzled transpose store to Hs[128][64]
#pragma unroll
    for (int i = 0; i < 8; i++) {
        int m = tq * 8 + i, mg = m >> 2, ml = m & 3;
#pragma unroll
        for (int p = 0; p < 4; p++) {
            float2 v = unpack2(acc[i][p]);
            int h0 = tx * 8 + p * 2;
            int hg = (h0 >> 2) & 15;      // h0 and h0+1 share the group
            int c = ((mg ^ hg) << 2) | ml;
            Hs[h0 * 64 + c]       = fmaxf(v.x, 0.f);
            Hs[(h0 + 1) * 64 + c] = fmaxf(v.y, 0.f);
        }
    }
    __syncthreads();
}

// GEMM2 (K=128): o[8][4] = Hs^T @ W2 + b2.
__device__ __forceinline__ void gemm_o8(const float* __restrict__ Hs,
                                        const float* __restrict__ Wg,
                                        const float* __restrict__ b2,
                                        float* __restrict__ sW, int t,
                                        float o[8][4])
{
    const int tx = t & 15, tq = t >> 4;
    uint64_t b0 = *(const uint64_t*)(b2 + tx * 4);
    uint64_t b1 = *(const uint64_t*)(b2 + tx * 4 + 2);
    uint64_t acc[8][2];
#pragma unroll
    for (int i = 0; i < 8; i++) { acc[i][0] = b0; acc[i][1] = b1; }
    stage32x64(Wg, sW, t);
    cp_commit();
#pragma unroll
    for (int kt = 0; kt < 4; kt++) {
        if (kt < 3) {
            stage32x64(Wg + (kt + 1) * 32 * 64, sW + ((kt + 1) & 1) * 2048, t);
            cp_commit();
            cp_wait<1>();
        } else cp_wait<0>();
        __syncthreads();
        const float* W = sW + (kt & 1) * 2048;
#pragma unroll
        for (int kk = 0; kk < 32; kk++) {
            int k = kt * 32 + kk;
            int kg = (k >> 2) & 15;
            float4 aA = *(const float4*)(Hs + k * 64 + ((((tq << 1)    ) ^ kg) << 2));
            float4 aB = *(const float4*)(Hs + k * 64 + ((((tq << 1) | 1) ^ kg) << 2));
            ulonglong2 w = *(const ulonglong2*)(W + kk * 64 + tx * 4);
            uint64_t a0 = rep2(aA.x), a1 = rep2(aA.y), a2 = rep2(aA.z), a3 = rep2(aA.w);
            uint64_t a4 = rep2(aB.x), a5 = rep2(aB.y), a6 = rep2(aB.z), a7 = rep2(aB.w);
            fma2(acc[0][0], a0, w.x); fma2(acc[0][1], a0, w.y);
            fma2(acc[1][0], a1, w.x); fma2(acc[1][1], a1, w.y);
            fma2(acc[2][0], a2, w.x); fma2(acc[2][1], a2, w.y);
            fma2(acc[3][0], a3, w.x); fma2(acc[3][1], a3, w.y);
            fma2(acc[4][0], a4, w.x); fma2(acc[4][1], a4, w.y);
            fma2(acc[5][0], a5, w.x); fma2(acc[5][1], a5, w.y);
            fma2(acc[6][0], a6, w.x); fma2(acc[6][1], a6, w.y);
            fma2(acc[7][0], a7, w.x); fma2(acc[7][1], a7, w.y);
        }
        __syncthreads();
    }
#pragma unroll
    for (int i = 0; i < 8; i++)
#pragma unroll
        for (int p = 0; p < 2; p++) {
            float2 v = unpack2(acc[i][p]);
            o[i][p * 2]     = v.x;
            o[i][p * 2 + 1] = v.y;
        }
}

// ---------------------------------------------------------------------------
// Edge kernel: 64 edges/CTA, 128 threads, 3 CTAs/SM.
// smem floats: A[4096] | sW[4096] | Hs[8192] | idx[192] = 66.3 KB
// ---------------------------------------------------------------------------
#define SME_A  0
#define SME_W  4096
#define SME_H  8192
#define SME_IX 16384
#define SME_FLOATS (16384 + 192)

__global__ void __launch_bounds__(128, 3)
edge_kernel(const int* __restrict__ ei,
            const float* __restrict__ e, const int* __restrict__ batch,
            const float* __restrict__ We1, const float* __restrict__ We2,
            const float* __restrict__ be2,
            const float* __restrict__ Wa1, const float* __restrict__ Wa2,
            const float* __restrict__ ba2,
            float* __restrict__ e_out)
{
    extern __shared__ float smem[];
    float* A  = smem + SME_A;
    float* sW = smem + SME_W;
    float* Hs = smem + SME_H;
    int* srcs = (int*)(smem + SME_IX);
    int* dsts = srcs + 64;
    int* gidx = dsts + 64;
    const int t = threadIdx.x;
    const int eb = blockIdx.x * 64;

    if (t < 64) {
        int s_ = ei[eb + t], d_ = ei[Ee + eb + t];
        srcs[t] = s_; dsts[t] = d_; gidx[t] = batch[s_];
    }
    __syncthreads();

    // Build A = e tile, K-major, xor-swizzled
    for (int i = t; i < 1024; i += 128) {
        int m = i >> 4, k4 = (i & 15) << 2;
        int c = ((((m >> 2) ^ (k4 >> 2)) & 15) << 2) | (m & 3);
        float4 v = *(const float4*)&e[(size_t)(eb + m) * 64 + k4];
        A[k4 * 64 + c] = v.x; A[(k4 + 1) * 64 + c] = v.y;
        A[(k4 + 2) * 64 + c] = v.z; A[(k4 + 3) * 64 + c] = v.w;
    }
    __syncthreads();

    const int tx = t & 15, tq = t >> 4;

    // --- MLP_e: acc init from gathered tables, K=64 GEMM on e ---
    uint64_t acc1[8][4];
#pragma unroll
    for (int i = 0; i < 8; i++) {
        int row = tq * 8 + i;
        const float* up = g_U1e + gidx[row] * 128 + tx * 8;
        const float* xs = g_Xs + (size_t)srcs[row] * 256 + tx * 8;
        const float* xd = g_Xd + (size_t)dsts[row] * 256 + tx * 8;
#pragma unroll
        for (int p = 0; p < 4; p++)
            acc1[i][p] = add2(*(const uint64_t*)(up + p * 2),
                         add2(*(const uint64_t*)(xs + p * 2),
                              *(const uint64_t*)(xd + p * 2)));
    }
    gemm_h8(A, We1 + 128 * 128, acc1, Hs, sW, t);
    float enew[8][4];
    gemm_o8(Hs, We2, be2, sW, t, enew);   // ends with __syncthreads

    float* eagg = Hs;                     // overlay 16*64 floats on Hs
#pragma unroll
    for (int i = 0; i < 8; i++) eagg[t + i * 128] = 0.f;
    __syncthreads();

    // write e_new; splice into A; accumulate per-graph sums
#pragma unroll
    for (int i = 0; i < 8; i++) {
        int row = tq * 8 + i;
        int mg = row >> 2, ml = row & 3;
        *(float4*)&e_out[(size_t)(eb + row) * 64 + tx * 4] =
            make_float4(enew[i][0], enew[i][1], enew[i][2], enew[i][3]);
        int cA = (((mg ^ tx) & 15) << 2) | ml;   // rows k=tx*4+j: kg = tx
        int g = gidx[row];
#pragma unroll
        for (int j = 0; j < 4; j++) {
            A[(tx * 4 + j) * 64 + cA] = enew[i][j];
            atomicAdd(&eagg[g * 64 + tx * 4 + j], enew[i][j]);
        }
    }
    __syncthreads();
    for (int q = t; q < 256; q += 128) {
        int g = q >> 4, c4 = (q & 15) << 2;
        const float* p = &eagg[g * 64 + c4];
        red4(&g_eagg[g * 64 + c4], p[0], p[1], p[2], p[3]);
    }

    // --- MLP_a: second halves of the tables ---
#pragma unroll
    for (int i = 0; i < 8; i++) {
        int row = tq * 8 + i;
        const float* up = g_U1a + gidx[row] * 128 + tx * 8;
        const float* xs = g_Xs + (size_t)srcs[row] * 256 + 128 + tx * 8;
        const float* xd = g_Xd + (size_t)dsts[row] * 256 + 128 + tx * 8;
#pragma unroll
        for (int p = 0; p < 4; p++)
            acc1[i][p] = add2(*(const uint64_t*)(up + p * 2),
                         add2(*(const uint64_t*)(xs + p * 2),
                              *(const uint64_t*)(xd + p * 2)));
    }
    gemm_h8(A, Wa1 + 128 * 128, acc1, Hs, sW, t);
    float av[8][4];
    gemm_o8(Hs, Wa2, ba2, sW, t, av);

    // scatter e_new * sigmoid(a) into g_agg[dst]
#pragma unroll
    for (int i = 0; i < 8; i++) {
        int row = tq * 8 + i;
        int dst = dsts[row];
        float w0 = enew[i][0] / (1.f + __expf(-av[i][0]));
        float w1 = enew[i][1] / (1.f + __expf(-av[i][1]));
        float w2 = enew[i][2] / (1.f + __expf(-av[i][2]));
        float w3 = enew[i][3] / (1.f + __expf(-av[i][3]));
        red4(&g_agg[(size_t)dst * 64 + tx * 4], w0, w1, w2, w3);
    }
}

// ---------------------------------------------------------------------------
// Node kernel: 64 nodes/CTA, 256 threads (R5-proven shape)
// ---------------------------------------------------------------------------
#define SMN_A  0
#define SMN_W  4096
#define SMN_H  12288
#define SMN_IX 20480
#define SMN_FLOATS (20480 + 64)

__global__ void __launch_bounds__(256, 2)
node_kernel(const int* __restrict__ batch,
            const float* __restrict__ Wn1, const float* __restrict__ Wn2,
            const float* __restrict__ bn2,
            float* __restrict__ x_out)
{
    extern __shared__ float smem[];
    float* A  = smem + SMN_A;
    float* sW = smem + SMN_W;
    float* Hs = smem + SMN_H;
    int* gid  = (int*)(smem + SMN_IX);
    const int t = threadIdx.x;
    const int nb = blockIdx.x * 64;

    if (t < 64) {
        int r = nb + t; if (r >= Nn) r = Nn - 1;
        gid[t] = batch[r];
    }
    __syncthreads();

    for (int i = t; i < 1024; i += 256) {
        int m = i >> 4, k4 = (i & 15) << 2;
        int r = nb + m; if (r >= Nn) r = Nn - 1;
        int c = ((((m >> 2) ^ (k4 >> 2)) & 15) << 2) | (m & 3);
        float4 v = *(const float4*)&g_agg[(size_t)r * 64 + k4];
        A[k4 * 64 + c] = v.x; A[(k4 + 1) * 64 + c] = v.y;
        A[(k4 + 2) * 64 + c] = v.z; A[(k4 + 3) * 64 + c] = v.w;
    }
    __syncthreads();

    const int tx = t & 15, ty = t >> 4;
    uint64_t ini[4][4];
#pragma unroll
    for (int i = 0; i < 4; i++) {
        int row = ty * 4 + i;
        int r = nb + row; if (r >= Nn) r = Nn - 1;
        const float* up = g_U1n + gid[row] * 128 + tx * 8;
        const float* xn = g_Xn + (size_t)r * 128 + tx * 8;
#pragma unroll
        for (int p = 0; p < 4; p++)
            ini[i][p] = add2(*(const uint64_t*)(up + p * 2),
                             *(const uint64_t*)(xn + p * 2));
    }
    gemm_h<64>(A, Wn1 + 64 * 128, ini, Hs, sW, t);
    float xo[4][4];
    gemm_o(Hs, Wn2, bn2, sW, t, xo);
    __syncthreads();

    float* nagg = Hs;
#pragma unroll
    for (int i = 0; i < 4; i++) nagg[t + i * 256] = 0.f;
    __syncthreads();

#pragma unroll
    for (int i = 0; i < 4; i++) {
        int row = ty * 4 + i;
        int r = nb + row;
        if (r < Nn) {
            *(float4*)&x_out[(size_t)r * 64 + tx * 4] =
                make_float4(xo[i][0], xo[i][1], xo[i][2], xo[i][3]);
            int g = gid[row];
#pragma unroll
            for (int j = 0; j < 4; j++)
                atomicAdd(&nagg[g * 64 + tx * 4 + j], xo[i][j]);
        }
    }
    __syncthreads();
    {
        int g = t >> 4, c4 = (t & 15) << 2;
        const float* p = &nagg[g * 64 + c4];
        red4(&g_nagg[g * 64 + c4], p[0], p[1], p[2], p[3]);
    }
}

// ---------------------------------------------------------------------------
// Prep tables: per 64-node tile, 5 x (64x128) GEMMs into g_Xs / g_Xd / g_Xn.
// ---------------------------------------------------------------------------
#define SPT_FLOATS 12288

__global__ void __launch_bounds__(256, 2)
prep_tables(const float* __restrict__ x,
            const float* __restrict__ We1, const float* __restrict__ Wa1,
            const float* __restrict__ Wn1)
{
    extern __shared__ float smem[];
    float* A  = smem;
    float* sW = smem + 4096;
    const int t = threadIdx.x;
    const int nb = blockIdx.x * 64;
    const int tx = t & 15, ty = t >> 4;

    for (int i = t; i < 1024; i += 256) {
        int m = i >> 4, k4 = (i & 15) << 2;
        int r = nb + m; if (r >= Nn) r = Nn - 1;
        int c = ((((m >> 2) ^ (k4 >> 2)) & 15) << 2) | (m & 3);
        float4 v = *(const float4*)&x[(size_t)r * 64 + k4];
        A[k4 * 64 + c] = v.x; A[(k4 + 1) * 64 + c] = v.y;
        A[(k4 + 2) * 64 + c] = v.z; A[(k4 + 3) * 64 + c] = v.w;
    }
    __syncthreads();

    const float* Ws[5] = { We1, Wa1, We1 + 64 * 128, Wa1 + 64 * 128, Wn1 };
    float* outs[5] = { g_Xs, g_Xs + 128, g_Xd, g_Xd + 128, g_Xn };
    const int stride[5] = { 256, 256, 256, 256, 128 };

#pragma unroll 1
    for (int seg = 0; seg < 5; seg++) {
        const float* W = Ws[seg];
        stage_w1(W, 0, sW, t);
        stage_w1(W, 1, sW + 4096, t);
        cp_commit();
        cp_wait<0>();
        __syncthreads();
        uint64_t acc[4][4];
#pragma unroll
        for (int i = 0; i < 4; i++)
#pragma unroll
            for (int p = 0; p < 4; p++) acc[i][p] = 0ull;
#pragma unroll
        for (int kt = 0; kt < 2; kt++) {
            const float* Wp = sW + kt * 4096;
#pragma unroll
            for (int kk = 0; kk < 32; kk++) {
                int k = kt * 32 + kk;
                float4 a = *(const float4*)(A + k * 64 + ((ty ^ ((k >> 2) & 15)) << 2));
                ulonglong2 w01 = *(const ulonglong2*)(Wp + kk * 128 + tx * 8);
                ulonglong2 w23 = *(const ulonglong2*)(Wp + kk * 128 + tx * 8 + 4);
                uint64_t a0 = rep2(a.x), a1 = rep2(a.y), a2 = rep2(a.z), a3 = rep2(a.w);
                fma2(acc[0][0], a0, w01.x); fma2(acc[0][1], a0, w01.y);
                fma2(acc[0][2], a0, w23.x); fma2(acc[0][3], a0, w23.y);
                fma2(acc[1][0], a1, w01.x); fma2(acc[1][1], a1, w01.y);
                fma2(acc[1][2], a1, w23.x); fma2(acc[1][3], a1, w23.y);
                fma2(acc[2][0], a2, w01.x); fma2(acc[2][1], a2, w01.y);
                fma2(acc[2][2], a2, w23.x); fma2(acc[2][3], a2, w23.y);
                fma2(acc[3][0], a3, w01.x); fma2(acc[3][1], a3, w01.y);
                fma2(acc[3][2], a3, w23.x); fma2(acc[3][3], a3, w23.y);
            }
        }
#pragma unroll
        for (int i = 0; i < 4; i++) {
            int r = nb + ty * 4 + i;
            if (r < Nn) {
                float* op = outs[seg] + (size_t)r * stride[seg] + tx * 8;
                float2 v0 = unpack2(acc[i][0]), v1 = unpack2(acc[i][1]);
                float2 v2 = unpack2(acc[i][2]), v3 = unpack2(acc[i][3]);
                *(float4*)op       = make_float4(v0.x, v0.y, v1.x, v1.y);
                *(float4*)(op + 4) = make_float4(v2.x, v2.y, v3.x, v3.y);
            }
        }
        __syncthreads();
    }
}

// ---------------------------------------------------------------------------
// Global kernel: 16 blocks x 128 threads
// ---------------------------------------------------------------------------
__global__ void __launch_bounds__(128)
global_kernel(const float* __restrict__ u,
              const float* __restrict__ Wg1, const float* __restrict__ bg1,
              const float* __restrict__ Wg2, const float* __restrict__ bg2,
              float* __restrict__ u_out)
{
    __shared__ float in[192];
    __shared__ float hid[128];
    const int g = blockIdx.x, t = threadIdx.x;
    if (t < 64) {
        in[t]       = u[g * 64 + t];
        in[64 + t]  = g_nagg[g * 64 + t];
        in[128 + t] = g_eagg[g * 64 + t];
    }
    __syncthreads();
    float acc = bg1[t];
#pragma unroll 8
    for (int k = 0; k < 192; k++) acc += in[k] * Wg1[(size_t)k * 128 + t];
    hid[t] = fmaxf(acc, 0.f);
    __syncthreads();
    if (t < 64) {
        float a2 = bg2[t];
#pragma unroll 8
        for (int k = 0; k < 128; k++) a2 += hid[k] * Wg2[(size_t)k * 64 + t];
        u_out[g * 64 + t] = a2;
    }
}

// ---------------------------------------------------------------------------
// Prep kernel: zero aggregates + precompute U1 tables (bias folded)
// ---------------------------------------------------------------------------
__global__ void __launch_bounds__(256)
prep_kernel(const float* __restrict__ u,
            const float* __restrict__ We1, const float* __restrict__ be1,
            const float* __restrict__ Wa1, const float* __restrict__ ba1,
            const float* __restrict__ Wn1, const float* __restrict__ bn1)
{
    const int b = blockIdx.x, t = threadIdx.x;
    size_t idx = (size_t)b * 256 + t;
    const size_t n4 = (size_t)Nn * Dd / 4;
    float4 z = make_float4(0.f, 0.f, 0.f, 0.f);
    for (size_t i = idx; i < n4; i += (size_t)gridDim.x * 256) ((float4*)g_agg)[i] = z;
    if (idx < 256) { ((float4*)g_nagg)[idx] = z; ((float4*)g_eagg)[idx] = z; }
    if (b < 3) {
        const float* W    = (b == 0) ? We1 + 192 * 128 : (b == 1) ? Wa1 + 192 * 128 : Wn1 + 128 * 128;
        const float* bias = (b == 0) ? be1 : (b == 1) ? ba1 : bn1;
        float* out        = (b == 0) ? g_U1e : (b == 1) ? g_U1a : g_U1n;
        for (int i = t; i < Gg * Hh; i += 256) {
            int g = i >> 7, h = i & 127;
            float acc = bias[h];
#pragma unroll 8
            for (int k = 0; k < 64; k++) acc += u[g * 64 + k] * W[(size_t)k * 128 + h];
            out[i] = acc;
        }
    }
}

extern "C" void kernel_launch(void* const* d_in, const int* in_sizes, int n_in,
                              void* d_out, int out_size)
{
    const float* x     = (const float*)d_in[0];
    const int*   ei    = (const int*)d_in[1];
    const float* e     = (const float*)d_in[2];
    const float* u     = (const float*)d_in[3];
    const int*   batch = (const int*)d_in[4];
    const float* We1 = (const float*)d_in[5];
    const float* be1 = (const float*)d_in[6];
    const float* We2 = (const float*)d_in[7];
    const float* be2 = (const float*)d_in[8];
    const float* Wa1 = (const float*)d_in[9];
    const float* ba1 = (const float*)d_in[10];
    const float* Wa2 = (const float*)d_in[11];
    const float* ba2 = (const float*)d_in[12];
    const float* Wn1 = (const float*)d_in[13];
    const float* bn1 = (const float*)d_in[14];
    const float* Wn2 = (const float*)d_in[15];
    const float* bn2 = (const float*)d_in[16];
    const float* Wg1 = (const float*)d_in[17];
    const float* bg1 = (const float*)d_in[18];
    const float* Wg2 = (const float*)d_in[19];
    const float* bg2 = (const float*)d_in[20];

    float* out   = (float*)d_out;
    float* x_out = out;
    float* e_out = out + (size_t)Nn * Dd;
    float* u_out = out + (size_t)Nn * Dd + (size_t)Ee * Dd;

    cudaFuncSetAttribute(edge_kernel, cudaFuncAttributeMaxDynamicSharedMemorySize,
                         SME_FLOATS * 4);
    cudaFuncSetAttribute(node_kernel, cudaFuncAttributeMaxDynamicSharedMemorySize,
                         SMN_FLOATS * 4);
    cudaFuncSetAttribute(prep_tables, cudaFuncAttributeMaxDynamicSharedMemorySize,
                         SPT_FLOATS * 4);

    prep_kernel<<<3125, 256>>>(u, We1, be1, Wa1, ba1, Wn1, bn1);
    prep_tables<<<(Nn + 63) / 64, 256, SPT_FLOATS * 4>>>(x, We1, Wa1, Wn1);
    edge_kernel<<<Ee / 64, 128, SME_FLOATS * 4>>>(ei, e, batch,
                                                  We1, We2, be2, Wa1, Wa2, ba2, e_out);
    node_kernel<<<(Nn + 63) / 64, 256, SMN_FLOATS * 4>>>(batch, Wn1, Wn2, bn2, x_out);
    global_kernel<<<Gg, 128>>>(u, Wg1, bg1, Wg2, bg2, u_out);
}

// round 8
// speedup vs baseline: 1.3923x; 1.3923x over previous
#include <cuda_runtime.h>
#include <stdint.h>
#include <math.h>

#define Nn 50000
#define Ee 800000
#define Gg 16
#define Dd 64
#define Hh 128

// Scratch (allocation-free: __device__ globals)
__device__ float g_agg[Nn * Dd];      // attention-weighted edge aggregate per node
__device__ float g_nagg[Gg * Dd];     // node aggregate per graph
__device__ float g_eagg[Gg * Dd];     // edge aggregate per graph
__device__ float g_U1e[Gg * Hh];      // be1 + u @ We1[192:256]
__device__ float g_U1a[Gg * Hh];      // ba1 + u @ Wa1[192:256]
__device__ float g_U1n[Gg * Hh];      // bn1 + u @ Wn1[128:192]
__device__ float g_Xs[(size_t)Nn * 256];  // [x@We1[0:64] | x@Wa1[0:64]]
__device__ float g_Xd[(size_t)Nn * 256];  // [x@We1[64:128] | x@Wa1[64:128]]
__device__ float g_Xn[(size_t)Nn * 128];  // x@Wn1[0:64]

// ---------------------------------------------------------------------------
// Packed fp32x2 helpers
// ---------------------------------------------------------------------------
__device__ __forceinline__ void fma2(uint64_t& d, uint64_t a, uint64_t b) {
    asm("fma.rn.f32x2 %0, %1, %2, %0;" : "+l"(d) : "l"(a), "l"(b));
}
__device__ __forceinline__ uint64_t add2(uint64_t a, uint64_t b) {
    uint64_t r; asm("add.rn.f32x2 %0, %1, %2;" : "=l"(r) : "l"(a), "l"(b)); return r;
}
__device__ __forceinline__ uint64_t rep2(float x) {
    uint64_t r; asm("mov.b64 %0, {%1, %1};" : "=l"(r) : "f"(x)); return r;
}
__device__ __forceinline__ float2 unpack2(uint64_t v) {
    float2 r; asm("mov.b64 {%0, %1}, %2;" : "=f"(r.x), "=f"(r.y) : "l"(v)); return r;
}
__device__ __forceinline__ void red4(float* p, float a, float b, float c, float d) {
    asm volatile("red.global.add.v4.f32 [%0], {%1,%2,%3,%4};"
                 :: "l"(p), "f"(a), "f"(b), "f"(c), "f"(d) : "memory");
}
__device__ __forceinline__ void cp16(float* smem_dst, const float* gsrc) {
    uint32_t s = (uint32_t)__cvta_generic_to_shared(smem_dst);
    asm volatile("cp.async.cg.shared.global [%0], [%1], 16;" :: "r"(s), "l"(gsrc));
}
__device__ __forceinline__ void cp_commit() { asm volatile("cp.async.commit_group;"); }
template<int N> __device__ __forceinline__ void cp_wait() {
    asm volatile("cp.async.wait_group %0;" :: "n"(N));
}
__device__ __forceinline__ void pfL2(const float* p) {
    asm volatile("prefetch.global.L2 [%0];" :: "l"(p));
}

// ===========================================================================
// 256-thread staging, 32-row tiles (node / prep kernels, R5-proven)
// ===========================================================================
__device__ __forceinline__ void stage_w1(const float* __restrict__ Wg, int kt,
                                         float* __restrict__ dst, int t) {
    const float* src = Wg + (size_t)kt * 32 * 128;
#pragma unroll
    for (int i = 0; i < 4; i++) {
        int idx = t + i * 256;
        int r = idx >> 5, c4 = (idx & 31) << 2;
        cp16(dst + r * 128 + c4, src + r * 128 + c4);
    }
}
__device__ __forceinline__ void stage_w2(const float* __restrict__ Wg, int kt,
                                         float* __restrict__ dst, int t) {
    const float* src = Wg + (size_t)kt * 64 * 64;
#pragma unroll
    for (int i = 0; i < 4; i++) {
        int idx = t + i * 256;
        int r = idx >> 4, c4 = (idx & 15) << 2;
        cp16(dst + r * 64 + c4, src + r * 64 + c4);
    }
}

template<int KTOT>
__device__ __forceinline__ void gemm_h(const float* __restrict__ A,
                                       const float* __restrict__ Wg,
                                       const uint64_t (&ini)[4][4],
                                       float* __restrict__ Hs,
                                       float* __restrict__ sW, int t)
{
    const int tx = t & 15, ty = t >> 4;
    uint64_t acc[4][4];
#pragma unroll
    for (int i = 0; i < 4; i++)
#pragma unroll
        for (int p = 0; p < 4; p++) acc[i][p] = ini[i][p];
    constexpr int NT = KTOT / 32;
    stage_w1(Wg, 0, sW, t);
    cp_commit();
#pragma unroll
    for (int kt = 0; kt < NT; kt++) {
        if (kt + 1 < NT) {
            stage_w1(Wg, kt + 1, sW + ((kt + 1) & 1) * 4096, t);
            cp_commit();
            cp_wait<1>();
        } else cp_wait<0>();
        __syncthreads();
        const float* W = sW + (kt & 1) * 4096;
#pragma unroll
        for (int kk = 0; kk < 32; kk++) {
            int k = kt * 32 + kk;
            float4 a = *(const float4*)(A + k * 64 + ((ty ^ ((k >> 2) & 15)) << 2));
            ulonglong2 w01 = *(const ulonglong2*)(W + kk * 128 + tx * 8);
            ulonglong2 w23 = *(const ulonglong2*)(W + kk * 128 + tx * 8 + 4);
            uint64_t a0 = rep2(a.x), a1 = rep2(a.y), a2 = rep2(a.z), a3 = rep2(a.w);
            fma2(acc[0][0], a0, w01.x); fma2(acc[0][1], a0, w01.y);
            fma2(acc[0][2], a0, w23.x); fma2(acc[0][3], a0, w23.y);
            fma2(acc[1][0], a1, w01.x); fma2(acc[1][1], a1, w01.y);
            fma2(acc[1][2], a1, w23.x); fma2(acc[1][3], a1, w23.y);
            fma2(acc[2][0], a2, w01.x); fma2(acc[2][1], a2, w01.y);
            fma2(acc[2][2], a2, w23.x); fma2(acc[2][3], a2, w23.y);
            fma2(acc[3][0], a3, w01.x); fma2(acc[3][1], a3, w01.y);
            fma2(acc[3][2], a3, w23.x); fma2(acc[3][3], a3, w23.y);
        }
        __syncthreads();
    }
#pragma unroll
    for (int i = 0; i < 4; i++)
#pragma unroll
        for (int p = 0; p < 4; p++) {
            float2 v = unpack2(acc[i][p]);
            int h0 = tx * 8 + p * 2;
            int c = ((ty ^ ((h0 >> 2) & 15)) << 2) | i;
            Hs[h0 * 64 + c]       = fmaxf(v.x, 0.f);
            Hs[(h0 + 1) * 64 + c] = fmaxf(v.y, 0.f);
        }
    __syncthreads();
}

__device__ __forceinline__ void gemm_o(const float* __restrict__ Hs,
                                       const float* __restrict__ Wg,
                                       const float* __restrict__ b2,
                                       float* __restrict__ sW, int t,
                                       float o[4][4])
{
    const int tx = t & 15, ty = t >> 4;
    uint64_t b0 = *(const uint64_t*)(b2 + tx * 4);
    uint64_t b1 = *(const uint64_t*)(b2 + tx * 4 + 2);
    uint64_t acc[4][2];
#pragma unroll
    for (int i = 0; i < 4; i++) { acc[i][0] = b0; acc[i][1] = b1; }
    stage_w2(Wg, 0, sW, t);
    cp_commit();
#pragma unroll
    for (int kt = 0; kt < 2; kt++) {
        if (kt == 0) { stage_w2(Wg, 1, sW + 4096, t); cp_commit(); cp_wait<1>(); }
        else cp_wait<0>();
        __syncthreads();
        const float* W = sW + kt * 4096;
#pragma unroll 8
        for (int kk = 0; kk < 64; kk++) {
            int k = kt * 64 + kk;
            float4 a = *(const float4*)(Hs + k * 64 + ((ty ^ ((k >> 2) & 15)) << 2));
            ulonglong2 w = *(const ulonglong2*)(W + kk * 64 + tx * 4);
            uint64_t a0 = rep2(a.x), a1 = rep2(a.y), a2 = rep2(a.z), a3 = rep2(a.w);
            fma2(acc[0][0], a0, w.x); fma2(acc[0][1], a0, w.y);
            fma2(acc[1][0], a1, w.x); fma2(acc[1][1], a1, w.y);
            fma2(acc[2][0], a2, w.x); fma2(acc[2][1], a2, w.y);
            fma2(acc[3][0], a3, w.x); fma2(acc[3][1], a3, w.y);
        }
        __syncthreads();
    }
#pragma unroll
    for (int i = 0; i < 4; i++)
#pragma unroll
        for (int p = 0; p < 2; p++) {
            float2 v = unpack2(acc[i][p]);
            o[i][p * 2]     = v.x;
            o[i][p * 2 + 1] = v.y;
        }
}

// ===========================================================================
// Edge-kernel variants: half-size W tiles (16x128 / 32x64) so smem fits
// 3 CTAs/SM. Same 4-row x 8-col register tile, 256 threads.
// ===========================================================================
__device__ __forceinline__ void st16(const float* __restrict__ src,
                                     float* __restrict__ dst, int t) {
#pragma unroll
    for (int i = 0; i < 2; i++) {
        int idx = t + i * 256;             // 0..511 float4s (16x128)
        int r = idx >> 5, c4 = (idx & 31) << 2;
        cp16(dst + r * 128 + c4, src + r * 128 + c4);
    }
}
__device__ __forceinline__ void st32(const float* __restrict__ src,
                                     float* __restrict__ dst, int t) {
#pragma unroll
    for (int i = 0; i < 2; i++) {
        int idx = t + i * 256;             // 0..511 float4s (32x64)
        int r = idx >> 4, c4 = (idx & 15) << 2;
        cp16(dst + r * 64 + c4, src + r * 64 + c4);
    }
}

// GEMM1 (K=64): 4 pipelined 16-row W tiles through a 2x2048-float buffer.
__device__ __forceinline__ void gemm_h3(const float* __restrict__ A,
                                        const float* __restrict__ Wg,
                                        const uint64_t (&ini)[4][4],
                                        float* __restrict__ Hs,
                                        float* __restrict__ sW, int t)
{
    const int tx = t & 15, ty = t >> 4;
    uint64_t acc[4][4];
#pragma unroll
    for (int i = 0; i < 4; i++)
#pragma unroll
        for (int p = 0; p < 4; p++) acc[i][p] = ini[i][p];
    st16(Wg, sW, t);
    cp_commit();
#pragma unroll
    for (int kt = 0; kt < 4; kt++) {
        if (kt < 3) {
            st16(Wg + (kt + 1) * 16 * 128, sW + ((kt + 1) & 1) * 2048, t);
            cp_commit();
            cp_wait<1>();
        } else cp_wait<0>();
        __syncthreads();
        const float* W = sW + (kt & 1) * 2048;
#pragma unroll
        for (int kk = 0; kk < 16; kk++) {
            int k = kt * 16 + kk;
            float4 a = *(const float4*)(A + k * 64 + ((ty ^ ((k >> 2) & 15)) << 2));
            ulonglong2 w01 = *(const ulonglong2*)(W + kk * 128 + tx * 8);
            ulonglong2 w23 = *(const ulonglong2*)(W + kk * 128 + tx * 8 + 4);
            uint64_t a0 = rep2(a.x), a1 = rep2(a.y), a2 = rep2(a.z), a3 = rep2(a.w);
            fma2(acc[0][0], a0, w01.x); fma2(acc[0][1], a0, w01.y);
            fma2(acc[0][2], a0, w23.x); fma2(acc[0][3], a0, w23.y);
            fma2(acc[1][0], a1, w01.x); fma2(acc[1][1], a1, w01.y);
            fma2(acc[1][2], a1, w23.x); fma2(acc[1][3], a1, w23.y);
            fma2(acc[2][0], a2, w01.x); fma2(acc[2][1], a2, w01.y);
            fma2(acc[2][2], a2, w23.x); fma2(acc[2][3], a2, w23.y);
            fma2(acc[3][0], a3, w01.x); fma2(acc[3][1], a3, w01.y);
            fma2(acc[3][2], a3, w23.x); fma2(acc[3][3], a3, w23.y);
        }
        __syncthreads();
    }
#pragma unroll
    for (int i = 0; i < 4; i++)
#pragma unroll
        for (int p = 0; p < 4; p++) {
            float2 v = unpack2(acc[i][p]);
            int h0 = tx * 8 + p * 2;
            int c = ((ty ^ ((h0 >> 2) & 15)) << 2) | i;
            Hs[h0 * 64 + c]       = fmaxf(v.x, 0.f);
            Hs[(h0 + 1) * 64 + c] = fmaxf(v.y, 0.f);
        }
    __syncthreads();
}

// GEMM2 (K=128): 4 pipelined 32-row W2 tiles through a 2x2048-float buffer.
__device__ __forceinline__ void gemm_o3(const float* __restrict__ Hs,
                                        const float* __restrict__ Wg,
                                        const float* __restrict__ b2,
                                        float* __restrict__ sW, int t,
                                        float o[4][4])
{
    const int tx = t & 15, ty = t >> 4;
    uint64_t b0 = *(const uint64_t*)(b2 + tx * 4);
    uint64_t b1 = *(const uint64_t*)(b2 + tx * 4 + 2);
    uint64_t acc[4][2];
#pragma unroll
    for (int i = 0; i < 4; i++) { acc[i][0] = b0; acc[i][1] = b1; }
    st32(Wg, sW, t);
    cp_commit();
#pragma unroll
    for (int kt = 0; kt < 4; kt++) {
        if (kt < 3) {
            st32(Wg + (kt + 1) * 32 * 64, sW + ((kt + 1) & 1) * 2048, t);
            cp_commit();
            cp_wait<1>();
        } else cp_wait<0>();
        __syncthreads();
        const float* W = sW + (kt & 1) * 2048;
#pragma unroll
        for (int kk = 0; kk < 32; kk++) {
            int k = kt * 32 + kk;
            float4 a = *(const float4*)(Hs + k * 64 + ((ty ^ ((k >> 2) & 15)) << 2));
            ulonglong2 w = *(const ulonglong2*)(W + kk * 64 + tx * 4);
            uint64_t a0 = rep2(a.x), a1 = rep2(a.y), a2 = rep2(a.z), a3 = rep2(a.w);
            fma2(acc[0][0], a0, w.x); fma2(acc[0][1], a0, w.y);
            fma2(acc[1][0], a1, w.x); fma2(acc[1][1], a1, w.y);
            fma2(acc[2][0], a2, w.x); fma2(acc[2][1], a2, w.y);
            fma2(acc[3][0], a3, w.x); fma2(acc[3][1], a3, w.y);
        }
        __syncthreads();
    }
#pragma unroll
    for (int i = 0; i < 4; i++)
#pragma unroll
        for (int p = 0; p < 2; p++) {
            float2 v = unpack2(acc[i][p]);
            o[i][p * 2]     = v.x;
            o[i][p * 2 + 1] = v.y;
        }
}

// ---------------------------------------------------------------------------
// Edge kernel: 64 edges/CTA, 256 threads, 3 CTAs/SM.
// smem floats: A[4096] | sW[2x2048] | Hs[8192] | idx[192] = 66.3 KB
// ---------------------------------------------------------------------------
#define SME_A  0
#define SME_W  4096
#define SME_H  8192
#define SME_IX 16384
#define SME_FLOATS (16384 + 192)

__global__ void __launch_bounds__(256, 3)
edge_kernel(const int* __restrict__ ei,
            const float* __restrict__ e, const int* __restrict__ batch,
            const float* __restrict__ We1, const float* __restrict__ We2,
            const float* __restrict__ be2,
            const float* __restrict__ Wa1, const float* __restrict__ Wa2,
            const float* __restrict__ ba2,
            float* __restrict__ e_out)
{
    extern __shared__ float smem[];
    float* A  = smem + SME_A;
    float* sW = smem + SME_W;
    float* Hs = smem + SME_H;
    int* srcs = (int*)(smem + SME_IX);
    int* dsts = srcs + 64;
    int* gidx = dsts + 64;
    const int t = threadIdx.x;
    const int eb = blockIdx.x * 64;

    if (t < 64) {
        int s_ = ei[eb + t], d_ = ei[Ee + eb + t];
        srcs[t] = s_; dsts[t] = d_; gidx[t] = batch[s_];
    }
    __syncthreads();

    const int tx = t & 15, ty = t >> 4;

    // L2-prefetch all table lines (both MLPs) before doing anything else:
    // overlaps scattered-gather latency with A-build + W staging.
#pragma unroll
    for (int i = 0; i < 4; i++) {
        int row = ty * 4 + i;
        const float* xs = g_Xs + (size_t)srcs[row] * 256 + tx * 8;
        const float* xd = g_Xd + (size_t)dsts[row] * 256 + tx * 8;
        pfL2(xs); pfL2(xs + 128);
        pfL2(xd); pfL2(xd + 128);
    }

    // Build A = e tile, K-major, xor-swizzled
    for (int i = t; i < 1024; i += 256) {
        int m = i >> 4, k4 = (i & 15) << 2;
        int c = ((((m >> 2) ^ (k4 >> 2)) & 15) << 2) | (m & 3);
        float4 v = *(const float4*)&e[(size_t)(eb + m) * 64 + k4];
        A[k4 * 64 + c] = v.x; A[(k4 + 1) * 64 + c] = v.y;
        A[(k4 + 2) * 64 + c] = v.z; A[(k4 + 3) * 64 + c] = v.w;
    }

    // --- MLP_e: acc init from gathered tables, K=64 GEMM on e ---
    uint64_t ini[4][4];
#pragma unroll
    for (int i = 0; i < 4; i++) {
        int row = ty * 4 + i;
        const float* up = g_U1e + gidx[row] * 128 + tx * 8;
        const float* xs = g_Xs + (size_t)srcs[row] * 256 + tx * 8;
        const float* xd = g_Xd + (size_t)dsts[row] * 256 + tx * 8;
#pragma unroll
        for (int p = 0; p < 4; p++)
            ini[i][p] = add2(*(const uint64_t*)(up + p * 2),
                        add2(*(const uint64_t*)(xs + p * 2),
                             *(const uint64_t*)(xd + p * 2)));
    }
    __syncthreads();   // A-build complete

    gemm_h3(A, We1 + 128 * 128, ini, Hs, sW, t);
    float enew[4][4];
    gemm_o3(Hs, We2, be2, sW, t, enew);
    __syncthreads();                 // all Hs reads done; reuse Hs as eagg

    float* eagg = Hs;                // 16*64 floats overlay
#pragma unroll
    for (int i = 0; i < 4; i++) eagg[t + i * 256] = 0.f;
    __syncthreads();

    // write e_new; splice into A; accumulate per-graph sums
#pragma unroll
    for (int i = 0; i < 4; i++) {
        int row = ty * 4 + i;
        *(float4*)&e_out[(size_t)(eb + row) * 64 + tx * 4] =
            make_float4(enew[i][0], enew[i][1], enew[i][2], enew[i][3]);
        int cA = (((ty ^ tx) & 15) << 2) | i;
        int g = gidx[row];
#pragma unroll
        for (int j = 0; j < 4; j++) {
            A[(tx * 4 + j) * 64 + cA] = enew[i][j];
            atomicAdd(&eagg[g * 64 + tx * 4 + j], enew[i][j]);
        }
    }
    __syncthreads();
    {
        int g = t >> 4, c4 = (t & 15) << 2;
        const float* p = &eagg[g * 64 + c4];
        red4(&g_eagg[g * 64 + c4], p[0], p[1], p[2], p[3]);
    }

    // --- MLP_a: second halves of the tables ---
#pragma unroll
    for (int i = 0; i < 4; i++) {
        int row = ty * 4 + i;
        const float* up = g_U1a + gidx[row] * 128 + tx * 8;
        const float* xs = g_Xs + (size_t)srcs[row] * 256 + 128 + tx * 8;
        const float* xd = g_Xd + (size_t)dsts[row] * 256 + 128 + tx * 8;
#pragma unroll
        for (int p = 0; p < 4; p++)
            ini[i][p] = add2(*(const uint64_t*)(up + p * 2),
                        add2(*(const uint64_t*)(xs + p * 2),
                             *(const uint64_t*)(xd + p * 2)));
    }
    gemm_h3(A, Wa1 + 128 * 128, ini, Hs, sW, t);
    float av[4][4];
    gemm_o3(Hs, Wa2, ba2, sW, t, av);

    // scatter e_new * sigmoid(a) into g_agg[dst]
#pragma unroll
    for (int i = 0; i < 4; i++) {
        int row = ty * 4 + i;
        int dst = dsts[row];
        float w0 = enew[i][0] / (1.f + __expf(-av[i][0]));
        float w1 = enew[i][1] / (1.f + __expf(-av[i][1]));
        float w2 = enew[i][2] / (1.f + __expf(-av[i][2]));
        float w3 = enew[i][3] / (1.f + __expf(-av[i][3]));
        red4(&g_agg[(size_t)dst * 64 + tx * 4], w0, w1, w2, w3);
    }
}

// ---------------------------------------------------------------------------
// Node kernel: 64 nodes/CTA, 256 threads (R5-proven shape)
// ---------------------------------------------------------------------------
#define SMN_A  0
#define SMN_W  4096
#define SMN_H  12288
#define SMN_IX 20480
#define SMN_FLOATS (20480 + 64)

__global__ void __launch_bounds__(256, 2)
node_kernel(const int* __restrict__ batch,
            const float* __restrict__ Wn1, const float* __restrict__ Wn2,
            const float* __restrict__ bn2,
            float* __restrict__ x_out)
{
    extern __shared__ float smem[];
    float* A  = smem + SMN_A;
    float* sW = smem + SMN_W;
    float* Hs = smem + SMN_H;
    int* gid  = (int*)(smem + SMN_IX);
    const int t = threadIdx.x;
    const int nb = blockIdx.x * 64;

    if (t < 64) {
        int r = nb + t; if (r >= Nn) r = Nn - 1;
        gid[t] = batch[r];
    }
    __syncthreads();

    for (int i = t; i < 1024; i += 256) {
        int m = i >> 4, k4 = (i & 15) << 2;
        int r = nb + m; if (r >= Nn) r = Nn - 1;
        int c = ((((m >> 2) ^ (k4 >> 2)) & 15) << 2) | (m & 3);
        float4 v = *(const float4*)&g_agg[(size_t)r * 64 + k4];
        A[k4 * 64 + c] = v.x; A[(k4 + 1) * 64 + c] = v.y;
        A[(k4 + 2) * 64 + c] = v.z; A[(k4 + 3) * 64 + c] = v.w;
    }

    const int tx = t & 15, ty = t >> 4;
    uint64_t ini[4][4];
#pragma unroll
    for (int i = 0; i < 4; i++) {
        int row = ty * 4 + i;
        int r = nb + row; if (r >= Nn) r = Nn - 1;
        const float* up = g_U1n + gid[row] * 128 + tx * 8;
        const float* xn = g_Xn + (size_t)r * 128 + tx * 8;
#pragma unroll
        for (int p = 0; p < 4; p++)
            ini[i][p] = add2(*(const uint64_t*)(up + p * 2),
                             *(const uint64_t*)(xn + p * 2));
    }
    __syncthreads();

    gemm_h<64>(A, Wn1 + 64 * 128, ini, Hs, sW, t);
    float xo[4][4];
    gemm_o(Hs, Wn2, bn2, sW, t, xo);
    __syncthreads();

    float* nagg = Hs;
#pragma unroll
    for (int i = 0; i < 4; i++) nagg[t + i * 256] = 0.f;
    __syncthreads();

#pragma unroll
    for (int i = 0; i < 4; i++) {
        int row = ty * 4 + i;
        int r = nb + row;
        if (r < Nn) {
            *(float4*)&x_out[(size_t)r * 64 + tx * 4] =
                make_float4(xo[i][0], xo[i][1], xo[i][2], xo[i][3]);
            int g = gid[row];
#pragma unroll
            for (int j = 0; j < 4; j++)
                atomicAdd(&nagg[g * 64 + tx * 4 + j], xo[i][j]);
        }
    }
    __syncthreads();
    {
        int g = t >> 4, c4 = (t & 15) << 2;
        const float* p = &nagg[g * 64 + c4];
        red4(&g_nagg[g * 64 + c4], p[0], p[1], p[2], p[3]);
    }
}

// ---------------------------------------------------------------------------
// Prep tables: per 64-node tile, 5 x (64x128) GEMMs into g_Xs / g_Xd / g_Xn.
// ---------------------------------------------------------------------------
#define SPT_FLOATS 12288

__global__ void __launch_bounds__(256, 2)
prep_tables(const float* __restrict__ x,
            const float* __restrict__ We1, const float* __restrict__ Wa1,
            const float* __restrict__ Wn1)
{
    extern __shared__ float smem[];
    float* A  = smem;
    float* sW = smem + 4096;
    const int t = threadIdx.x;
    const int nb = blockIdx.x * 64;
    const int tx = t & 15, ty = t >> 4;

    for (int i = t; i < 1024; i += 256) {
        int m = i >> 4, k4 = (i & 15) << 2;
        int r = nb + m; if (r >= Nn) r = Nn - 1;
        int c = ((((m >> 2) ^ (k4 >> 2)) & 15) << 2) | (m & 3);
        float4 v = *(const float4*)&x[(size_t)r * 64 + k4];
        A[k4 * 64 + c] = v.x; A[(k4 + 1) * 64 + c] = v.y;
        A[(k4 + 2) * 64 + c] = v.z; A[(k4 + 3) * 64 + c] = v.w;
    }
    __syncthreads();

    const float* Ws[5] = { We1, Wa1, We1 + 64 * 128, Wa1 + 64 * 128, Wn1 };
    float* outs[5] = { g_Xs, g_Xs + 128, g_Xd, g_Xd + 128, g_Xn };
    const int stride[5] = { 256, 256, 256, 256, 128 };

#pragma unroll 1
    for (int seg = 0; seg < 5; seg++) {
        const float* W = Ws[seg];
        stage_w1(W, 0, sW, t);
        stage_w1(W, 1, sW + 4096, t);
        cp_commit();
        cp_wait<0>();
        __syncthreads();
        uint64_t acc[4][4];
#pragma unroll
        for (int i = 0; i < 4; i++)
#pragma unroll
            for (int p = 0; p < 4; p++) acc[i][p] = 0ull;
#pragma unroll
        for (int kt = 0; kt < 2; kt++) {
            const float* Wp = sW + kt * 4096;
#pragma unroll
            for (int kk = 0; kk < 32; kk++) {
                int k = kt * 32 + kk;
                float4 a = *(const float4*)(A + k * 64 + ((ty ^ ((k >> 2) & 15)) << 2));
                ulonglong2 w01 = *(const ulonglong2*)(Wp + kk * 128 + tx * 8);
                ulonglong2 w23 = *(const ulonglong2*)(Wp + kk * 128 + tx * 8 + 4);
                uint64_t a0 = rep2(a.x), a1 = rep2(a.y), a2 = rep2(a.z), a3 = rep2(a.w);
                fma2(acc[0][0], a0, w01.x); fma2(acc[0][1], a0, w01.y);
                fma2(acc[0][2], a0, w23.x); fma2(acc[0][3], a0, w23.y);
                fma2(acc[1][0], a1, w01.x); fma2(acc[1][1], a1, w01.y);
                fma2(acc[1][2], a1, w23.x); fma2(acc[1][3], a1, w23.y);
                fma2(acc[2][0], a2, w01.x); fma2(acc[2][1], a2, w01.y);
                fma2(acc[2][2], a2, w23.x); fma2(acc[2][3], a2, w23.y);
                fma2(acc[3][0], a3, w01.x); fma2(acc[3][1], a3, w01.y);
                fma2(acc[3][2], a3, w23.x); fma2(acc[3][3], a3, w23.y);
            }
        }
#pragma unroll
        for (int i = 0; i < 4; i++) {
            int r = nb + ty * 4 + i;
            if (r < Nn) {
                float* op = outs[seg] + (size_t)r * stride[seg] + tx * 8;
                float2 v0 = unpack2(acc[i][0]), v1 = unpack2(acc[i][1]);
                float2 v2 = unpack2(acc[i][2]), v3 = unpack2(acc[i][3]);
                *(float4*)op       = make_float4(v0.x, v0.y, v1.x, v1.y);
                *(float4*)(op + 4) = make_float4(v2.x, v2.y, v3.x, v3.y);
            }
        }
        __syncthreads();
    }
}

// ---------------------------------------------------------------------------
// Global kernel: 16 blocks x 128 threads
// ---------------------------------------------------------------------------
__global__ void __launch_bounds__(128)
global_kernel(const float* __restrict__ u,
              const float* __restrict__ Wg1, const float* __restrict__ bg1,
              const float* __restrict__ Wg2, const float* __restrict__ bg2,
              float* __restrict__ u_out)
{
    __shared__ float in[192];
    __shared__ float hid[128];
    const int g = blockIdx.x, t = threadIdx.x;
    if (t < 64) {
        in[t]       = u[g * 64 + t];
        in[64 + t]  = g_nagg[g * 64 + t];
        in[128 + t] = g_eagg[g * 64 + t];
    }
    __syncthreads();
    float acc = bg1[t];
#pragma unroll 8
    for (int k = 0; k < 192; k++) acc += in[k] * Wg1[(size_t)k * 128 + t];
    hid[t] = fmaxf(acc, 0.f);
    __syncthreads();
    if (t < 64) {
        float a2 = bg2[t];
#pragma unroll 8
        for (int k = 0; k < 128; k++) a2 += hid[k] * Wg2[(size_t)k * 64 + t];
        u_out[g * 64 + t] = a2;
    }
}

// ---------------------------------------------------------------------------
// Prep kernel: zero aggregates + precompute U1 tables (bias folded)
// ---------------------------------------------------------------------------
__global__ void __launch_bounds__(256)
prep_kernel(const float* __restrict__ u,
            const float* __restrict__ We1, const float* __restrict__ be1,
            const float* __restrict__ Wa1, const float* __restrict__ ba1,
            const float* __restrict__ Wn1, const float* __restrict__ bn1)
{
    const int b = blockIdx.x, t = threadIdx.x;
    size_t idx = (size_t)b * 256 + t;
    const size_t n4 = (size_t)Nn * Dd / 4;
    float4 z = make_float4(0.f, 0.f, 0.f, 0.f);
    for (size_t i = idx; i < n4; i += (size_t)gridDim.x * 256) ((float4*)g_agg)[i] = z;
    if (idx < 256) { ((float4*)g_nagg)[idx] = z; ((float4*)g_eagg)[idx] = z; }
    if (b < 3) {
        const float* W    = (b == 0) ? We1 + 192 * 128 : (b == 1) ? Wa1 + 192 * 128 : Wn1 + 128 * 128;
        const float* bias = (b == 0) ? be1 : (b == 1) ? ba1 : bn1;
        float* out        = (b == 0) ? g_U1e : (b == 1) ? g_U1a : g_U1n;
        for (int i = t; i < Gg * Hh; i += 256) {
            int g = i >> 7, h = i & 127;
            float acc = bias[h];
#pragma unroll 8
            for (int k = 0; k < 64; k++) acc += u[g * 64 + k] * W[(size_t)k * 128 + h];
            out[i] = acc;
        }
    }
}

extern "C" void kernel_launch(void* const* d_in, const int* in_sizes, int n_in,
                              void* d_out, int out_size)
{
    const float* x     = (const float*)d_in[0];
    const int*   ei    = (const int*)d_in[1];
    const float* e     = (const float*)d_in[2];
    const float* u     = (const float*)d_in[3];
    const int*   batch = (const int*)d_in[4];
    const float* We1 = (const float*)d_in[5];
    const float* be1 = (const float*)d_in[6];
    const float* We2 = (const float*)d_in[7];
    const float* be2 = (const float*)d_in[8];
    const float* Wa1 = (const float*)d_in[9];
    const float* ba1 = (const float*)d_in[10];
    const float* Wa2 = (const float*)d_in[11];
    const float* ba2 = (const float*)d_in[12];
    const float* Wn1 = (const float*)d_in[13];
    const float* bn1 = (const float*)d_in[14];
    const float* Wn2 = (const float*)d_in[15];
    const float* bn2 = (const float*)d_in[16];
    const float* Wg1 = (const float*)d_in[17];
    const float* bg1 = (const float*)d_in[18];
    const float* Wg2 = (const float*)d_in[19];
    const float* bg2 = (const float*)d_in[20];

    float* out   = (float*)d_out;
    float* x_out = out;
    float* e_out = out + (size_t)Nn * Dd;
    float* u_out = out + (size_t)Nn * Dd + (size_t)Ee * Dd;

    cudaFuncSetAttribute(edge_kernel, cudaFuncAttributeMaxDynamicSharedMemorySize,
                         SME_FLOATS * 4);
    cudaFuncSetAttribute(node_kernel, cudaFuncAttributeMaxDynamicSharedMemorySize,
                         SMN_FLOATS * 4);
    cudaFuncSetAttribute(prep_tables, cudaFuncAttributeMaxDynamicSharedMemorySize,
                         SPT_FLOATS * 4);

    prep_kernel<<<3125, 256>>>(u, We1, be1, Wa1, ba1, Wn1, bn1);
    prep_tables<<<(Nn + 63) / 64, 256, SPT_FLOATS * 4>>>(x, We1, Wa1, Wn1);
    edge_kernel<<<Ee / 64, 256, SME_FLOATS * 4>>>(ei, e, batch,
                                                  We1, We2, be2, Wa1, Wa2, ba2, e_out);
    node_kernel<<<(Nn + 63) / 64, 256, SMN_FLOATS * 4>>>(batch, Wn1, Wn2, bn2, x_out);
    global_kernel<<<Gg, 128>>>(u, Wg1, bg1, Wg2, bg2, u_out);
}

// round 11
// speedup vs baseline: 1.3946x; 1.0016x over previous
#include <cuda_runtime.h>
#include <stdint.h>
#include <math.h>

#define Nn 50000
#define Ee 800000
#define Gg 16
#define Dd 64
#define Hh 128

// Scratch (allocation-free: __device__ globals)
__device__ float g_agg[Nn * Dd];      // attention-weighted edge aggregate per node
__device__ float g_nagg[Gg * Dd];     // node aggregate per graph
__device__ float g_eagg[Gg * Dd];     // edge aggregate per graph
__device__ float g_U1e[Gg * Hh];      // be1 + u @ We1[192:256]
__device__ float g_U1a[Gg * Hh];      // ba1 + u @ Wa1[192:256]
__device__ float g_U1n[Gg * Hh];      // bn1 + u @ Wn1[128:192]
__device__ float g_Xs[(size_t)Nn * 256];  // [x@We1[0:64] | x@Wa1[0:64]]
__device__ float g_Xd[(size_t)Nn * 256];  // [x@We1[64:128] | x@Wa1[64:128]]
__device__ float g_Xn[(size_t)Nn * 128];  // x@Wn1[0:64]

// ---------------------------------------------------------------------------
// Packed fp32x2 helpers
// ---------------------------------------------------------------------------
__device__ __forceinline__ void fma2(uint64_t& d, uint64_t a, uint64_t b) {
    asm("fma.rn.f32x2 %0, %1, %2, %0;" : "+l"(d) : "l"(a), "l"(b));
}
__device__ __forceinline__ uint64_t add2(uint64_t a, uint64_t b) {
    uint64_t r; asm("add.rn.f32x2 %0, %1, %2;" : "=l"(r) : "l"(a), "l"(b)); return r;
}
__device__ __forceinline__ uint64_t rep2(float x) {
    uint64_t r; asm("mov.b64 %0, {%1, %1};" : "=l"(r) : "f"(x)); return r;
}
__device__ __forceinline__ float2 unpack2(uint64_t v) {
    float2 r; asm("mov.b64 {%0, %1}, %2;" : "=f"(r.x), "=f"(r.y) : "l"(v)); return r;
}
__device__ __forceinline__ void red4(float* p, float a, float b, float c, float d) {
    asm volatile("red.global.add.v4.f32 [%0], {%1,%2,%3,%4};"
                 :: "l"(p), "f"(a), "f"(b), "f"(c), "f"(d) : "memory");
}
__device__ __forceinline__ void cp16(float* smem_dst, const float* gsrc) {
    uint32_t s = (uint32_t)__cvta_generic_to_shared(smem_dst);
    asm volatile("cp.async.cg.shared.global [%0], [%1], 16;" :: "r"(s), "l"(gsrc));
}
__device__ __forceinline__ void cp_commit() { asm volatile("cp.async.commit_group;"); }
template<int N> __device__ __forceinline__ void cp_wait() {
    asm volatile("cp.async.wait_group %0;" :: "n"(N));
}
__device__ __forceinline__ void pfL2(const float* p) {
    asm volatile("prefetch.global.L2 [%0];" :: "l"(p));
}

// ===========================================================================
// 256-thread staging, 32-row tiles (node / prep kernels, R5-proven)
// ===========================================================================
__device__ __forceinline__ void stage_w1(const float* __restrict__ Wg, int kt,
                                         float* __restrict__ dst, int t) {
    const float* src = Wg + (size_t)kt * 32 * 128;
#pragma unroll
    for (int i = 0; i < 4; i++) {
        int idx = t + i * 256;
        int r = idx >> 5, c4 = (idx & 31) << 2;
        cp16(dst + r * 128 + c4, src + r * 128 + c4);
    }
}
__device__ __forceinline__ void stage_w2(const float* __restrict__ Wg, int kt,
                                         float* __restrict__ dst, int t) {
    const float* src = Wg + (size_t)kt * 64 * 64;
#pragma unroll
    for (int i = 0; i < 4; i++) {
        int idx = t + i * 256;
        int r = idx >> 4, c4 = (idx & 15) << 2;
        cp16(dst + r * 64 + c4, src + r * 64 + c4);
    }
}

template<int KTOT>
__device__ __forceinline__ void gemm_h(const float* __restrict__ A,
                                       const float* __restrict__ Wg,
                                       const uint64_t (&ini)[4][4],
                                       float* __restrict__ Hs,
                                       float* __restrict__ sW, int t)
{
    const int tx = t & 15, ty = t >> 4;
    uint64_t acc[4][4];
#pragma unroll
    for (int i = 0; i < 4; i++)
#pragma unroll
        for (int p = 0; p < 4; p++) acc[i][p] = ini[i][p];
    constexpr int NT = KTOT / 32;
    stage_w1(Wg, 0, sW, t);
    cp_commit();
#pragma unroll
    for (int kt = 0; kt < NT; kt++) {
        if (kt + 1 < NT) {
            stage_w1(Wg, kt + 1, sW + ((kt + 1) & 1) * 4096, t);
            cp_commit();
            cp_wait<1>();
        } else cp_wait<0>();
        __syncthreads();
        const float* W = sW + (kt & 1) * 4096;
#pragma unroll
        for (int kk = 0; kk < 32; kk++) {
            int k = kt * 32 + kk;
            float4 a = *(const float4*)(A + k * 64 + ((ty ^ ((k >> 2) & 15)) << 2));
            ulonglong2 w01 = *(const ulonglong2*)(W + kk * 128 + tx * 8);
            ulonglong2 w23 = *(const ulonglong2*)(W + kk * 128 + tx * 8 + 4);
            uint64_t a0 = rep2(a.x), a1 = rep2(a.y), a2 = rep2(a.z), a3 = rep2(a.w);
            fma2(acc[0][0], a0, w01.x); fma2(acc[0][1], a0, w01.y);
            fma2(acc[0][2], a0, w23.x); fma2(acc[0][3], a0, w23.y);
            fma2(acc[1][0], a1, w01.x); fma2(acc[1][1], a1, w01.y);
            fma2(acc[1][2], a1, w23.x); fma2(acc[1][3], a1, w23.y);
            fma2(acc[2][0], a2, w01.x); fma2(acc[2][1], a2, w01.y);
            fma2(acc[2][2], a2, w23.x); fma2(acc[2][3], a2, w23.y);
            fma2(acc[3][0], a3, w01.x); fma2(acc[3][1], a3, w01.y);
            fma2(acc[3][2], a3, w23.x); fma2(acc[3][3], a3, w23.y);
        }
        __syncthreads();
    }
#pragma unroll
    for (int i = 0; i < 4; i++)
#pragma unroll
        for (int p = 0; p < 4; p++) {
            float2 v = unpack2(acc[i][p]);
            int h0 = tx * 8 + p * 2;
            int c = ((ty ^ ((h0 >> 2) & 15)) << 2) | i;
            Hs[h0 * 64 + c]       = fmaxf(v.x, 0.f);
            Hs[(h0 + 1) * 64 + c] = fmaxf(v.y, 0.f);
        }
    __syncthreads();
}

__device__ __forceinline__ void gemm_o(const float* __restrict__ Hs,
                                       const float* __restrict__ Wg,
                                       const float* __restrict__ b2,
                                       float* __restrict__ sW, int t,
                                       float o[4][4])
{
    const int tx = t & 15, ty = t >> 4;
    uint64_t b0 = *(const uint64_t*)(b2 + tx * 4);
    uint64_t b1 = *(const uint64_t*)(b2 + tx * 4 + 2);
    uint64_t acc[4][2];
#pragma unroll
    for (int i = 0; i < 4; i++) { acc[i][0] = b0; acc[i][1] = b1; }
    stage_w2(Wg, 0, sW, t);
    cp_commit();
#pragma unroll
    for (int kt = 0; kt < 2; kt++) {
        if (kt == 0) { stage_w2(Wg, 1, sW + 4096, t); cp_commit(); cp_wait<1>(); }
        else cp_wait<0>();
        __syncthreads();
        const float* W = sW + kt * 4096;
#pragma unroll 8
        for (int kk = 0; kk < 64; kk++) {
            int k = kt * 64 + kk;
            float4 a = *(const float4*)(Hs + k * 64 + ((ty ^ ((k >> 2) & 15)) << 2));
            ulonglong2 w = *(const ulonglong2*)(W + kk * 64 + tx * 4);
            uint64_t a0 = rep2(a.x), a1 = rep2(a.y), a2 = rep2(a.z), a3 = rep2(a.w);
            fma2(acc[0][0], a0, w.x); fma2(acc[0][1], a0, w.y);
            fma2(acc[1][0], a1, w.x); fma2(acc[1][1], a1, w.y);
            fma2(acc[2][0], a2, w.x); fma2(acc[2][1], a2, w.y);
            fma2(acc[3][0], a3, w.x); fma2(acc[3][1], a3, w.y);
        }
        __syncthreads();
    }
#pragma unroll
    for (int i = 0; i < 4; i++)
#pragma unroll
        for (int p = 0; p < 2; p++) {
            float2 v = unpack2(acc[i][p]);
            o[i][p * 2]     = v.x;
            o[i][p * 2 + 1] = v.y;
        }
}

// ===========================================================================
// Edge-kernel variants: half-size W tiles (16x128 / 32x64) so smem fits
// 3 CTAs/SM. Same 4-row x 8-col register tile, 256 threads.
// ===========================================================================
__device__ __forceinline__ void st16(const float* __restrict__ src,
                                     float* __restrict__ dst, int t) {
#pragma unroll
    for (int i = 0; i < 2; i++) {
        int idx = t + i * 256;             // 0..511 float4s (16x128)
        int r = idx >> 5, c4 = (idx & 31) << 2;
        cp16(dst + r * 128 + c4, src + r * 128 + c4);
    }
}
__device__ __forceinline__ void st32(const float* __restrict__ src,
                                     float* __restrict__ dst, int t) {
#pragma unroll
    for (int i = 0; i < 2; i++) {
        int idx = t + i * 256;             // 0..511 float4s (32x64)
        int r = idx >> 4, c4 = (idx & 15) << 2;
        cp16(dst + r * 64 + c4, src + r * 64 + c4);
    }
}

// GEMM1 (K=64): 4 pipelined 16-row W tiles through a 2x2048-float buffer.
__device__ __forceinline__ void gemm_h3(const float* __restrict__ A,
                                        const float* __restrict__ Wg,
                                        const uint64_t (&ini)[4][4],
                                        float* __restrict__ Hs,
                                        float* __restrict__ sW, int t)
{
    const int tx = t & 15, ty = t >> 4;
    uint64_t acc[4][4];
#pragma unroll
    for (int i = 0; i < 4; i++)
#pragma unroll
        for (int p = 0; p < 4; p++) acc[i][p] = ini[i][p];
    st16(Wg, sW, t);
    cp_commit();
#pragma unroll
    for (int kt = 0; kt < 4; kt++) {
        if (kt < 3) {
            st16(Wg + (kt + 1) * 16 * 128, sW + ((kt + 1) & 1) * 2048, t);
            cp_commit();
            cp_wait<1>();
        } else cp_wait<0>();
        __syncthreads();
        const float* W = sW + (kt & 1) * 2048;
#pragma unroll
        for (int kk = 0; kk < 16; kk++) {
            int k = kt * 16 + kk;
            float4 a = *(const float4*)(A + k * 64 + ((ty ^ ((k >> 2) & 15)) << 2));
            ulonglong2 w01 = *(const ulonglong2*)(W + kk * 128 + tx * 8);
            ulonglong2 w23 = *(const ulonglong2*)(W + kk * 128 + tx * 8 + 4);
            uint64_t a0 = rep2(a.x), a1 = rep2(a.y), a2 = rep2(a.z), a3 = rep2(a.w);
            fma2(acc[0][0], a0, w01.x); fma2(acc[0][1], a0, w01.y);
            fma2(acc[0][2], a0, w23.x); fma2(acc[0][3], a0, w23.y);
            fma2(acc[1][0], a1, w01.x); fma2(acc[1][1], a1, w01.y);
            fma2(acc[1][2], a1, w23.x); fma2(acc[1][3], a1, w23.y);
            fma2(acc[2][0], a2, w01.x); fma2(acc[2][1], a2, w01.y);
            fma2(acc[2][2], a2, w23.x); fma2(acc[2][3], a2, w23.y);
            fma2(acc[3][0], a3, w01.x); fma2(acc[3][1], a3, w01.y);
            fma2(acc[3][2], a3, w23.x); fma2(acc[3][3], a3, w23.y);
        }
        __syncthreads();
    }
#pragma unroll
    for (int i = 0; i < 4; i++)
#pragma unroll
        for (int p = 0; p < 4; p++) {
            float2 v = unpack2(acc[i][p]);
            int h0 = tx * 8 + p * 2;
            int c = ((ty ^ ((h0 >> 2) & 15)) << 2) | i;
            Hs[h0 * 64 + c]       = fmaxf(v.x, 0.f);
            Hs[(h0 + 1) * 64 + c] = fmaxf(v.y, 0.f);
        }
    __syncthreads();
}

// GEMM2 (K=128): 4 pipelined 32-row W2 tiles through a 2x2048-float buffer.
__device__ __forceinline__ void gemm_o3(const float* __restrict__ Hs,
                                        const float* __restrict__ Wg,
                                        const float* __restrict__ b2,
                                        float* __restrict__ sW, int t,
                                        float o[4][4])
{
    const int tx = t & 15, ty = t >> 4;
    uint64_t b0 = *(const uint64_t*)(b2 + tx * 4);
    uint64_t b1 = *(const uint64_t*)(b2 + tx * 4 + 2);
    uint64_t acc[4][2];
#pragma unroll
    for (int i = 0; i < 4; i++) { acc[i][0] = b0; acc[i][1] = b1; }
    st32(Wg, sW, t);
    cp_commit();
#pragma unroll
    for (int kt = 0; kt < 4; kt++) {
        if (kt < 3) {
            st32(Wg + (kt + 1) * 32 * 64, sW + ((kt + 1) & 1) * 2048, t);
            cp_commit();
            cp_wait<1>();
        } else cp_wait<0>();
        __syncthreads();
        const float* W = sW + (kt & 1) * 2048;
#pragma unroll
        for (int kk = 0; kk < 32; kk++) {
            int k = kt * 32 + kk;
            float4 a = *(const float4*)(Hs + k * 64 + ((ty ^ ((k >> 2) & 15)) << 2));
            ulonglong2 w = *(const ulonglong2*)(W + kk * 64 + tx * 4);
            uint64_t a0 = rep2(a.x), a1 = rep2(a.y), a2 = rep2(a.z), a3 = rep2(a.w);
            fma2(acc[0][0], a0, w.x); fma2(acc[0][1], a0, w.y);
            fma2(acc[1][0], a1, w.x); fma2(acc[1][1], a1, w.y);
            fma2(acc[2][0], a2, w.x); fma2(acc[2][1], a2, w.y);
            fma2(acc[3][0], a3, w.x); fma2(acc[3][1], a3, w.y);
        }
        __syncthreads();
    }
#pragma unroll
    for (int i = 0; i < 4; i++)
#pragma unroll
        for (int p = 0; p < 2; p++) {
            float2 v = unpack2(acc[i][p]);
            o[i][p * 2]     = v.x;
            o[i][p * 2 + 1] = v.y;
        }
}

// ---------------------------------------------------------------------------
// Edge kernel: 64 edges/CTA, 256 threads, 3 CTAs/SM.
// smem floats: A[4096] | sW[2x2048] | Hs[8192] | idx[192] = 66.3 KB
// ---------------------------------------------------------------------------
#define SME_A  0
#define SME_W  4096
#define SME_H  8192
#define SME_IX 16384
#define SME_FLOATS (16384 + 192)

__global__ void __launch_bounds__(256, 3)
edge_kernel(const int* __restrict__ ei,
            const float* __restrict__ e, const int* __restrict__ batch,
            const float* __restrict__ We1, const float* __restrict__ We2,
            const float* __restrict__ be2,
            const float* __restrict__ Wa1, const float* __restrict__ Wa2,
            const float* __restrict__ ba2,
            float* __restrict__ e_out)
{
    extern __shared__ float smem[];
    float* A  = smem + SME_A;
    float* sW = smem + SME_W;
    float* Hs = smem + SME_H;
    int* srcs = (int*)(smem + SME_IX);
    int* dsts = srcs + 64;
    int* gidx = dsts + 64;
    const int t = threadIdx.x;
    const int eb = blockIdx.x * 64;

    if (t < 64) {
        int s_ = ei[eb + t], d_ = ei[Ee + eb + t];
        srcs[t] = s_; dsts[t] = d_; gidx[t] = batch[s_];
    }
    __syncthreads();

    const int tx = t & 15, ty = t >> 4;

    // L2-prefetch all table lines (both MLPs) before doing anything else:
    // overlaps scattered-gather latency with A-build + W staging.
#pragma unroll
    for (int i = 0; i < 4; i++) {
        int row = ty * 4 + i;
        const float* xs = g_Xs + (size_t)srcs[row] * 256 + tx * 8;
        const float* xd = g_Xd + (size_t)dsts[row] * 256 + tx * 8;
        pfL2(xs); pfL2(xs + 128);
        pfL2(xd); pfL2(xd + 128);
    }

    // Build A = e tile, K-major, xor-swizzled
    for (int i = t; i < 1024; i += 256) {
        int m = i >> 4, k4 = (i & 15) << 2;
        int c = ((((m >> 2) ^ (k4 >> 2)) & 15) << 2) | (m & 3);
        float4 v = *(const float4*)&e[(size_t)(eb + m) * 64 + k4];
        A[k4 * 64 + c] = v.x; A[(k4 + 1) * 64 + c] = v.y;
        A[(k4 + 2) * 64 + c] = v.z; A[(k4 + 3) * 64 + c] = v.w;
    }

    // --- MLP_e: acc init from gathered tables, K=64 GEMM on e ---
    uint64_t ini[4][4];
#pragma unroll
    for (int i = 0; i < 4; i++) {
        int row = ty * 4 + i;
        const float* up = g_U1e + gidx[row] * 128 + tx * 8;
        const float* xs = g_Xs + (size_t)srcs[row] * 256 + tx * 8;
        const float* xd = g_Xd + (size_t)dsts[row] * 256 + tx * 8;
#pragma unroll
        for (int p = 0; p < 4; p++)
            ini[i][p] = add2(*(const uint64_t*)(up + p * 2),
                        add2(*(const uint64_t*)(xs + p * 2),
                             *(const uint64_t*)(xd + p * 2)));
    }
    __syncthreads();   // A-build complete

    gemm_h3(A, We1 + 128 * 128, ini, Hs, sW, t);
    float enew[4][4];
    gemm_o3(Hs, We2, be2, sW, t, enew);
    __syncthreads();                 // all Hs reads done; reuse Hs as eagg

    float* eagg = Hs;                // 16*64 floats overlay
#pragma unroll
    for (int i = 0; i < 4; i++) eagg[t + i * 256] = 0.f;
    __syncthreads();

    // write e_new; splice into A; accumulate per-graph sums
#pragma unroll
    for (int i = 0; i < 4; i++) {
        int row = ty * 4 + i;
        *(float4*)&e_out[(size_t)(eb + row) * 64 + tx * 4] =
            make_float4(enew[i][0], enew[i][1], enew[i][2], enew[i][3]);
        int cA = (((ty ^ tx) & 15) << 2) | i;
        int g = gidx[row];
#pragma unroll
        for (int j = 0; j < 4; j++) {
            A[(tx * 4 + j) * 64 + cA] = enew[i][j];
            atomicAdd(&eagg[g * 64 + tx * 4 + j], enew[i][j]);
        }
    }
    __syncthreads();
    {
        int g = t >> 4, c4 = (t & 15) << 2;
        const float* p = &eagg[g * 64 + c4];
        red4(&g_eagg[g * 64 + c4], p[0], p[1], p[2], p[3]);
    }

    // --- MLP_a: second halves of the tables ---
#pragma unroll
    for (int i = 0; i < 4; i++) {
        int row = ty * 4 + i;
        const float* up = g_U1a + gidx[row] * 128 + tx * 8;
        const float* xs = g_Xs + (size_t)srcs[row] * 256 + 128 + tx * 8;
        const float* xd = g_Xd + (size_t)dsts[row] * 256 + 128 + tx * 8;
#pragma unroll
        for (int p = 0; p < 4; p++)
            ini[i][p] = add2(*(const uint64_t*)(up + p * 2),
                        add2(*(const uint64_t*)(xs + p * 2),
                             *(const uint64_t*)(xd + p * 2)));
    }
    gemm_h3(A, Wa1 + 128 * 128, ini, Hs, sW, t);
    float av[4][4];
    gemm_o3(Hs, Wa2, ba2, sW, t, av);

    // scatter e_new * sigmoid(a) into g_agg[dst]
#pragma unroll
    for (int i = 0; i < 4; i++) {
        int row = ty * 4 + i;
        int dst = dsts[row];
        float w0 = enew[i][0] / (1.f + __expf(-av[i][0]));
        float w1 = enew[i][1] / (1.f + __expf(-av[i][1]));
        float w2 = enew[i][2] / (1.f + __expf(-av[i][2]));
        float w3 = enew[i][3] / (1.f + __expf(-av[i][3]));
        red4(&g_agg[(size_t)dst * 64 + tx * 4], w0, w1, w2, w3);
    }
}

// ---------------------------------------------------------------------------
// Node kernel: 64 nodes/CTA, 256 threads (R5-proven shape)
// ---------------------------------------------------------------------------
#define SMN_A  0
#define SMN_W  4096
#define SMN_H  12288
#define SMN_IX 20480
#define SMN_FLOATS (20480 + 64)

__global__ void __launch_bounds__(256, 2)
node_kernel(const int* __restrict__ batch,
            const float* __restrict__ Wn1, const float* __restrict__ Wn2,
            const float* __restrict__ bn2,
            float* __restrict__ x_out)
{
    extern __shared__ float smem[];
    float* A  = smem + SMN_A;
    float* sW = smem + SMN_W;
    float* Hs = smem + SMN_H;
    int* gid  = (int*)(smem + SMN_IX);
    const int t = threadIdx.x;
    const int nb = blockIdx.x * 64;

    if (t < 64) {
        int r = nb + t; if (r >= Nn) r = Nn - 1;
        gid[t] = batch[r];
    }
    __syncthreads();

    for (int i = t; i < 1024; i += 256) {
        int m = i >> 4, k4 = (i & 15) << 2;
        int r = nb + m; if (r >= Nn) r = Nn - 1;
        int c = ((((m >> 2) ^ (k4 >> 2)) & 15) << 2) | (m & 3);
        float4 v = *(const float4*)&g_agg[(size_t)r * 64 + k4];
        A[k4 * 64 + c] = v.x; A[(k4 + 1) * 64 + c] = v.y;
        A[(k4 + 2) * 64 + c] = v.z; A[(k4 + 3) * 64 + c] = v.w;
    }

    const int tx = t & 15, ty = t >> 4;
    uint64_t ini[4][4];
#pragma unroll
    for (int i = 0; i < 4; i++) {
        int row = ty * 4 + i;
        int r = nb + row; if (r >= Nn) r = Nn - 1;
        const float* up = g_U1n + gid[row] * 128 + tx * 8;
        const float* xn = g_Xn + (size_t)r * 128 + tx * 8;
#pragma unroll
        for (int p = 0; p < 4; p++)
            ini[i][p] = add2(*(const uint64_t*)(up + p * 2),
                             *(const uint64_t*)(xn + p * 2));
    }
    __syncthreads();

    gemm_h<64>(A, Wn1 + 64 * 128, ini, Hs, sW, t);
    float xo[4][4];
    gemm_o(Hs, Wn2, bn2, sW, t, xo);
    __syncthreads();

    float* nagg = Hs;
#pragma unroll
    for (int i = 0; i < 4; i++) nagg[t + i * 256] = 0.f;
    __syncthreads();

#pragma unroll
    for (int i = 0; i < 4; i++) {
        int row = ty * 4 + i;
        int r = nb + row;
        if (r < Nn) {
            *(float4*)&x_out[(size_t)r * 64 + tx * 4] =
                make_float4(xo[i][0], xo[i][1], xo[i][2], xo[i][3]);
            int g = gid[row];
#pragma unroll
            for (int j = 0; j < 4; j++)
                atomicAdd(&nagg[g * 64 + tx * 4 + j], xo[i][j]);
        }
    }
    __syncthreads();
    {
        int g = t >> 4, c4 = (t & 15) << 2;
        const float* p = &nagg[g * 64 + c4];
        red4(&g_nagg[g * 64 + c4], p[0], p[1], p[2], p[3]);
    }
}

// ---------------------------------------------------------------------------
// Prep tables: per 64-node tile, 5 x (64x128) GEMMs into g_Xs / g_Xd / g_Xn.
// ---------------------------------------------------------------------------
#define SPT_FLOATS 12288

__global__ void __launch_bounds__(256, 2)
prep_tables(const float* __restrict__ x,
            const float* __restrict__ We1, const float* __restrict__ Wa1,
            const float* __restrict__ Wn1)
{
    extern __shared__ float smem[];
    float* A  = smem;
    float* sW = smem + 4096;
    const int t = threadIdx.x;
    const int nb = blockIdx.x * 64;
    const int tx = t & 15, ty = t >> 4;

    for (int i = t; i < 1024; i += 256) {
        int m = i >> 4, k4 = (i & 15) << 2;
        int r = nb + m; if (r >= Nn) r = Nn - 1;
        int c = ((((m >> 2) ^ (k4 >> 2)) & 15) << 2) | (m & 3);
        float4 v = *(const float4*)&x[(size_t)r * 64 + k4];
        A[k4 * 64 + c] = v.x; A[(k4 + 1) * 64 + c] = v.y;
        A[(k4 + 2) * 64 + c] = v.z; A[(k4 + 3) * 64 + c] = v.w;
    }
    __syncthreads();

    const float* Ws[5] = { We1, Wa1, We1 + 64 * 128, Wa1 + 64 * 128, Wn1 };
    float* outs[5] = { g_Xs, g_Xs + 128, g_Xd, g_Xd + 128, g_Xn };
    const int stride[5] = { 256, 256, 256, 256, 128 };

#pragma unroll 1
    for (int seg = 0; seg < 5; seg++) {
        const float* W = Ws[seg];
        stage_w1(W, 0, sW, t);
        stage_w1(W, 1, sW + 4096, t);
        cp_commit();
        cp_wait<0>();
        __syncthreads();
        uint64_t acc[4][4];
#pragma unroll
        for (int i = 0; i < 4; i++)
#pragma unroll
            for (int p = 0; p < 4; p++) acc[i][p] = 0ull;
#pragma unroll
        for (int kt = 0; kt < 2; kt++) {
            const float* Wp = sW + kt * 4096;
#pragma unroll
            for (int kk = 0; kk < 32; kk++) {
                int k = kt * 32 + kk;
                float4 a = *(const float4*)(A + k * 64 + ((ty ^ ((k >> 2) & 15)) << 2));
                ulonglong2 w01 = *(const ulonglong2*)(Wp + kk * 128 + tx * 8);
                ulonglong2 w23 = *(const ulonglong2*)(Wp + kk * 128 + tx * 8 + 4);
                uint64_t a0 = rep2(a.x), a1 = rep2(a.y), a2 = rep2(a.z), a3 = rep2(a.w);
                fma2(acc[0][0], a0, w01.x); fma2(acc[0][1], a0, w01.y);
                fma2(acc[0][2], a0, w23.x); fma2(acc[0][3], a0, w23.y);
                fma2(acc[1][0], a1, w01.x); fma2(acc[1][1], a1, w01.y);
                fma2(acc[1][2], a1, w23.x); fma2(acc[1][3], a1, w23.y);
                fma2(acc[2][0], a2, w01.x); fma2(acc[2][1], a2, w01.y);
                fma2(acc[2][2], a2, w23.x); fma2(acc[2][3], a2, w23.y);
                fma2(acc[3][0], a3, w01.x); fma2(acc[3][1], a3, w01.y);
                fma2(acc[3][2], a3, w23.x); fma2(acc[3][3], a3, w23.y);
            }
        }
#pragma unroll
        for (int i = 0; i < 4; i++) {
            int r = nb + ty * 4 + i;
            if (r < Nn) {
                float* op = outs[seg] + (size_t)r * stride[seg] + tx * 8;
                float2 v0 = unpack2(acc[i][0]), v1 = unpack2(acc[i][1]);
                float2 v2 = unpack2(acc[i][2]), v3 = unpack2(acc[i][3]);
                *(float4*)op       = make_float4(v0.x, v0.y, v1.x, v1.y);
                *(float4*)(op + 4) = make_float4(v2.x, v2.y, v3.x, v3.y);
            }
        }
        __syncthreads();
    }
}

// ---------------------------------------------------------------------------
// Global kernel: 16 blocks x 128 threads
// ---------------------------------------------------------------------------
__global__ void __launch_bounds__(128)
global_kernel(const float* __restrict__ u,
              const float* __restrict__ Wg1, const float* __restrict__ bg1,
              const float* __restrict__ Wg2, const float* __restrict__ bg2,
              float* __restrict__ u_out)
{
    __shared__ float in[192];
    __shared__ float hid[128];
    const int g = blockIdx.x, t = threadIdx.x;
    if (t < 64) {
        in[t]       = u[g * 64 + t];
        in[64 + t]  = g_nagg[g * 64 + t];
        in[128 + t] = g_eagg[g * 64 + t];
    }
    __syncthreads();
    float acc = bg1[t];
#pragma unroll 8
    for (int k = 0; k < 192; k++) acc += in[k] * Wg1[(size_t)k * 128 + t];
    hid[t] = fmaxf(acc, 0.f);
    __syncthreads();
    if (t < 64) {
        float a2 = bg2[t];
#pragma unroll 8
        for (int k = 0; k < 128; k++) a2 += hid[k] * Wg2[(size_t)k * 64 + t];
        u_out[g * 64 + t] = a2;
    }
}

// ---------------------------------------------------------------------------
// Prep kernel: zero aggregates + precompute U1 tables (bias folded)
// ---------------------------------------------------------------------------
__global__ void __launch_bounds__(256)
prep_kernel(const float* __restrict__ u,
            const float* __restrict__ We1, const float* __restrict__ be1,
            const float* __restrict__ Wa1, const float* __restrict__ ba1,
            const float* __restrict__ Wn1, const float* __restrict__ bn1)
{
    const int b = blockIdx.x, t = threadIdx.x;
    size_t idx = (size_t)b * 256 + t;
    const size_t n4 = (size_t)Nn * Dd / 4;
    float4 z = make_float4(0.f, 0.f, 0.f, 0.f);
    for (size_t i = idx; i < n4; i += (size_t)gridDim.x * 256) ((float4*)g_agg)[i] = z;
    if (idx < 256) { ((float4*)g_nagg)[idx] = z; ((float4*)g_eagg)[idx] = z; }
    if (b < 3) {
        const float* W    = (b == 0) ? We1 + 192 * 128 : (b == 1) ? Wa1 + 192 * 128 : Wn1 + 128 * 128;
        const float* bias = (b == 0) ? be1 : (b == 1) ? ba1 : bn1;
        float* out        = (b == 0) ? g_U1e : (b == 1) ? g_U1a : g_U1n;
        for (int i = t; i < Gg * Hh; i += 256) {
            int g = i >> 7, h = i & 127;
            float acc = bias[h];
#pragma unroll 8
            for (int k = 0; k < 64; k++) acc += u[g * 64 + k] * W[(size_t)k * 128 + h];
            out[i] = acc;
        }
    }
}

extern "C" void kernel_launch(void* const* d_in, const int* in_sizes, int n_in,
                              void* d_out, int out_size)
{
    const float* x     = (const float*)d_in[0];
    const int*   ei    = (const int*)d_in[1];
    const float* e     = (const float*)d_in[2];
    const float* u     = (const float*)d_in[3];
    const int*   batch = (const int*)d_in[4];
    const float* We1 = (const float*)d_in[5];
    const float* be1 = (const float*)d_in[6];
    const float* We2 = (const float*)d_in[7];
    const float* be2 = (const float*)d_in[8];
    const float* Wa1 = (const float*)d_in[9];
    const float* ba1 = (const float*)d_in[10];
    const float* Wa2 = (const float*)d_in[11];
    const float* ba2 = (const float*)d_in[12];
    const float* Wn1 = (const float*)d_in[13];
    const float* bn1 = (const float*)d_in[14];
    const float* Wn2 = (const float*)d_in[15];
    const float* bn2 = (const float*)d_in[16];
    const float* Wg1 = (const float*)d_in[17];
    const float* bg1 = (const float*)d_in[18];
    const float* Wg2 = (const float*)d_in[19];
    const float* bg2 = (const float*)d_in[20];

    float* out   = (float*)d_out;
    float* x_out = out;
    float* e_out = out + (size_t)Nn * Dd;
    float* u_out = out + (size_t)Nn * Dd + (size_t)Ee * Dd;

    cudaFuncSetAttribute(edge_kernel, cudaFuncAttributeMaxDynamicSharedMemorySize,
                         SME_FLOATS * 4);
    cudaFuncSetAttribute(node_kernel, cudaFuncAttributeMaxDynamicSharedMemorySize,
                         SMN_FLOATS * 4);
    cudaFuncSetAttribute(prep_tables, cudaFuncAttributeMaxDynamicSharedMemorySize,
                         SPT_FLOATS * 4);

    prep_kernel<<<3125, 256>>>(u, We1, be1, Wa1, ba1, Wn1, bn1);
    prep_tables<<<(Nn + 63) / 64, 256, SPT_FLOATS * 4>>>(x, We1, Wa1, Wn1);
    edge_kernel<<<Ee / 64, 256, SME_FLOATS * 4>>>(ei, e, batch,
                                                  We1, We2, be2, Wa1, Wa2, ba2, e_out);
    node_kernel<<<(Nn + 63) / 64, 256, SMN_FLOATS * 4>>>(batch, Wn1, Wn2, bn2, x_out);
    global_kernel<<<Gg, 128>>>(u, Wg1, bg1, Wg2, bg2, u_out);
}

// round 14
// speedup vs baseline: 1.9283x; 1.3827x over previous
#include <cuda_runtime.h>
#include <stdint.h>
#include <math.h>

#define Nn 50000
#define Ee 800000
#define Gg 16
#define Dd 64
#define Hh 128

__device__ float g_agg[Nn * Dd];
__device__ float g_nagg[Gg * Dd];
__device__ float g_eagg[Gg * Dd];
__device__ float g_U1e[Gg * Hh];
__device__ float g_U1a[Gg * Hh];
__device__ float g_U1n[Gg * Hh];
__device__ float g_Xs[(size_t)Nn * 256];
__device__ float g_Xd[(size_t)Nn * 256];
__device__ float g_Xn[(size_t)Nn * 128];
// tf32 weight tiles in mma.sync fragment-packed order:
// B1: [ntile(16)][ktile(8)][64]  where entry 2*l+hi = W1[k][n],
//     l = (n&7)*4 + (k&3), hi = (k>>2)&1, n = ntile*8+.., k = ktile*8+..
__device__ float g_B1e[8192];
__device__ float g_B1a[8192];
// B2: [ntile(8)][ktile(16)][64], same packing, W2 [128k][64n]
__device__ float g_B2e[8192];
__device__ float g_B2a[8192];

// ---------------------------------------------------------------------------
__device__ __forceinline__ void fma2(uint64_t& d, uint64_t a, uint64_t b) {
    asm("fma.rn.f32x2 %0, %1, %2, %0;" : "+l"(d) : "l"(a), "l"(b));
}
__device__ __forceinline__ uint64_t add2(uint64_t a, uint64_t b) {
    uint64_t r; asm("add.rn.f32x2 %0, %1, %2;" : "=l"(r) : "l"(a), "l"(b)); return r;
}
__device__ __forceinline__ uint64_t rep2(float x) {
    uint64_t r; asm("mov.b64 %0, {%1, %1};" : "=l"(r) : "f"(x)); return r;
}
__device__ __forceinline__ float2 unpack2(uint64_t v) {
    float2 r; asm("mov.b64 {%0, %1}, %2;" : "=f"(r.x), "=f"(r.y) : "l"(v)); return r;
}
__device__ __forceinline__ void red4(float* p, float a, float b, float c, float d) {
    asm volatile("red.global.add.v4.f32 [%0], {%1,%2,%3,%4};"
                 :: "l"(p), "f"(a), "f"(b), "f"(c), "f"(d) : "memory");
}
__device__ __forceinline__ void red2(float* p, float a, float b) {
    asm volatile("red.global.add.v2.f32 [%0], {%1,%2};"
                 :: "l"(p), "f"(a), "f"(b) : "memory");
}
__device__ __forceinline__ void cp16(float* smem_dst, const float* gsrc) {
    uint32_t s = (uint32_t)__cvta_generic_to_shared(smem_dst);
    asm volatile("cp.async.cg.shared.global [%0], [%1], 16;" :: "r"(s), "l"(gsrc));
}
__device__ __forceinline__ void cp_commit() { asm volatile("cp.async.commit_group;"); }
template<int N> __device__ __forceinline__ void cp_wait() {
    asm volatile("cp.async.wait_group %0;" :: "n"(N));
}
__device__ __forceinline__ void pfL2(const float* p) {
    asm volatile("prefetch.global.L2 [%0];" :: "l"(p));
}
__device__ __forceinline__ uint32_t f2tf32(float x) {
    uint32_t r; asm("cvt.rna.tf32.f32 %0, %1;" : "=r"(r) : "f"(x)); return r;
}
__device__ __forceinline__ float tf32r(float x) { return __uint_as_float(f2tf32(x)); }

// mma.sync m16n8k8 tf32 (sm_80-level PTX; compiles for plain sm_103)
__device__ __forceinline__ void mma8(float c[4], uint32_t a0, uint32_t a1,
                                     uint32_t a2, uint32_t a3,
                                     uint32_t b0, uint32_t b1) {
    asm volatile("mma.sync.aligned.m16n8k8.row.col.f32.tf32.tf32.f32 "
                 "{%0,%1,%2,%3}, {%4,%5,%6,%7}, {%8,%9}, {%0,%1,%2,%3};"
                 : "+f"(c[0]), "+f"(c[1]), "+f"(c[2]), "+f"(c[3])
                 : "r"(a0), "r"(a1), "r"(a2), "r"(a3), "r"(b0), "r"(b1));
}

// ===========================================================================
// Edge kernel (mma.sync tf32): 64 edges/CTA, 256 threads (8 warps), 2 CTAs/SM
// Warp w: m-tile (w&3)*16.  GEMM1: n-tiles (w>>2)*8..+8 (N=128).
//                           GEMM2: n-tiles (w>>2)*4..+4 (N=64).
// SMEM: AH[64][132] (A then H, phase-overlaid) | B1 8192 | B2 8192 | eagg | idx
// ===========================================================================
#define EAH   0
#define EB1   8448
#define EB2   16640
#define EEAGG 24832
#define EIX   25856
#define E_FLOATS (25856 + 192)

// GEMM1: C[8][4] += A(64x64, AH cols 0..63) @ B1pack
__device__ __forceinline__ void gemm1_mma(const float* AH, const float* B1,
                                          int w, int lane, float c[8][4]) {
    const uint32_t* A32 = (const uint32_t*)AH;
    const uint32_t* Bp  = (const uint32_t*)B1;
    int r0 = (w & 3) * 16 + (lane >> 2);
    int kq = lane & 3;
    int nb8 = (w >> 2) * 8;
#pragma unroll
    for (int kt = 0; kt < 8; kt++) {
        int k0 = kt * 8 + kq;
        uint32_t a0 = A32[r0 * 132 + k0];
        uint32_t a1 = A32[(r0 + 8) * 132 + k0];
        uint32_t a2 = A32[r0 * 132 + k0 + 4];
        uint32_t a3 = A32[(r0 + 8) * 132 + k0 + 4];
#pragma unroll
        for (int nt = 0; nt < 8; nt++) {
            const uint32_t* bp = Bp + (((nb8 + nt) * 8 + kt) << 6) + 2 * lane;
            mma8(c[nt], a0, a1, a2, a3, bp[0], bp[1]);
        }
    }
}
// GEMM2: C[4][4] += H(64x128) @ B2pack
__device__ __forceinline__ void gemm2_mma(const float* AH, const float* B2,
                                          int w, int lane, float c[4][4]) {
    const uint32_t* A32 = (const uint32_t*)AH;
    const uint32_t* Bp  = (const uint32_t*)B2;
    int r0 = (w & 3) * 16 + (lane >> 2);
    int kq = lane & 3;
    int nb4 = (w >> 2) * 4;
#pragma unroll
    for (int kt = 0; kt < 16; kt++) {
        int k0 = kt * 8 + kq;
        uint32_t a0 = A32[r0 * 132 + k0];
        uint32_t a1 = A32[(r0 + 8) * 132 + k0];
        uint32_t a2 = A32[r0 * 132 + k0 + 4];
        uint32_t a3 = A32[(r0 + 8) * 132 + k0 + 4];
#pragma unroll
        for (int nt = 0; nt < 4; nt++) {
            const uint32_t* bp = Bp + (((nb4 + nt) * 16 + kt) << 6) + 2 * lane;
            mma8(c[nt], a0, a1, a2, a3, bp[0], bp[1]);
        }
    }
}
// Epilogue: H = relu(C + Xs + Xd + U1), tf32-round, store into AH
__device__ __forceinline__ void epi_h(float* AH, const float c1[8][4],
                                      const float* xs0, const float* xd0, const float* u0,
                                      const float* xs1, const float* xd1, const float* u1,
                                      int r0, int r1, int nb, int q) {
#pragma unroll
    for (int nt = 0; nt < 8; nt++) {
        int n = nb + nt * 8 + 2 * q;
        float2 sa = *(const float2*)(xs0 + n), da = *(const float2*)(xd0 + n);
        float2 ua = *(const float2*)(u0 + n);
        float2 sb = *(const float2*)(xs1 + n), db = *(const float2*)(xd1 + n);
        float2 ub = *(const float2*)(u1 + n);
        float h0 = fmaxf(c1[nt][0] + sa.x + da.x + ua.x, 0.f);
        float h1 = fmaxf(c1[nt][1] + sa.y + da.y + ua.y, 0.f);
        float h2 = fmaxf(c1[nt][2] + sb.x + db.x + ub.x, 0.f);
        float h3 = fmaxf(c1[nt][3] + sb.y + db.y + ub.y, 0.f);
        *(float2*)(AH + r0 * 132 + n) = make_float2(tf32r(h0), tf32r(h1));
        *(float2*)(AH + r1 * 132 + n) = make_float2(tf32r(h2), tf32r(h3));
    }
}

__global__ void __launch_bounds__(256, 2)
edge_kernel(const int* __restrict__ ei,
            const float* __restrict__ e, const int* __restrict__ batch,
            const float* __restrict__ be2, const float* __restrict__ ba2,
            float* __restrict__ e_out)
{
    extern __shared__ float S[];
    float* AH   = S + EAH;
    float* B1   = S + EB1;
    float* B2   = S + EB2;
    float* eagg = S + EEAGG;
    int* srcs = (int*)(S + EIX);
    int* dsts = srcs + 64;
    int* gidx = dsts + 64;
    const int t = threadIdx.x;
    const int w = t >> 5, lane = t & 31;
    const int q = lane & 3;
    const int r0 = (w & 3) * 16 + (lane >> 2), r1 = r0 + 8;
    const int eb = blockIdx.x * 64;

    if (t < 64) {
        int s_ = ei[eb + t], d_ = ei[Ee + eb + t];
        srcs[t] = s_; dsts[t] = d_; gidx[t] = batch[s_];
    }
#pragma unroll
    for (int i = 0; i < 4; i++) eagg[t + i * 256] = 0.f;

    // Stage B1e/B2e packs (32 KB each)
#pragma unroll
    for (int i = 0; i < 8; i++) cp16(B1 + (t + i * 256) * 4, g_B1e + (t + i * 256) * 4);
#pragma unroll
    for (int i = 0; i < 8; i++) cp16(B2 + (t + i * 256) * 4, g_B2e + (t + i * 256) * 4);
    cp_commit();

    // Build A = e tile [64m][cols 0..63], tf32-rounded (stride 132 conflict-lite)
    for (int i = t; i < 1024; i += 256) {
        int m = i >> 4, k4 = (i & 15) << 2;
        float4 v = *(const float4*)&e[(size_t)(eb + m) * 64 + k4];
        *(float4*)(AH + m * 132 + k4) =
            make_float4(tf32r(v.x), tf32r(v.y), tf32r(v.z), tf32r(v.w));
    }
    cp_wait<0>();
    __syncthreads();

    const int s0 = srcs[r0], d0 = dsts[r0], gg0 = gidx[r0];
    const int s1 = srcs[r1], d1 = dsts[r1], gg1 = gidx[r1];
    const float* xs0 = g_Xs + (size_t)s0 * 256;
    const float* xd0 = g_Xd + (size_t)d0 * 256;
    const float* xs1 = g_Xs + (size_t)s1 * 256;
    const float* xd1 = g_Xd + (size_t)d1 * 256;
    // L2 prefetch of table rows (overlaps with GEMM1)
    pfL2(xs0 + 2 * q * 16); pfL2(xd0 + 2 * q * 16);
    pfL2(xs1 + 2 * q * 16); pfL2(xd1 + 2 * q * 16);
    pfL2(xs0 + 128 + 2 * q * 16); pfL2(xd0 + 128 + 2 * q * 16);
    pfL2(xs1 + 128 + 2 * q * 16); pfL2(xd1 + 128 + 2 * q * 16);

    // ======== MLP_e ========
    float c1[8][4];
#pragma unroll
    for (int i = 0; i < 8; i++) { c1[i][0]=0.f; c1[i][1]=0.f; c1[i][2]=0.f; c1[i][3]=0.f; }
    gemm1_mma(AH, B1, w, lane, c1);
    __syncthreads();                       // all A reads done
    // start B1a reload (B1 free)
#pragma unroll
    for (int i = 0; i < 8; i++) cp16(B1 + (t + i * 256) * 4, g_B1a + (t + i * 256) * 4);
    cp_commit();

    epi_h(AH, c1, xs0, xd0, g_U1e + gg0 * 128, xs1, xd1, g_U1e + gg1 * 128,
          r0, r1, (w >> 2) * 64, q);
    __syncthreads();                       // H visible

    float c2[4][4];
#pragma unroll
    for (int i = 0; i < 4; i++) { c2[i][0]=0.f; c2[i][1]=0.f; c2[i][2]=0.f; c2[i][3]=0.f; }
    gemm2_mma(AH, B2, w, lane, c2);
    __syncthreads();                       // all H reads done

    // start B2a reload (B2 free)
#pragma unroll
    for (int i = 0; i < 8; i++) cp16(B2 + (t + i * 256) * 4, g_B2a + (t + i * 256) * 4);
    cp_commit();

    // Epilogue2: e_new = C2 + be2 ; e_out ; splice into AH ; eagg
    float en[4][4];
    const int nb2 = (w >> 2) * 32;
#pragma unroll
    for (int nt = 0; nt < 4; nt++) {
        int n = nb2 + nt * 8 + 2 * q;
        float2 b = *(const float2*)(be2 + n);
        en[nt][0] = c2[nt][0] + b.x; en[nt][1] = c2[nt][1] + b.y;
        en[nt][2] = c2[nt][2] + b.x; en[nt][3] = c2[nt][3] + b.y;
        *(float2*)&e_out[(size_t)(eb + r0) * 64 + n] = make_float2(en[nt][0], en[nt][1]);
        *(float2*)&e_out[(size_t)(eb + r1) * 64 + n] = make_float2(en[nt][2], en[nt][3]);
        *(float2*)(AH + r0 * 132 + n) = make_float2(tf32r(en[nt][0]), tf32r(en[nt][1]));
        *(float2*)(AH + r1 * 132 + n) = make_float2(tf32r(en[nt][2]), tf32r(en[nt][3]));
        atomicAdd(&eagg[gg0 * 64 + n],     en[nt][0]);
        atomicAdd(&eagg[gg0 * 64 + n + 1], en[nt][1]);
        atomicAdd(&eagg[gg1 * 64 + n],     en[nt][2]);
        atomicAdd(&eagg[gg1 * 64 + n + 1], en[nt][3]);
    }
    __syncthreads();                       // splice + eagg complete
    {
        int g = t >> 4, c4 = (t & 15) << 2;
        const float* p = &eagg[g * 64 + c4];
        red4(&g_eagg[g * 64 + c4], p[0], p[1], p[2], p[3]);
    }
    cp_wait<1>();                          // B1a ready (B2a may be in flight)
    __syncthreads();

    // ======== MLP_a ========
#pragma unroll
    for (int i = 0; i < 8; i++) { c1[i][0]=0.f; c1[i][1]=0.f; c1[i][2]=0.f; c1[i][3]=0.f; }
    gemm1_mma(AH, B1, w, lane, c1);
    __syncthreads();
    epi_h(AH, c1, xs0 + 128, xd0 + 128, g_U1a + gg0 * 128,
          xs1 + 128, xd1 + 128, g_U1a + gg1 * 128, r0, r1, (w >> 2) * 64, q);
    cp_wait<0>();                          // B2a ready
    __syncthreads();

#pragma unroll
    for (int i = 0; i < 4; i++) { c2[i][0]=0.f; c2[i][1]=0.f; c2[i][2]=0.f; c2[i][3]=0.f; }
    gemm2_mma(AH, B2, w, lane, c2);

    // Epilogue4: scatter e_new * sigmoid(C2a + ba2)
#pragma unroll
    for (int nt = 0; nt < 4; nt++) {
        int n = nb2 + nt * 8 + 2 * q;
        float2 b = *(const float2*)(ba2 + n);
        float w00 = en[nt][0] / (1.f + __expf(-(c2[nt][0] + b.x)));
        float w01 = en[nt][1] / (1.f + __expf(-(c2[nt][1] + b.y)));
        float w10 = en[nt][2] / (1.f + __expf(-(c2[nt][2] + b.x)));
        float w11 = en[nt][3] / (1.f + __expf(-(c2[nt][3] + b.y)));
        red2(&g_agg[(size_t)d0 * 64 + n], w00, w01);
        red2(&g_agg[(size_t)d1 * 64 + n], w10, w11);
    }
}

// ===========================================================================
// FFMA2 helpers for node / prep kernels (R5-proven)
// ===========================================================================
__device__ __forceinline__ void stage_w1(const float* __restrict__ Wg, int kt,
                                         float* __restrict__ dst, int t) {
    const float* src = Wg + (size_t)kt * 32 * 128;
#pragma unroll
    for (int i = 0; i < 4; i++) {
        int idx = t + i * 256;
        int r = idx >> 5, c4 = (idx & 31) << 2;
        cp16(dst + r * 128 + c4, src + r * 128 + c4);
    }
}
__device__ __forceinline__ void stage_w2(const float* __restrict__ Wg, int kt,
                                         float* __restrict__ dst, int t) {
    const float* src = Wg + (size_t)kt * 64 * 64;
#pragma unroll
    for (int i = 0; i < 4; i++) {
        int idx = t + i * 256;
        int r = idx >> 4, c4 = (idx & 15) << 2;
        cp16(dst + r * 64 + c4, src + r * 64 + c4);
    }
}

template<int KTOT>
__device__ __forceinline__ void gemm_h(const float* __restrict__ A,
                                       const float* __restrict__ Wg,
                                       const uint64_t (&ini)[4][4],
                                       float* __restrict__ Hs,
                                       float* __restrict__ sW, int t)
{
    const int tx = t & 15, ty = t >> 4;
    uint64_t acc[4][4];
#pragma unroll
    for (int i = 0; i < 4; i++)
#pragma unroll
        for (int p = 0; p < 4; p++) acc[i][p] = ini[i][p];
    constexpr int NT = KTOT / 32;
    stage_w1(Wg, 0, sW, t);
    cp_commit();
#pragma unroll
    for (int kt = 0; kt < NT; kt++) {
        if (kt + 1 < NT) {
            stage_w1(Wg, kt + 1, sW + ((kt + 1) & 1) * 4096, t);
            cp_commit();
            cp_wait<1>();
        } else cp_wait<0>();
        __syncthreads();
        const float* W = sW + (kt & 1) * 4096;
#pragma unroll
        for (int kk = 0; kk < 32; kk++) {
            int k = kt * 32 + kk;
            float4 a = *(const float4*)(A + k * 64 + ((ty ^ ((k >> 2) & 15)) << 2));
            ulonglong2 w01 = *(const ulonglong2*)(W + kk * 128 + tx * 8);
            ulonglong2 w23 = *(const ulonglong2*)(W + kk * 128 + tx * 8 + 4);
            uint64_t a0 = rep2(a.x), a1 = rep2(a.y), a2 = rep2(a.z), a3 = rep2(a.w);
            fma2(acc[0][0], a0, w01.x); fma2(acc[0][1], a0, w01.y);
            fma2(acc[0][2], a0, w23.x); fma2(acc[0][3], a0, w23.y);
            fma2(acc[1][0], a1, w01.x); fma2(acc[1][1], a1, w01.y);
            fma2(acc[1][2], a1, w23.x); fma2(acc[1][3], a1, w23.y);
            fma2(acc[2][0], a2, w01.x); fma2(acc[2][1], a2, w01.y);
            fma2(acc[2][2], a2, w23.x); fma2(acc[2][3], a2, w23.y);
            fma2(acc[3][0], a3, w01.x); fma2(acc[3][1], a3, w01.y);
            fma2(acc[3][2], a3, w23.x); fma2(acc[3][3], a3, w23.y);
        }
        __syncthreads();
    }
#pragma unroll
    for (int i = 0; i < 4; i++)
#pragma unroll
        for (int p = 0; p < 4; p++) {
            float2 v = unpack2(acc[i][p]);
            int h0 = tx * 8 + p * 2;
            int c = ((ty ^ ((h0 >> 2) & 15)) << 2) | i;
            Hs[h0 * 64 + c]       = fmaxf(v.x, 0.f);
            Hs[(h0 + 1) * 64 + c] = fmaxf(v.y, 0.f);
        }
    __syncthreads();
}

__device__ __forceinline__ void gemm_o(const float* __restrict__ Hs,
                                       const float* __restrict__ Wg,
                                       const float* __restrict__ b2,
                                       float* __restrict__ sW, int t,
                                       float o[4][4])
{
    const int tx = t & 15, ty = t >> 4;
    uint64_t b0 = *(const uint64_t*)(b2 + tx * 4);
    uint64_t b1 = *(const uint64_t*)(b2 + tx * 4 + 2);
    uint64_t acc[4][2];
#pragma unroll
    for (int i = 0; i < 4; i++) { acc[i][0] = b0; acc[i][1] = b1; }
    stage_w2(Wg, 0, sW, t);
    cp_commit();
#pragma unroll
    for (int kt = 0; kt < 2; kt++) {
        if (kt == 0) { stage_w2(Wg, 1, sW + 4096, t); cp_commit(); cp_wait<1>(); }
        else cp_wait<0>();
        __syncthreads();
        const float* W = sW + kt * 4096;
#pragma unroll 8
        for (int kk = 0; kk < 64; kk++) {
            int k = kt * 64 + kk;
            float4 a = *(const float4*)(Hs + k * 64 + ((ty ^ ((k >> 2) & 15)) << 2));
            ulonglong2 w = *(const ulonglong2*)(W + kk * 64 + tx * 4);
            uint64_t a0 = rep2(a.x), a1 = rep2(a.y), a2 = rep2(a.z), a3 = rep2(a.w);
            fma2(acc[0][0], a0, w.x); fma2(acc[0][1], a0, w.y);
            fma2(acc[1][0], a1, w.x); fma2(acc[1][1], a1, w.y);
            fma2(acc[2][0], a2, w.x); fma2(acc[2][1], a2, w.y);
            fma2(acc[3][0], a3, w.x); fma2(acc[3][1], a3, w.y);
        }
        __syncthreads();
    }
#pragma unroll
    for (int i = 0; i < 4; i++)
#pragma unroll
        for (int p = 0; p < 2; p++) {
            float2 v = unpack2(acc[i][p]);
            o[i][p * 2]     = v.x;
            o[i][p * 2 + 1] = v.y;
        }
}

// ---------------------------------------------------------------------------
#define SMN_A  0
#define SMN_W  4096
#define SMN_H  12288
#define SMN_IX 20480
#define SMN_FLOATS (20480 + 64)

__global__ void __launch_bounds__(256, 2)
node_kernel(const int* __restrict__ batch,
            const float* __restrict__ Wn1, const float* __restrict__ Wn2,
            const float* __restrict__ bn2,
            float* __restrict__ x_out)
{
    extern __shared__ float smem[];
    float* A  = smem + SMN_A;
    float* sW = smem + SMN_W;
    float* Hs = smem + SMN_H;
    int* gid  = (int*)(smem + SMN_IX);
    const int t = threadIdx.x;
    const int nb = blockIdx.x * 64;

    if (t < 64) {
        int r = nb + t; if (r >= Nn) r = Nn - 1;
        gid[t] = batch[r];
    }
    __syncthreads();

    for (int i = t; i < 1024; i += 256) {
        int m = i >> 4, k4 = (i & 15) << 2;
        int r = nb + m; if (r >= Nn) r = Nn - 1;
        int c = ((((m >> 2) ^ (k4 >> 2)) & 15) << 2) | (m & 3);
        float4 v = *(const float4*)&g_agg[(size_t)r * 64 + k4];
        A[k4 * 64 + c] = v.x; A[(k4 + 1) * 64 + c] = v.y;
        A[(k4 + 2) * 64 + c] = v.z; A[(k4 + 3) * 64 + c] = v.w;
    }

    const int tx = t & 15, ty = t >> 4;
    uint64_t ini[4][4];
#pragma unroll
    for (int i = 0; i < 4; i++) {
        int row = ty * 4 + i;
        int r = nb + row; if (r >= Nn) r = Nn - 1;
        const float* up = g_U1n + gid[row] * 128 + tx * 8;
        const float* xn = g_Xn + (size_t)r * 128 + tx * 8;
#pragma unroll
        for (int p = 0; p < 4; p++)
            ini[i][p] = add2(*(const uint64_t*)(up + p * 2),
                             *(const uint64_t*)(xn + p * 2));
    }
    __syncthreads();

    gemm_h<64>(A, Wn1 + 64 * 128, ini, Hs, sW, t);
    float xo[4][4];
    gemm_o(Hs, Wn2, bn2, sW, t, xo);
    __syncthreads();

    float* nagg = Hs;
#pragma unroll
    for (int i = 0; i < 4; i++) nagg[t + i * 256] = 0.f;
    __syncthreads();

#pragma unroll
    for (int i = 0; i < 4; i++) {
        int row = ty * 4 + i;
        int r = nb + row;
        if (r < Nn) {
            *(float4*)&x_out[(size_t)r * 64 + tx * 4] =
                make_float4(xo[i][0], xo[i][1], xo[i][2], xo[i][3]);
            int g = gid[row];
#pragma unroll
            for (int j = 0; j < 4; j++)
                atomicAdd(&nagg[g * 64 + tx * 4 + j], xo[i][j]);
        }
    }
    __syncthreads();
    {
        int g = t >> 4, c4 = (t & 15) << 2;
        const float* p = &nagg[g * 64 + c4];
        red4(&g_nagg[g * 64 + c4], p[0], p[1], p[2], p[3]);
    }
}

// ---------------------------------------------------------------------------
#define SPT_FLOATS 12288

__global__ void __launch_bounds__(256, 2)
prep_tables(const float* __restrict__ x,
            const float* __restrict__ We1, const float* __restrict__ Wa1,
            const float* __restrict__ Wn1)
{
    extern __shared__ float smem[];
    float* A  = smem;
    float* sW = smem + 4096;
    const int t = threadIdx.x;
    const int nb = blockIdx.x * 64;
    const int tx = t & 15, ty = t >> 4;

    for (int i = t; i < 1024; i += 256) {
        int m = i >> 4, k4 = (i & 15) << 2;
        int r = nb + m; if (r >= Nn) r = Nn - 1;
        int c = ((((m >> 2) ^ (k4 >> 2)) & 15) << 2) | (m & 3);
        float4 v = *(const float4*)&x[(size_t)r * 64 + k4];
        A[k4 * 64 + c] = v.x; A[(k4 + 1) * 64 + c] = v.y;
        A[(k4 + 2) * 64 + c] = v.z; A[(k4 + 3) * 64 + c] = v.w;
    }
    __syncthreads();

    const float* Ws[5] = { We1, Wa1, We1 + 64 * 128, Wa1 + 64 * 128, Wn1 };
    float* outs[5] = { g_Xs, g_Xs + 128, g_Xd, g_Xd + 128, g_Xn };
    const int stride[5] = { 256, 256, 256, 256, 128 };

#pragma unroll 1
    for (int seg = 0; seg < 5; seg++) {
        const float* W = Ws[seg];
        stage_w1(W, 0, sW, t);
        stage_w1(W, 1, sW + 4096, t);
        cp_commit();
        cp_wait<0>();
        __syncthreads();
        uint64_t acc[4][4];
#pragma unroll
        for (int i = 0; i < 4; i++)
#pragma unroll
            for (int p = 0; p < 4; p++) acc[i][p] = 0ull;
#pragma unroll
        for (int kt = 0; kt < 2; kt++) {
            const float* Wp = sW + kt * 4096;
#pragma unroll
            for (int kk = 0; kk < 32; kk++) {
                int k = kt * 32 + kk;
                float4 a = *(const float4*)(A + k * 64 + ((ty ^ ((k >> 2) & 15)) << 2));
                ulonglong2 w01 = *(const ulonglong2*)(Wp + kk * 128 + tx * 8);
                ulonglong2 w23 = *(const ulonglong2*)(Wp + kk * 128 + tx * 8 + 4);
                uint64_t a0 = rep2(a.x), a1 = rep2(a.y), a2 = rep2(a.z), a3 = rep2(a.w);
                fma2(acc[0][0], a0, w01.x); fma2(acc[0][1], a0, w01.y);
                fma2(acc[0][2], a0, w23.x); fma2(acc[0][3], a0, w23.y);
                fma2(acc[1][0], a1, w01.x); fma2(acc[1][1], a1, w01.y);
                fma2(acc[1][2], a1, w23.x); fma2(acc[1][3], a1, w23.y);
                fma2(acc[2][0], a2, w01.x); fma2(acc[2][1], a2, w01.y);
                fma2(acc[2][2], a2, w23.x); fma2(acc[2][3], a2, w23.y);
                fma2(acc[3][0], a3, w01.x); fma2(acc[3][1], a3, w01.y);
                fma2(acc[3][2], a3, w23.x); fma2(acc[3][3], a3, w23.y);
            }
        }
#pragma unroll
        for (int i = 0; i < 4; i++) {
            int r = nb + ty * 4 + i;
            if (r < Nn) {
                float* op = outs[seg] + (size_t)r * stride[seg] + tx * 8;
                float2 v0 = unpack2(acc[i][0]), v1 = unpack2(acc[i][1]);
                float2 v2 = unpack2(acc[i][2]), v3 = unpack2(acc[i][3]);
                *(float4*)op       = make_float4(v0.x, v0.y, v1.x, v1.y);
                *(float4*)(op + 4) = make_float4(v2.x, v2.y, v3.x, v3.y);
            }
        }
        __syncthreads();
    }
}

// ---------------------------------------------------------------------------
__global__ void __launch_bounds__(128)
global_kernel(const float* __restrict__ u,
              const float* __restrict__ Wg1, const float* __restrict__ bg1,
              const float* __restrict__ Wg2, const float* __restrict__ bg2,
              float* __restrict__ u_out)
{
    __shared__ float in[192];
    __shared__ float hid[128];
    const int g = blockIdx.x, t = threadIdx.x;
    if (t < 64) {
        in[t]       = u[g * 64 + t];
        in[64 + t]  = g_nagg[g * 64 + t];
        in[128 + t] = g_eagg[g * 64 + t];
    }
    __syncthreads();
    float acc = bg1[t];
#pragma unroll 8
    for (int k = 0; k < 192; k++) acc += in[k] * Wg1[(size_t)k * 128 + t];
    hid[t] = fmaxf(acc, 0.f);
    __syncthreads();
    if (t < 64) {
        float a2 = bg2[t];
#pragma unroll 8
        for (int k = 0; k < 128; k++) a2 += hid[k] * Wg2[(size_t)k * 64 + t];
        u_out[g * 64 + t] = a2;
    }
}

// ---------------------------------------------------------------------------
// Prep: zero aggregates, U1 tables, fragment-packed tf32 weight tiles
// ---------------------------------------------------------------------------
__global__ void __launch_bounds__(256)
prep_kernel(const float* __restrict__ u,
            const float* __restrict__ We1, const float* __restrict__ be1,
            const float* __restrict__ Wa1, const float* __restrict__ ba1,
            const float* __restrict__ Wn1, const float* __restrict__ bn1,
            const float* __restrict__ We2, const float* __restrict__ Wa2)
{
    const int b = blockIdx.x, t = threadIdx.x;
    size_t idx = (size_t)b * 256 + t;
    const size_t n4 = (size_t)Nn * Dd / 4;
    float4 z = make_float4(0.f, 0.f, 0.f, 0.f);
    for (size_t i = idx; i < n4; i += (size_t)gridDim.x * 256) ((float4*)g_agg)[i] = z;
    if (idx < 256) { ((float4*)g_nagg)[idx] = z; ((float4*)g_eagg)[idx] = z; }
    if (b < 3) {
        const float* W    = (b == 0) ? We1 + 192 * 128 : (b == 1) ? Wa1 + 192 * 128 : Wn1 + 128 * 128;
        const float* bias = (b == 0) ? be1 : (b == 1) ? ba1 : bn1;
        float* out        = (b == 0) ? g_U1e : (b == 1) ? g_U1a : g_U1n;
        for (int i = t; i < Gg * Hh; i += 256) {
            int g = i >> 7, h = i & 127;
            float acc = bias[h];
#pragma unroll 8
            for (int k = 0; k < 64; k++) acc += u[g * 64 + k] * W[(size_t)k * 128 + h];
            out[i] = acc;
        }
    } else if (b < 5) {
        // B1 pack: W1[128+k][n]  (k<64, n<128)
        const float* src = (b == 3) ? We1 : Wa1;
        float* dst = (b == 3) ? g_B1e : g_B1a;
        for (int i = t; i < 8192; i += 256) {
            int n = i >> 6, k = i & 63;
            float v = src[(size_t)(128 + k) * 128 + n];
            int pos = (((n >> 3) * 8 + (k >> 3)) << 6)
                    + 2 * ((n & 7) * 4 + (k & 3)) + ((k >> 2) & 1);
            dst[pos] = tf32r(v);
        }
    } else if (b < 7) {
        // B2 pack: W2[k][n]  (k<128, n<64)
        const float* src = (b == 5) ? We2 : Wa2;
        float* dst = (b == 5) ? g_B2e : g_B2a;
        for (int i = t; i < 8192; i += 256) {
            int k = i >> 6, n = i & 63;
            float v = src[(size_t)k * 64 + n];
            int pos = (((n >> 3) * 16 + (k >> 3)) << 6)
                    + 2 * ((n & 7) * 4 + (k & 3)) + ((k >> 2) & 1);
            dst[pos] = tf32r(v);
        }
    }
}

extern "C" void kernel_launch(void* const* d_in, const int* in_sizes, int n_in,
                              void* d_out, int out_size)
{
    const float* x     = (const float*)d_in[0];
    const int*   ei    = (const int*)d_in[1];
    const float* e     = (const float*)d_in[2];
    const float* u     = (const float*)d_in[3];
    const int*   batch = (const int*)d_in[4];
    const float* We1 = (const float*)d_in[5];
    const float* be1 = (const float*)d_in[6];
    const float* We2 = (const float*)d_in[7];
    const float* be2 = (const float*)d_in[8];
    const float* Wa1 = (const float*)d_in[9];
    const float* ba1 = (const float*)d_in[10];
    const float* Wa2 = (const float*)d_in[11];
    const float* ba2 = (const float*)d_in[12];
    const float* Wn1 = (const float*)d_in[13];
    const float* bn1 = (const float*)d_in[14];
    const float* Wn2 = (const float*)d_in[15];
    const float* bn2 = (const float*)d_in[16];
    const float* Wg1 = (const float*)d_in[17];
    const float* bg1 = (const float*)d_in[18];
    const float* Wg2 = (const float*)d_in[19];
    const float* bg2 = (const float*)d_in[20];

    float* out   = (float*)d_out;
    float* x_out = out;
    float* e_out = out + (size_t)Nn * Dd;
    float* u_out = out + (size_t)Nn * Dd + (size_t)Ee * Dd;

    cudaFuncSetAttribute(edge_kernel, cudaFuncAttributeMaxDynamicSharedMemorySize,
                         E_FLOATS * 4);
    cudaFuncSetAttribute(node_kernel, cudaFuncAttributeMaxDynamicSharedMemorySize,
                         SMN_FLOATS * 4);
    cudaFuncSetAttribute(prep_tables, cudaFuncAttributeMaxDynamicSharedMemorySize,
                         SPT_FLOATS * 4);

    prep_kernel<<<3125, 256>>>(u, We1, be1, Wa1, ba1, Wn1, bn1, We2, Wa2);
    prep_tables<<<(Nn + 63) / 64, 256, SPT_FLOATS * 4>>>(x, We1, Wa1, Wn1);
    edge_kernel<<<Ee / 64, 256, E_FLOATS * 4>>>(ei, e, batch, be2, ba2, e_out);
    node_kernel<<<(Nn + 63) / 64, 256, SMN_FLOATS * 4>>>(batch, Wn1, Wn2, bn2, x_out);
    global_kernel<<<Gg, 128>>>(u, Wg1, bg1, Wg2, bg2, u_out);
}

// round 16
// speedup vs baseline: 2.6308x; 1.3643x over previous
#include <cuda_runtime.h>
#include <cuda_fp16.h>
#include <stdint.h>
#include <math.h>

#define Nn 50000
#define Ee 800000
#define Gg 16
#define Dd 64
#define Hh 128

__device__ float g_agg[Nn * Dd];
__device__ float g_nagg[Gg * Dd];
__device__ float g_eagg[Gg * Dd];
__device__ float g_U1e[Gg * Hh];
__device__ float g_U1a[Gg * Hh];
__device__ float g_U1n[Gg * Hh];
__device__ float g_Xs[(size_t)Nn * 256];
__device__ float g_Xd[(size_t)Nn * 256];
__device__ float g_Xn[(size_t)Nn * 128];
// fp16 weight packs in mma.sync m16n8k16 fragment order (see prep_kernel)
__device__ __half g_B1e[8192];   // We1[128:192,:]  K=64, N=128
__device__ __half g_B1a[8192];
__device__ __half g_B2e[8192];   // We2             K=128, N=64
__device__ __half g_B2a[8192];

// ---------------------------------------------------------------------------
__device__ __forceinline__ void fma2(uint64_t& d, uint64_t a, uint64_t b) {
    asm("fma.rn.f32x2 %0, %1, %2, %0;" : "+l"(d) : "l"(a), "l"(b));
}
__device__ __forceinline__ uint64_t add2(uint64_t a, uint64_t b) {
    uint64_t r; asm("add.rn.f32x2 %0, %1, %2;" : "=l"(r) : "l"(a), "l"(b)); return r;
}
__device__ __forceinline__ uint64_t rep2(float x) {
    uint64_t r; asm("mov.b64 %0, {%1, %1};" : "=l"(r) : "f"(x)); return r;
}
__device__ __forceinline__ float2 unpack2(uint64_t v) {
    float2 r; asm("mov.b64 {%0, %1}, %2;" : "=f"(r.x), "=f"(r.y) : "l"(v)); return r;
}
__device__ __forceinline__ void red4(float* p, float a, float b, float c, float d) {
    asm volatile("red.global.add.v4.f32 [%0], {%1,%2,%3,%4};"
                 :: "l"(p), "f"(a), "f"(b), "f"(c), "f"(d) : "memory");
}
__device__ __forceinline__ void red2(float* p, float a, float b) {
    asm volatile("red.global.add.v2.f32 [%0], {%1,%2};"
                 :: "l"(p), "f"(a), "f"(b) : "memory");
}
__device__ __forceinline__ void cp16(float* smem_dst, const float* gsrc) {
    uint32_t s = (uint32_t)__cvta_generic_to_shared(smem_dst);
    asm volatile("cp.async.cg.shared.global [%0], [%1], 16;" :: "r"(s), "l"(gsrc));
}
__device__ __forceinline__ void cp_commit() { asm volatile("cp.async.commit_group;"); }
template<int N> __device__ __forceinline__ void cp_wait() {
    asm volatile("cp.async.wait_group %0;" :: "n"(N));
}
__device__ __forceinline__ void pfL2(const float* p) {
    asm volatile("prefetch.global.L2 [%0];" :: "l"(p));
}
__device__ __forceinline__ uint32_t pack_h2(float a, float b) {
    __half2 h = __floats2half2_rn(a, b);
    return *(uint32_t*)&h;
}

// mma.sync m16n8k16 fp16 in, f32 out
__device__ __forceinline__ void mma16(float c[4], uint32_t a0, uint32_t a1,
                                      uint32_t a2, uint32_t a3,
                                      uint32_t b0, uint32_t b1) {
    asm volatile("mma.sync.aligned.m16n8k16.row.col.f32.f16.f16.f32 "
                 "{%0,%1,%2,%3}, {%4,%5,%6,%7}, {%8,%9}, {%0,%1,%2,%3};"
                 : "+f"(c[0]), "+f"(c[1]), "+f"(c[2]), "+f"(c[3])
                 : "r"(a0), "r"(a1), "r"(a2), "r"(a3), "r"(b0), "r"(b1));
}

// ===========================================================================
// Edge kernel (mma.sync fp16): 64 edges/CTA, 256 threads, 2 CTAs/SM.
// AH: 64 rows x 68 uint32 words (fp16x2). A = words 0..31 (K=64),
// H = words 0..63 (K=128), phase-overlaid. All 4 B packs smem-resident.
// ===========================================================================
#define EAH   0
#define EB1E  4352
#define EB1A  8448
#define EB2E  12544
#define EB2A  16640
#define EEAGG 20736
#define EIX   21760
#define E_FLOATS (21760 + 192)

// GEMM1: K=64 (4 k16-tiles), per-warp 8 n-tiles
__device__ __forceinline__ void gemm1h(const uint32_t* AH32, const uint32_t* Bp,
                                       int w, int lane, float c[8][4]) {
    int g = lane >> 2, q = lane & 3;
    int r0 = (w & 3) * 16 + g;
    int nb8 = (w >> 2) * 8;
#pragma unroll
    for (int kt = 0; kt < 4; kt++) {
        uint32_t a0 = AH32[r0 * 68 + kt * 8 + q];
        uint32_t a1 = AH32[(r0 + 8) * 68 + kt * 8 + q];
        uint32_t a2 = AH32[r0 * 68 + kt * 8 + q + 4];
        uint32_t a3 = AH32[(r0 + 8) * 68 + kt * 8 + q + 4];
#pragma unroll
        for (int nt = 0; nt < 8; nt++) {
            const uint32_t* bp = Bp + (((nb8 + nt) * 4 + kt) << 6) + 2 * lane;
            mma16(c[nt], a0, a1, a2, a3, bp[0], bp[1]);
        }
    }
}
// GEMM2: K=128 (8 k16-tiles), per-warp 4 n-tiles
__device__ __forceinline__ void gemm2h(const uint32_t* AH32, const uint32_t* Bp,
                                       int w, int lane, float c[4][4]) {
    int g = lane >> 2, q = lane & 3;
    int r0 = (w & 3) * 16 + g;
    int nb4 = (w >> 2) * 4;
#pragma unroll
    for (int kt = 0; kt < 8; kt++) {
        uint32_t a0 = AH32[r0 * 68 + kt * 8 + q];
        uint32_t a1 = AH32[(r0 + 8) * 68 + kt * 8 + q];
        uint32_t a2 = AH32[r0 * 68 + kt * 8 + q + 4];
        uint32_t a3 = AH32[(r0 + 8) * 68 + kt * 8 + q + 4];
#pragma unroll
        for (int nt = 0; nt < 4; nt++) {
            const uint32_t* bp = Bp + (((nb4 + nt) * 8 + kt) << 6) + 2 * lane;
            mma16(c[nt], a0, a1, a2, a3, bp[0], bp[1]);
        }
    }
}
// Epilogue: H = relu(C + Xs + Xd + U1) -> fp16x2 words in AH
__device__ __forceinline__ void epi_h(uint32_t* AH32, const float c1[8][4],
                                      const float* xs0, const float* xd0, const float* u0,
                                      const float* xs1, const float* xd1, const float* u1,
                                      int r0, int r1, int nb, int q) {
    int wb = nb >> 1;
#pragma unroll
    for (int nt = 0; nt < 8; nt++) {
        int n = nb + nt * 8 + 2 * q;
        float2 sa = *(const float2*)(xs0 + n), da = *(const float2*)(xd0 + n);
        float2 ua = *(const float2*)(u0 + n);
        float2 sb = *(const float2*)(xs1 + n), db = *(const float2*)(xd1 + n);
        float2 ub = *(const float2*)(u1 + n);
        float h0 = fmaxf(c1[nt][0] + sa.x + da.x + ua.x, 0.f);
        float h1 = fmaxf(c1[nt][1] + sa.y + da.y + ua.y, 0.f);
        float h2 = fmaxf(c1[nt][2] + sb.x + db.x + ub.x, 0.f);
        float h3 = fmaxf(c1[nt][3] + sb.y + db.y + ub.y, 0.f);
        AH32[r0 * 68 + wb + nt * 4 + q] = pack_h2(h0, h1);
        AH32[r1 * 68 + wb + nt * 4 + q] = pack_h2(h2, h3);
    }
}

__global__ void __launch_bounds__(256, 2)
edge_kernel(const int* __restrict__ ei,
            const float* __restrict__ e, const int* __restrict__ batch,
            const float* __restrict__ be2, const float* __restrict__ ba2,
            float* __restrict__ e_out)
{
    extern __shared__ float S[];
    uint32_t* AH32 = (uint32_t*)(S + EAH);
    const uint32_t* B1e = (const uint32_t*)(S + EB1E);
    const uint32_t* B1a = (const uint32_t*)(S + EB1A);
    const uint32_t* B2e = (const uint32_t*)(S + EB2E);
    const uint32_t* B2a = (const uint32_t*)(S + EB2A);
    float* eagg = S + EEAGG;
    int* srcs = (int*)(S + EIX);
    int* dsts = srcs + 64;
    int* gidx = dsts + 64;
    const int t = threadIdx.x;
    const int w = t >> 5, lane = t & 31;
    const int q = lane & 3;
    const int r0 = (w & 3) * 16 + (lane >> 2), r1 = r0 + 8;
    const int eb = blockIdx.x * 64;

    if (t < 64) {
        int s_ = ei[eb + t], d_ = ei[Ee + eb + t];
        srcs[t] = s_; dsts[t] = d_; gidx[t] = batch[s_];
    }
#pragma unroll
    for (int i = 0; i < 4; i++) eagg[t + i * 256] = 0.f;

    // Stage ALL four B packs (16 KB each) once
#pragma unroll
    for (int i = 0; i < 4; i++) cp16(S + EB1E + (t + i * 256) * 4, (const float*)g_B1e + (t + i * 256) * 4);
#pragma unroll
    for (int i = 0; i < 4; i++) cp16(S + EB1A + (t + i * 256) * 4, (const float*)g_B1a + (t + i * 256) * 4);
#pragma unroll
    for (int i = 0; i < 4; i++) cp16(S + EB2E + (t + i * 256) * 4, (const float*)g_B2e + (t + i * 256) * 4);
#pragma unroll
    for (int i = 0; i < 4; i++) cp16(S + EB2A + (t + i * 256) * 4, (const float*)g_B2a + (t + i * 256) * 4);
    cp_commit();

    // Build A = e tile as fp16x2 words (words 0..31 per row)
    for (int i = t; i < 1024; i += 256) {
        int m = i >> 4, k4 = (i & 15) << 2;
        float4 v = *(const float4*)&e[(size_t)(eb + m) * 64 + k4];
        uint2 pw = make_uint2(pack_h2(v.x, v.y), pack_h2(v.z, v.w));
        *(uint2*)&AH32[m * 68 + (k4 >> 1)] = pw;
    }

    const int s0 = srcs[r0], d0 = dsts[r0], gg0 = gidx[r0];
    const int s1 = srcs[r1], d1 = dsts[r1], gg1 = gidx[r1];
    const float* xs0 = g_Xs + (size_t)s0 * 256;
    const float* xd0 = g_Xd + (size_t)d0 * 256;
    const float* xs1 = g_Xs + (size_t)s1 * 256;
    const float* xd1 = g_Xd + (size_t)d1 * 256;
    pfL2(xs0 + 2 * q * 16); pfL2(xd0 + 2 * q * 16);
    pfL2(xs1 + 2 * q * 16); pfL2(xd1 + 2 * q * 16);
    pfL2(xs0 + 128 + 2 * q * 16); pfL2(xd0 + 128 + 2 * q * 16);
    pfL2(xs1 + 128 + 2 * q * 16); pfL2(xd1 + 128 + 2 * q * 16);

    cp_wait<0>();
    __syncthreads();

    // ======== MLP_e ========
    float c1[8][4];
#pragma unroll
    for (int i = 0; i < 8; i++) { c1[i][0]=0.f; c1[i][1]=0.f; c1[i][2]=0.f; c1[i][3]=0.f; }
    gemm1h(AH32, B1e, w, lane, c1);
    __syncthreads();                       // A reads done before H overwrite
    epi_h(AH32, c1, xs0, xd0, g_U1e + gg0 * 128, xs1, xd1, g_U1e + gg1 * 128,
          r0, r1, (w >> 2) * 64, q);
    __syncthreads();                       // H visible

    float c2[4][4];
#pragma unroll
    for (int i = 0; i < 4; i++) { c2[i][0]=0.f; c2[i][1]=0.f; c2[i][2]=0.f; c2[i][3]=0.f; }
    gemm2h(AH32, B2e, w, lane, c2);
    __syncthreads();                       // H reads done before splice

    // Epilogue2: e_new = C2 + be2 (f32) ; e_out ; splice fp16 into A ; eagg
    float en[4][4];
    const int nb2 = (w >> 2) * 32;
#pragma unroll
    for (int nt = 0; nt < 4; nt++) {
        int n = nb2 + nt * 8 + 2 * q;
        float2 b = *(const float2*)(be2 + n);
        en[nt][0] = c2[nt][0] + b.x; en[nt][1] = c2[nt][1] + b.y;
        en[nt][2] = c2[nt][2] + b.x; en[nt][3] = c2[nt][3] + b.y;
        *(float2*)&e_out[(size_t)(eb + r0) * 64 + n] = make_float2(en[nt][0], en[nt][1]);
        *(float2*)&e_out[(size_t)(eb + r1) * 64 + n] = make_float2(en[nt][2], en[nt][3]);
        AH32[r0 * 68 + (n >> 1)] = pack_h2(en[nt][0], en[nt][1]);
        AH32[r1 * 68 + (n >> 1)] = pack_h2(en[nt][2], en[nt][3]);
        atomicAdd(&eagg[gg0 * 64 + n],     en[nt][0]);
        atomicAdd(&eagg[gg0 * 64 + n + 1], en[nt][1]);
        atomicAdd(&eagg[gg1 * 64 + n],     en[nt][2]);
        atomicAdd(&eagg[gg1 * 64 + n + 1], en[nt][3]);
    }
    __syncthreads();                       // splice + eagg complete
    {
        int g = t >> 4, c4 = (t & 15) << 2;
        const float* p = &eagg[g * 64 + c4];
        red4(&g_eagg[g * 64 + c4], p[0], p[1], p[2], p[3]);
    }

    // ======== MLP_a ========
#pragma unroll
    for (int i = 0; i < 8; i++) { c1[i][0]=0.f; c1[i][1]=0.f; c1[i][2]=0.f; c1[i][3]=0.f; }
    gemm1h(AH32, B1a, w, lane, c1);
    __syncthreads();
    epi_h(AH32, c1, xs0 + 128, xd0 + 128, g_U1a + gg0 * 128,
          xs1 + 128, xd1 + 128, g_U1a + gg1 * 128, r0, r1, (w >> 2) * 64, q);
    __syncthreads();

#pragma unroll
    for (int i = 0; i < 4; i++) { c2[i][0]=0.f; c2[i][1]=0.f; c2[i][2]=0.f; c2[i][3]=0.f; }
    gemm2h(AH32, B2a, w, lane, c2);

    // Epilogue4: scatter e_new * sigmoid(C2a + ba2)
#pragma unroll
    for (int nt = 0; nt < 4; nt++) {
        int n = nb2 + nt * 8 + 2 * q;
        float2 b = *(const float2*)(ba2 + n);
        float w00 = en[nt][0] / (1.f + __expf(-(c2[nt][0] + b.x)));
        float w01 = en[nt][1] / (1.f + __expf(-(c2[nt][1] + b.y)));
        float w10 = en[nt][2] / (1.f + __expf(-(c2[nt][2] + b.x)));
        float w11 = en[nt][3] / (1.f + __expf(-(c2[nt][3] + b.y)));
        red2(&g_agg[(size_t)d0 * 64 + n], w00, w01);
        red2(&g_agg[(size_t)d1 * 64 + n], w10, w11);
    }
}

// ===========================================================================
// FFMA2 helpers for node / prep kernels (R5-proven, unchanged)
// ===========================================================================
__device__ __forceinline__ void stage_w1(const float* __restrict__ Wg, int kt,
                                         float* __restrict__ dst, int t) {
    const float* src = Wg + (size_t)kt * 32 * 128;
#pragma unroll
    for (int i = 0; i < 4; i++) {
        int idx = t + i * 256;
        int r = idx >> 5, c4 = (idx & 31) << 2;
        cp16(dst + r * 128 + c4, src + r * 128 + c4);
    }
}
__device__ __forceinline__ void stage_w2(const float* __restrict__ Wg, int kt,
                                         float* __restrict__ dst, int t) {
    const float* src = Wg + (size_t)kt * 64 * 64;
#pragma unroll
    for (int i = 0; i < 4; i++) {
        int idx = t + i * 256;
        int r = idx >> 4, c4 = (idx & 15) << 2;
        cp16(dst + r * 64 + c4, src + r * 64 + c4);
    }
}

template<int KTOT>
__device__ __forceinline__ void gemm_h(const float* __restrict__ A,
                                       const float* __restrict__ Wg,
                                       const uint64_t (&ini)[4][4],
                                       float* __restrict__ Hs,
                                       float* __restrict__ sW, int t)
{
    const int tx = t & 15, ty = t >> 4;
    uint64_t acc[4][4];
#pragma unroll
    for (int i = 0; i < 4; i++)
#pragma unroll
        for (int p = 0; p < 4; p++) acc[i][p] = ini[i][p];
    constexpr int NT = KTOT / 32;
    stage_w1(Wg, 0, sW, t);
    cp_commit();
#pragma unroll
    for (int kt = 0; kt < NT; kt++) {
        if (kt + 1 < NT) {
            stage_w1(Wg, kt + 1, sW + ((kt + 1) & 1) * 4096, t);
            cp_commit();
            cp_wait<1>();
        } else cp_wait<0>();
        __syncthreads();
        const float* W = sW + (kt & 1) * 4096;
#pragma unroll
        for (int kk = 0; kk < 32; kk++) {
            int k = kt * 32 + kk;
            float4 a = *(const float4*)(A + k * 64 + ((ty ^ ((k >> 2) & 15)) << 2));
            ulonglong2 w01 = *(const ulonglong2*)(W + kk * 128 + tx * 8);
            ulonglong2 w23 = *(const ulonglong2*)(W + kk * 128 + tx * 8 + 4);
            uint64_t a0 = rep2(a.x), a1 = rep2(a.y), a2 = rep2(a.z), a3 = rep2(a.w);
            fma2(acc[0][0], a0, w01.x); fma2(acc[0][1], a0, w01.y);
            fma2(acc[0][2], a0, w23.x); fma2(acc[0][3], a0, w23.y);
            fma2(acc[1][0], a1, w01.x); fma2(acc[1][1], a1, w01.y);
            fma2(acc[1][2], a1, w23.x); fma2(acc[1][3], a1, w23.y);
            fma2(acc[2][0], a2, w01.x); fma2(acc[2][1], a2, w01.y);
            fma2(acc[2][2], a2, w23.x); fma2(acc[2][3], a2, w23.y);
            fma2(acc[3][0], a3, w01.x); fma2(acc[3][1], a3, w01.y);
            fma2(acc[3][2], a3, w23.x); fma2(acc[3][3], a3, w23.y);
        }
        __syncthreads();
    }
#pragma unroll
    for (int i = 0; i < 4; i++)
#pragma unroll
        for (int p = 0; p < 4; p++) {
            float2 v = unpack2(acc[i][p]);
            int h0 = tx * 8 + p * 2;
            int c = ((ty ^ ((h0 >> 2) & 15)) << 2) | i;
            Hs[h0 * 64 + c]       = fmaxf(v.x, 0.f);
            Hs[(h0 + 1) * 64 + c] = fmaxf(v.y, 0.f);
        }
    __syncthreads();
}

__device__ __forceinline__ void gemm_o(const float* __restrict__ Hs,
                                       const float* __restrict__ Wg,
                                       const float* __restrict__ b2,
                                       float* __restrict__ sW, int t,
                                       float o[4][4])
{
    const int tx = t & 15, ty = t >> 4;
    uint64_t b0 = *(const uint64_t*)(b2 + tx * 4);
    uint64_t b1 = *(const uint64_t*)(b2 + tx * 4 + 2);
    uint64_t acc[4][2];
#pragma unroll
    for (int i = 0; i < 4; i++) { acc[i][0] = b0; acc[i][1] = b1; }
    stage_w2(Wg, 0, sW, t);
    cp_commit();
#pragma unroll
    for (int kt = 0; kt < 2; kt++) {
        if (kt == 0) { stage_w2(Wg, 1, sW + 4096, t); cp_commit(); cp_wait<1>(); }
        else cp_wait<0>();
        __syncthreads();
        const float* W = sW + kt * 4096;
#pragma unroll 8
        for (int kk = 0; kk < 64; kk++) {
            int k = kt * 64 + kk;
            float4 a = *(const float4*)(Hs + k * 64 + ((ty ^ ((k >> 2) & 15)) << 2));
            ulonglong2 w = *(const ulonglong2*)(W + kk * 64 + tx * 4);
            uint64_t a0 = rep2(a.x), a1 = rep2(a.y), a2 = rep2(a.z), a3 = rep2(a.w);
            fma2(acc[0][0], a0, w.x); fma2(acc[0][1], a0, w.y);
            fma2(acc[1][0], a1, w.x); fma2(acc[1][1], a1, w.y);
            fma2(acc[2][0], a2, w.x); fma2(acc[2][1], a2, w.y);
            fma2(acc[3][0], a3, w.x); fma2(acc[3][1], a3, w.y);
        }
        __syncthreads();
    }
#pragma unroll
    for (int i = 0; i < 4; i++)
#pragma unroll
        for (int p = 0; p < 2; p++) {
            float2 v = unpack2(acc[i][p]);
            o[i][p * 2]     = v.x;
            o[i][p * 2 + 1] = v.y;
        }
}

// ---------------------------------------------------------------------------
#define SMN_A  0
#define SMN_W  4096
#define SMN_H  12288
#define SMN_IX 20480
#define SMN_FLOATS (20480 + 64)

__global__ void __launch_bounds__(256, 2)
node_kernel(const int* __restrict__ batch,
            const float* __restrict__ Wn1, const float* __restrict__ Wn2,
            const float* __restrict__ bn2,
            float* __restrict__ x_out)
{
    extern __shared__ float smem[];
    float* A  = smem + SMN_A;
    float* sW = smem + SMN_W;
    float* Hs = smem + SMN_H;
    int* gid  = (int*)(smem + SMN_IX);
    const int t = threadIdx.x;
    const int nb = blockIdx.x * 64;

    if (t < 64) {
        int r = nb + t; if (r >= Nn) r = Nn - 1;
        gid[t] = batch[r];
    }
    __syncthreads();

    for (int i = t; i < 1024; i += 256) {
        int m = i >> 4, k4 = (i & 15) << 2;
        int r = nb + m; if (r >= Nn) r = Nn - 1;
        int c = ((((m >> 2) ^ (k4 >> 2)) & 15) << 2) | (m & 3);
        float4 v = *(const float4*)&g_agg[(size_t)r * 64 + k4];
        A[k4 * 64 + c] = v.x; A[(k4 + 1) * 64 + c] = v.y;
        A[(k4 + 2) * 64 + c] = v.z; A[(k4 + 3) * 64 + c] = v.w;
    }

    const int tx = t & 15, ty = t >> 4;
    uint64_t ini[4][4];
#pragma unroll
    for (int i = 0; i < 4; i++) {
        int row = ty * 4 + i;
        int r = nb + row; if (r >= Nn) r = Nn - 1;
        const float* up = g_U1n + gid[row] * 128 + tx * 8;
        const float* xn = g_Xn + (size_t)r * 128 + tx * 8;
#pragma unroll
        for (int p = 0; p < 4; p++)
            ini[i][p] = add2(*(const uint64_t*)(up + p * 2),
                             *(const uint64_t*)(xn + p * 2));
    }
    __syncthreads();

    gemm_h<64>(A, Wn1 + 64 * 128, ini, Hs, sW, t);
    float xo[4][4];
    gemm_o(Hs, Wn2, bn2, sW, t, xo);
    __syncthreads();

    float* nagg = Hs;
#pragma unroll
    for (int i = 0; i < 4; i++) nagg[t + i * 256] = 0.f;
    __syncthreads();

#pragma unroll
    for (int i = 0; i < 4; i++) {
        int row = ty * 4 + i;
        int r = nb + row;
        if (r < Nn) {
            *(float4*)&x_out[(size_t)r * 64 + tx * 4] =
                make_float4(xo[i][0], xo[i][1], xo[i][2], xo[i][3]);
            int g = gid[row];
#pragma unroll
            for (int j = 0; j < 4; j++)
                atomicAdd(&nagg[g * 64 + tx * 4 + j], xo[i][j]);
        }
    }
    __syncthreads();
    {
        int g = t >> 4, c4 = (t & 15) << 2;
        const float* p = &nagg[g * 64 + c4];
        red4(&g_nagg[g * 64 + c4], p[0], p[1], p[2], p[3]);
    }
}

// ---------------------------------------------------------------------------
#define SPT_FLOATS 12288

__global__ void __launch_bounds__(256, 2)
prep_tables(const float* __restrict__ x,
            const float* __restrict__ We1, const float* __restrict__ Wa1,
            const float* __restrict__ Wn1)
{
    extern __shared__ float smem[];
    float* A  = smem;
    float* sW = smem + 4096;
    const int t = threadIdx.x;
    const int nb = blockIdx.x * 64;
    const int tx = t & 15, ty = t >> 4;

    for (int i = t; i < 1024; i += 256) {
        int m = i >> 4, k4 = (i & 15) << 2;
        int r = nb + m; if (r >= Nn) r = Nn - 1;
        int c = ((((m >> 2) ^ (k4 >> 2)) & 15) << 2) | (m & 3);
        float4 v = *(const float4*)&x[(size_t)r * 64 + k4];
        A[k4 * 64 + c] = v.x; A[(k4 + 1) * 64 + c] = v.y;
        A[(k4 + 2) * 64 + c] = v.z; A[(k4 + 3) * 64 + c] = v.w;
    }
    __syncthreads();

    const float* Ws[5] = { We1, Wa1, We1 + 64 * 128, Wa1 + 64 * 128, Wn1 };
    float* outs[5] = { g_Xs, g_Xs + 128, g_Xd, g_Xd + 128, g_Xn };
    const int stride[5] = { 256, 256, 256, 256, 128 };

#pragma unroll 1
    for (int seg = 0; seg < 5; seg++) {
        const float* W = Ws[seg];
        stage_w1(W, 0, sW, t);
        stage_w1(W, 1, sW + 4096, t);
        cp_commit();
        cp_wait<0>();
        __syncthreads();
        uint64_t acc[4][4];
#pragma unroll
        for (int i = 0; i < 4; i++)
#pragma unroll
            for (int p = 0; p < 4; p++) acc[i][p] = 0ull;
#pragma unroll
        for (int kt = 0; kt < 2; kt++) {
            const float* Wp = sW + kt * 4096;
#pragma unroll
            for (int kk = 0; kk < 32; kk++) {
                int k = kt * 32 + kk;
                float4 a = *(const float4*)(A + k * 64 + ((ty ^ ((k >> 2) & 15)) << 2));
                ulonglong2 w01 = *(const ulonglong2*)(Wp + kk * 128 + tx * 8);
                ulonglong2 w23 = *(const ulonglong2*)(Wp + kk * 128 + tx * 8 + 4);
                uint64_t a0 = rep2(a.x), a1 = rep2(a.y), a2 = rep2(a.z), a3 = rep2(a.w);
                fma2(acc[0][0], a0, w01.x); fma2(acc[0][1], a0, w01.y);
                fma2(acc[0][2], a0, w23.x); fma2(acc[0][3], a0, w23.y);
                fma2(acc[1][0], a1, w01.x); fma2(acc[1][1], a1, w01.y);
                fma2(acc[1][2], a1, w23.x); fma2(acc[1][3], a1, w23.y);
                fma2(acc[2][0], a2, w01.x); fma2(acc[2][1], a2, w01.y);
                fma2(acc[2][2], a2, w23.x); fma2(acc[2][3], a2, w23.y);
                fma2(acc[3][0], a3, w01.x); fma2(acc[3][1], a3, w01.y);
                fma2(acc[3][2], a3, w23.x); fma2(acc[3][3], a3, w23.y);
            }
        }
#pragma unroll
        for (int i = 0; i < 4; i++) {
            int r = nb + ty * 4 + i;
            if (r < Nn) {
                float* op = outs[seg] + (size_t)r * stride[seg] + tx * 8;
                float2 v0 = unpack2(acc[i][0]), v1 = unpack2(acc[i][1]);
                float2 v2 = unpack2(acc[i][2]), v3 = unpack2(acc[i][3]);
                *(float4*)op       = make_float4(v0.x, v0.y, v1.x, v1.y);
                *(float4*)(op + 4) = make_float4(v2.x, v2.y, v3.x, v3.y);
            }
        }
        __syncthreads();
    }
}

// ---------------------------------------------------------------------------
__global__ void __launch_bounds__(128)
global_kernel(const float* __restrict__ u,
              const float* __restrict__ Wg1, const float* __restrict__ bg1,
              const float* __restrict__ Wg2, const float* __restrict__ bg2,
              float* __restrict__ u_out)
{
    __shared__ float in[192];
    __shared__ float hid[128];
    const int g = blockIdx.x, t = threadIdx.x;
    if (t < 64) {
        in[t]       = u[g * 64 + t];
        in[64 + t]  = g_nagg[g * 64 + t];
        in[128 + t] = g_eagg[g * 64 + t];
    }
    __syncthreads();
    float acc = bg1[t];
#pragma unroll 8
    for (int k = 0; k < 192; k++) acc += in[k] * Wg1[(size_t)k * 128 + t];
    hid[t] = fmaxf(acc, 0.f);
    __syncthreads();
    if (t < 64) {
        float a2 = bg2[t];
#pragma unroll 8
        for (int k = 0; k < 128; k++) a2 += hid[k] * Wg2[(size_t)k * 64 + t];
        u_out[g * 64 + t] = a2;
    }
}

__global__ void dummy_kernel() {}

// ---------------------------------------------------------------------------
// Prep: zero aggregates, U1 tables, fp16 fragment-packed weight tiles
// ---------------------------------------------------------------------------
__global__ void __launch_bounds__(256)
prep_kernel(const float* __restrict__ u,
            const float* __restrict__ We1, const float* __restrict__ be1,
            const float* __restrict__ Wa1, const float* __restrict__ ba1,
            const float* __restrict__ Wn1, const float* __restrict__ bn1,
            const float* __restrict__ We2, const float* __restrict__ Wa2)
{
    const int b = blockIdx.x, t = threadIdx.x;
    size_t idx = (size_t)b * 256 + t;
    const size_t n4 = (size_t)Nn * Dd / 4;
    float4 z = make_float4(0.f, 0.f, 0.f, 0.f);
    for (size_t i = idx; i < n4; i += (size_t)gridDim.x * 256) ((float4*)g_agg)[i] = z;
    if (idx < 256) { ((float4*)g_nagg)[idx] = z; ((float4*)g_eagg)[idx] = z; }
    if (b < 3) {
        const float* W    = (b == 0) ? We1 + 192 * 128 : (b == 1) ? Wa1 + 192 * 128 : Wn1 + 128 * 128;
        const float* bias = (b == 0) ? be1 : (b == 1) ? ba1 : bn1;
        float* out        = (b == 0) ? g_U1e : (b == 1) ? g_U1a : g_U1n;
        for (int i = t; i < Gg * Hh; i += 256) {
            int g = i >> 7, h = i & 127;
            float acc = bias[h];
#pragma unroll 8
            for (int k = 0; k < 64; k++) acc += u[g * 64 + k] * W[(size_t)k * 128 + h];
            out[i] = acc;
        }
    } else if (b < 5) {
        // B1 pack (K=64, N=128): src row 128+k, col n of W1
        const float* src = (b == 3) ? We1 : Wa1;
        __half* dst = (b == 3) ? g_B1e : g_B1a;
        for (int i = t; i < 8192; i += 256) {
            int n = i >> 6, k = i & 63;
            float v = src[(size_t)(128 + k) * 128 + n];
            int kl = k & 15;
            int reg = kl >> 3, lq = (kl & 7) >> 1, hw = kl & 1;
            int lane = (n & 7) * 4 + lq;
            int pos = (((n >> 3) * 4 + (k >> 4)) << 6) + 2 * lane + reg;
            dst[2 * pos + hw] = __float2half_rn(v);
        }
    } else if (b < 7) {
        // B2 pack (K=128, N=64): src W2[k][n]
        const float* src = (b == 5) ? We2 : Wa2;
        __half* dst = (b == 5) ? g_B2e : g_B2a;
        for (int i = t; i < 8192; i += 256) {
            int k = i >> 6, n = i & 63;
            float v = src[(size_t)k * 64 + n];
            int kl = k & 15;
            int reg = kl >> 3, lq = (kl & 7) >> 1, hw = kl & 1;
            int lane = (n & 7) * 4 + lq;
            int pos = (((n >> 3) * 8 + (k >> 4)) << 6) + 2 * lane + reg;
            dst[2 * pos + hw] = __float2half_rn(v);
        }
    }
}

extern "C" void kernel_launch(void* const* d_in, const int* in_sizes, int n_in,
                              void* d_out, int out_size)
{
    const float* x     = (const float*)d_in[0];
    const int*   ei    = (const int*)d_in[1];
    const float* e     = (const float*)d_in[2];
    const float* u     = (const float*)d_in[3];
    const int*   batch = (const int*)d_in[4];
    const float* We1 = (const float*)d_in[5];
    const float* be1 = (const float*)d_in[6];
    const float* We2 = (const float*)d_in[7];
    const float* be2 = (const float*)d_in[8];
    const float* Wa1 = (const float*)d_in[9];
    const float* ba1 = (const float*)d_in[10];
    const float* Wa2 = (const float*)d_in[11];
    const float* ba2 = (const float*)d_in[12];
    const float* Wn1 = (const float*)d_in[13];
    const float* bn1 = (const float*)d_in[14];
    const float* Wn2 = (const float*)d_in[15];
    const float* bn2 = (const float*)d_in[16];
    const float* Wg1 = (const float*)d_in[17];
    const float* bg1 = (const float*)d_in[18];
    const float* Wg2 = (const float*)d_in[19];
    const float* bg2 = (const float*)d_in[20];

    float* out   = (float*)d_out;
    float* x_out = out;
    float* e_out = out + (size_t)Nn * Dd;
    float* u_out = out + (size_t)Nn * Dd + (size_t)Ee * Dd;

    cudaFuncSetAttribute(edge_kernel, cudaFuncAttributeMaxDynamicSharedMemorySize,
                         E_FLOATS * 4);
    cudaFuncSetAttribute(node_kernel, cudaFuncAttributeMaxDynamicSharedMemorySize,
                         SMN_FLOATS * 4);
    cudaFuncSetAttribute(prep_tables, cudaFuncAttributeMaxDynamicSharedMemorySize,
                         SPT_FLOATS * 4);

    prep_kernel<<<3125, 256>>>(u, We1, be1, Wa1, ba1, Wn1, bn1, We2, Wa2);
    prep_tables<<<(Nn + 63) / 64, 256, SPT_FLOATS * 4>>>(x, We1, Wa1, Wn1);
    dummy_kernel<<<1, 32>>>();
    edge_kernel<<<Ee / 64, 256, E_FLOATS * 4>>>(ei, e, batch, be2, ba2, e_out);
    node_kernel<<<(Nn + 63) / 64, 256, SMN_FLOATS * 4>>>(batch, Wn1, Wn2, bn2, x_out);
    global_kernel<<<Gg, 128>>>(u, Wg1, bg1, Wg2, bg2, u_out);
}

// round 17
// speedup vs baseline: 2.7789x; 1.0563x over previous
#include <cuda_runtime.h>
#include <cuda_fp16.h>
#include <stdint.h>
#include <math.h>

#define Nn 50000
#define Ee 800000
#define Gg 16
#define Dd 64
#define Hh 128

__device__ float g_agg[Nn * Dd];
__device__ float g_nagg[Gg * Dd];
__device__ float g_eagg[Gg * Dd];
__device__ float g_U1e[Gg * Hh];
__device__ float g_U1a[Gg * Hh];
__device__ float g_U1n[Gg * Hh];
__device__ __half g_Xs[(size_t)Nn * 256];   // fp16 tables (halved gather traffic)
__device__ __half g_Xd[(size_t)Nn * 256];
__device__ float  g_Xn[(size_t)Nn * 128];   // node path stays fp32
// fp16 weight packs in mma.sync m16n8k16 fragment order (see prep_kernel)
__device__ __half g_B1e[8192];   // We1[128:192,:]  K=64, N=128
__device__ __half g_B1a[8192];
__device__ __half g_B2e[8192];   // We2             K=128, N=64
__device__ __half g_B2a[8192];

// ---------------------------------------------------------------------------
__device__ __forceinline__ void fma2(uint64_t& d, uint64_t a, uint64_t b) {
    asm("fma.rn.f32x2 %0, %1, %2, %0;" : "+l"(d) : "l"(a), "l"(b));
}
__device__ __forceinline__ uint64_t add2(uint64_t a, uint64_t b) {
    uint64_t r; asm("add.rn.f32x2 %0, %1, %2;" : "=l"(r) : "l"(a), "l"(b)); return r;
}
__device__ __forceinline__ uint64_t rep2(float x) {
    uint64_t r; asm("mov.b64 %0, {%1, %1};" : "=l"(r) : "f"(x)); return r;
}
__device__ __forceinline__ float2 unpack2(uint64_t v) {
    float2 r; asm("mov.b64 {%0, %1}, %2;" : "=f"(r.x), "=f"(r.y) : "l"(v)); return r;
}
__device__ __forceinline__ void red4(float* p, float a, float b, float c, float d) {
    asm volatile("red.global.add.v4.f32 [%0], {%1,%2,%3,%4};"
                 :: "l"(p), "f"(a), "f"(b), "f"(c), "f"(d) : "memory");
}
__device__ __forceinline__ void red2(float* p, float a, float b) {
    asm volatile("red.global.add.v2.f32 [%0], {%1,%2};"
                 :: "l"(p), "f"(a), "f"(b) : "memory");
}
__device__ __forceinline__ void cp16(float* smem_dst, const float* gsrc) {
    uint32_t s = (uint32_t)__cvta_generic_to_shared(smem_dst);
    asm volatile("cp.async.cg.shared.global [%0], [%1], 16;" :: "r"(s), "l"(gsrc));
}
__device__ __forceinline__ void cp_commit() { asm volatile("cp.async.commit_group;"); }
template<int N> __device__ __forceinline__ void cp_wait() {
    asm volatile("cp.async.wait_group %0;" :: "n"(N));
}
__device__ __forceinline__ void pfL2(const void* p) {
    asm volatile("prefetch.global.L2 [%0];" :: "l"(p));
}
__device__ __forceinline__ uint32_t pack_h2(float a, float b) {
    __half2 h = __floats2half2_rn(a, b);
    return *(uint32_t*)&h;
}
__device__ __forceinline__ float2 ldh2(const __half* p) {
    return __half22float2(*(const __half2*)p);
}

// mma.sync m16n8k16 fp16 in, f32 out
__device__ __forceinline__ void mma16(float c[4], uint32_t a0, uint32_t a1,
                                      uint32_t a2, uint32_t a3,
                                      uint32_t b0, uint32_t b1) {
    asm volatile("mma.sync.aligned.m16n8k16.row.col.f32.f16.f16.f32 "
                 "{%0,%1,%2,%3}, {%4,%5,%6,%7}, {%8,%9}, {%0,%1,%2,%3};"
                 : "+f"(c[0]), "+f"(c[1]), "+f"(c[2]), "+f"(c[3])
                 : "r"(a0), "r"(a1), "r"(a2), "r"(a3), "r"(b0), "r"(b1));
}

// ===========================================================================
// Edge kernel (mma.sync fp16): 64 edges/CTA, 256 threads, 2 CTAs/SM.
// ===========================================================================
#define EAH   0
#define EB1E  4352
#define EB1A  8448
#define EB2E  12544
#define EB2A  16640
#define EEAGG 20736
#define EIX   21760
#define E_FLOATS (21760 + 192)

__device__ __forceinline__ void gemm1h(const uint32_t* AH32, const uint32_t* Bp,
                                       int w, int lane, float c[8][4]) {
    int g = lane >> 2, q = lane & 3;
    int r0 = (w & 3) * 16 + g;
    int nb8 = (w >> 2) * 8;
#pragma unroll
    for (int kt = 0; kt < 4; kt++) {
        uint32_t a0 = AH32[r0 * 68 + kt * 8 + q];
        uint32_t a1 = AH32[(r0 + 8) * 68 + kt * 8 + q];
        uint32_t a2 = AH32[r0 * 68 + kt * 8 + q + 4];
        uint32_t a3 = AH32[(r0 + 8) * 68 + kt * 8 + q + 4];
#pragma unroll
        for (int nt = 0; nt < 8; nt++) {
            const uint32_t* bp = Bp + (((nb8 + nt) * 4 + kt) << 6) + 2 * lane;
            mma16(c[nt], a0, a1, a2, a3, bp[0], bp[1]);
        }
    }
}
__device__ __forceinline__ void gemm2h(const uint32_t* AH32, const uint32_t* Bp,
                                       int w, int lane, float c[4][4]) {
    int g = lane >> 2, q = lane & 3;
    int r0 = (w & 3) * 16 + g;
    int nb4 = (w >> 2) * 4;
#pragma unroll
    for (int kt = 0; kt < 8; kt++) {
        uint32_t a0 = AH32[r0 * 68 + kt * 8 + q];
        uint32_t a1 = AH32[(r0 + 8) * 68 + kt * 8 + q];
        uint32_t a2 = AH32[r0 * 68 + kt * 8 + q + 4];
        uint32_t a3 = AH32[(r0 + 8) * 68 + kt * 8 + q + 4];
#pragma unroll
        for (int nt = 0; nt < 4; nt++) {
            const uint32_t* bp = Bp + (((nb4 + nt) * 8 + kt) << 6) + 2 * lane;
            mma16(c[nt], a0, a1, a2, a3, bp[0], bp[1]);
        }
    }
}
// Epilogue: H = relu(C + Xs + Xd + U1) -> fp16x2 words in AH (fp16 tables)
__device__ __forceinline__ void epi_h(uint32_t* AH32, const float c1[8][4],
                                      const __half* xs0, const __half* xd0, const float* u0,
                                      const __half* xs1, const __half* xd1, const float* u1,
                                      int r0, int r1, int nb, int q) {
    int wb = nb >> 1;
#pragma unroll
    for (int nt = 0; nt < 8; nt++) {
        int n = nb + nt * 8 + 2 * q;
        float2 sa = ldh2(xs0 + n), da = ldh2(xd0 + n);
        float2 ua = *(const float2*)(u0 + n);
        float2 sb = ldh2(xs1 + n), db = ldh2(xd1 + n);
        float2 ub = *(const float2*)(u1 + n);
        float h0 = fmaxf(c1[nt][0] + sa.x + da.x + ua.x, 0.f);
        float h1 = fmaxf(c1[nt][1] + sa.y + da.y + ua.y, 0.f);
        float h2 = fmaxf(c1[nt][2] + sb.x + db.x + ub.x, 0.f);
        float h3 = fmaxf(c1[nt][3] + sb.y + db.y + ub.y, 0.f);
        AH32[r0 * 68 + wb + nt * 4 + q] = pack_h2(h0, h1);
        AH32[r1 * 68 + wb + nt * 4 + q] = pack_h2(h2, h3);
    }
}

__global__ void __launch_bounds__(256, 2)
edge_kernel(const int* __restrict__ ei,
            const float* __restrict__ e, const int* __restrict__ batch,
            const float* __restrict__ be2, const float* __restrict__ ba2,
            float* __restrict__ e_out)
{
    extern __shared__ float S[];
    uint32_t* AH32 = (uint32_t*)(S + EAH);
    const uint32_t* B1e = (const uint32_t*)(S + EB1E);
    const uint32_t* B1a = (const uint32_t*)(S + EB1A);
    const uint32_t* B2e = (const uint32_t*)(S + EB2E);
    const uint32_t* B2a = (const uint32_t*)(S + EB2A);
    float* eagg = S + EEAGG;
    int* srcs = (int*)(S + EIX);
    int* dsts = srcs + 64;
    int* gidx = dsts + 64;
    const int t = threadIdx.x;
    const int w = t >> 5, lane = t & 31;
    const int q = lane & 3;
    const int r0 = (w & 3) * 16 + (lane >> 2), r1 = r0 + 8;
    const int eb = blockIdx.x * 64;

    if (t < 64) {
        int s_ = ei[eb + t], d_ = ei[Ee + eb + t];
        srcs[t] = s_; dsts[t] = d_; gidx[t] = batch[s_];
    }
#pragma unroll
    for (int i = 0; i < 4; i++) eagg[t + i * 256] = 0.f;

    // Stage ALL four B packs (16 KB each) once
#pragma unroll
    for (int i = 0; i < 4; i++) cp16(S + EB1E + (t + i * 256) * 4, (const float*)g_B1e + (t + i * 256) * 4);
#pragma unroll
    for (int i = 0; i < 4; i++) cp16(S + EB1A + (t + i * 256) * 4, (const float*)g_B1a + (t + i * 256) * 4);
#pragma unroll
    for (int i = 0; i < 4; i++) cp16(S + EB2E + (t + i * 256) * 4, (const float*)g_B2e + (t + i * 256) * 4);
#pragma unroll
    for (int i = 0; i < 4; i++) cp16(S + EB2A + (t + i * 256) * 4, (const float*)g_B2a + (t + i * 256) * 4);
    cp_commit();

    // Build A = e tile as fp16x2 words (words 0..31 per row)
    for (int i = t; i < 1024; i += 256) {
        int m = i >> 4, k4 = (i & 15) << 2;
        float4 v = *(const float4*)&e[(size_t)(eb + m) * 64 + k4];
        uint2 pw = make_uint2(pack_h2(v.x, v.y), pack_h2(v.z, v.w));
        *(uint2*)&AH32[m * 68 + (k4 >> 1)] = pw;
    }

    const int s0 = srcs[r0], d0 = dsts[r0], gg0 = gidx[r0];
    const int s1 = srcs[r1], d1 = dsts[r1], gg1 = gidx[r1];
    const __half* xs0 = g_Xs + (size_t)s0 * 256;
    const __half* xd0 = g_Xd + (size_t)d0 * 256;
    const __half* xs1 = g_Xs + (size_t)s1 * 256;
    const __half* xd1 = g_Xd + (size_t)d1 * 256;
    pfL2(xs0 + 2 * q * 32); pfL2(xd0 + 2 * q * 32);
    pfL2(xs1 + 2 * q * 32); pfL2(xd1 + 2 * q * 32);

    cp_wait<0>();
    __syncthreads();

    // ======== MLP_e ========
    float c1[8][4];
#pragma unroll
    for (int i = 0; i < 8; i++) { c1[i][0]=0.f; c1[i][1]=0.f; c1[i][2]=0.f; c1[i][3]=0.f; }
    gemm1h(AH32, B1e, w, lane, c1);
    __syncthreads();                       // A reads done before H overwrite
    epi_h(AH32, c1, xs0, xd0, g_U1e + gg0 * 128, xs1, xd1, g_U1e + gg1 * 128,
          r0, r1, (w >> 2) * 64, q);
    __syncthreads();                       // H visible

    float c2[4][4];
#pragma unroll
    for (int i = 0; i < 4; i++) { c2[i][0]=0.f; c2[i][1]=0.f; c2[i][2]=0.f; c2[i][3]=0.f; }
    gemm2h(AH32, B2e, w, lane, c2);
    __syncthreads();                       // H reads done before splice

    // Epilogue2: e_new = C2 + be2 (f32) ; e_out ; splice fp16 into A ; eagg
    float en[4][4];
    const int nb2 = (w >> 2) * 32;
#pragma unroll
    for (int nt = 0; nt < 4; nt++) {
        int n = nb2 + nt * 8 + 2 * q;
        float2 b = *(const float2*)(be2 + n);
        en[nt][0] = c2[nt][0] + b.x; en[nt][1] = c2[nt][1] + b.y;
        en[nt][2] = c2[nt][2] + b.x; en[nt][3] = c2[nt][3] + b.y;
        *(float2*)&e_out[(size_t)(eb + r0) * 64 + n] = make_float2(en[nt][0], en[nt][1]);
        *(float2*)&e_out[(size_t)(eb + r1) * 64 + n] = make_float2(en[nt][2], en[nt][3]);
        AH32[r0 * 68 + (n >> 1)] = pack_h2(en[nt][0], en[nt][1]);
        AH32[r1 * 68 + (n >> 1)] = pack_h2(en[nt][2], en[nt][3]);
        atomicAdd(&eagg[gg0 * 64 + n],     en[nt][0]);
        atomicAdd(&eagg[gg0 * 64 + n + 1], en[nt][1]);
        atomicAdd(&eagg[gg1 * 64 + n],     en[nt][2]);
        atomicAdd(&eagg[gg1 * 64 + n + 1], en[nt][3]);
    }
    __syncthreads();                       // splice + eagg complete
    {
        int g = t >> 4, c4 = (t & 15) << 2;
        const float* p = &eagg[g * 64 + c4];
        red4(&g_eagg[g * 64 + c4], p[0], p[1], p[2], p[3]);
    }

    // ======== MLP_a ========
#pragma unroll
    for (int i = 0; i < 8; i++) { c1[i][0]=0.f; c1[i][1]=0.f; c1[i][2]=0.f; c1[i][3]=0.f; }
    gemm1h(AH32, B1a, w, lane, c1);
    __syncthreads();
    epi_h(AH32, c1, xs0 + 128, xd0 + 128, g_U1a + gg0 * 128,
          xs1 + 128, xd1 + 128, g_U1a + gg1 * 128, r0, r1, (w >> 2) * 64, q);
    __syncthreads();

#pragma unroll
    for (int i = 0; i < 4; i++) { c2[i][0]=0.f; c2[i][1]=0.f; c2[i][2]=0.f; c2[i][3]=0.f; }
    gemm2h(AH32, B2a, w, lane, c2);

    // Epilogue4: scatter e_new * sigmoid(C2a + ba2)
#pragma unroll
    for (int nt = 0; nt < 4; nt++) {
        int n = nb2 + nt * 8 + 2 * q;
        float2 b = *(const float2*)(ba2 + n);
        float w00 = en[nt][0] / (1.f + __expf(-(c2[nt][0] + b.x)));
        float w01 = en[nt][1] / (1.f + __expf(-(c2[nt][1] + b.y)));
        float w10 = en[nt][2] / (1.f + __expf(-(c2[nt][2] + b.x)));
        float w11 = en[nt][3] / (1.f + __expf(-(c2[nt][3] + b.y)));
        red2(&g_agg[(size_t)d0 * 64 + n], w00, w01);
        red2(&g_agg[(size_t)d1 * 64 + n], w10, w11);
    }
}

// ===========================================================================
// FFMA2 helpers for node / prep kernels (proven, unchanged)
// ===========================================================================
__device__ __forceinline__ void stage_w1(const float* __restrict__ Wg, int kt,
                                         float* __restrict__ dst, int t) {
    const float* src = Wg + (size_t)kt * 32 * 128;
#pragma unroll
    for (int i = 0; i < 4; i++) {
        int idx = t + i * 256;
        int r = idx >> 5, c4 = (idx & 31) << 2;
        cp16(dst + r * 128 + c4, src + r * 128 + c4);
    }
}
__device__ __forceinline__ void stage_w2(const float* __restrict__ Wg, int kt,
                                         float* __restrict__ dst, int t) {
    const float* src = Wg + (size_t)kt * 64 * 64;
#pragma unroll
    for (int i = 0; i < 4; i++) {
        int idx = t + i * 256;
        int r = idx >> 4, c4 = (idx & 15) << 2;
        cp16(dst + r * 64 + c4, src + r * 64 + c4);
    }
}

template<int KTOT>
__device__ __forceinline__ void gemm_h(const float* __restrict__ A,
                                       const float* __restrict__ Wg,
                                       const uint64_t (&ini)[4][4],
                                       float* __restrict__ Hs,
                                       float* __restrict__ sW, int t)
{
    const int tx = t & 15, ty = t >> 4;
    uint64_t acc[4][4];
#pragma unroll
    for (int i = 0; i < 4; i++)
#pragma unroll
        for (int p = 0; p < 4; p++) acc[i][p] = ini[i][p];
    constexpr int NT = KTOT / 32;
    stage_w1(Wg, 0, sW, t);
    cp_commit();
#pragma unroll
    for (int kt = 0; kt < NT; kt++) {
        if (kt + 1 < NT) {
            stage_w1(Wg, kt + 1, sW + ((kt + 1) & 1) * 4096, t);
            cp_commit();
            cp_wait<1>();
        } else cp_wait<0>();
        __syncthreads();
        const float* W = sW + (kt & 1) * 4096;
#pragma unroll
        for (int kk = 0; kk < 32; kk++) {
            int k = kt * 32 + kk;
            float4 a = *(const float4*)(A + k * 64 + ((ty ^ ((k >> 2) & 15)) << 2));
            ulonglong2 w01 = *(const ulonglong2*)(W + kk * 128 + tx * 8);
            ulonglong2 w23 = *(const ulonglong2*)(W + kk * 128 + tx * 8 + 4);
            uint64_t a0 = rep2(a.x), a1 = rep2(a.y), a2 = rep2(a.z), a3 = rep2(a.w);
            fma2(acc[0][0], a0, w01.x); fma2(acc[0][1], a0, w01.y);
            fma2(acc[0][2], a0, w23.x); fma2(acc[0][3], a0, w23.y);
            fma2(acc[1][0], a1, w01.x); fma2(acc[1][1], a1, w01.y);
            fma2(acc[1][2], a1, w23.x); fma2(acc[1][3], a1, w23.y);
            fma2(acc[2][0], a2, w01.x); fma2(acc[2][1], a2, w01.y);
            fma2(acc[2][2], a2, w23.x); fma2(acc[2][3], a2, w23.y);
            fma2(acc[3][0], a3, w01.x); fma2(acc[3][1], a3, w01.y);
            fma2(acc[3][2], a3, w23.x); fma2(acc[3][3], a3, w23.y);
        }
        __syncthreads();
    }
#pragma unroll
    for (int i = 0; i < 4; i++)
#pragma unroll
        for (int p = 0; p < 4; p++) {
            float2 v = unpack2(acc[i][p]);
            int h0 = tx * 8 + p * 2;
            int c = ((ty ^ ((h0 >> 2) & 15)) << 2) | i;
            Hs[h0 * 64 + c]       = fmaxf(v.x, 0.f);
            Hs[(h0 + 1) * 64 + c] = fmaxf(v.y, 0.f);
        }
    __syncthreads();
}

__device__ __forceinline__ void gemm_o(const float* __restrict__ Hs,
                                       const float* __restrict__ Wg,
                                       const float* __restrict__ b2,
                                       float* __restrict__ sW, int t,
                                       float o[4][4])
{
    const int tx = t & 15, ty = t >> 4;
    uint64_t b0 = *(const uint64_t*)(b2 + tx * 4);
    uint64_t b1 = *(const uint64_t*)(b2 + tx * 4 + 2);
    uint64_t acc[4][2];
#pragma unroll
    for (int i = 0; i < 4; i++) { acc[i][0] = b0; acc[i][1] = b1; }
    stage_w2(Wg, 0, sW, t);
    cp_commit();
#pragma unroll
    for (int kt = 0; kt < 2; kt++) {
        if (kt == 0) { stage_w2(Wg, 1, sW + 4096, t); cp_commit(); cp_wait<1>(); }
        else cp_wait<0>();
        __syncthreads();
        const float* W = sW + kt * 4096;
#pragma unroll 8
        for (int kk = 0; kk < 64; kk++) {
            int k = kt * 64 + kk;
            float4 a = *(const float4*)(Hs + k * 64 + ((ty ^ ((k >> 2) & 15)) << 2));
            ulonglong2 w = *(const ulonglong2*)(W + kk * 64 + tx * 4);
            uint64_t a0 = rep2(a.x), a1 = rep2(a.y), a2 = rep2(a.z), a3 = rep2(a.w);
            fma2(acc[0][0], a0, w.x); fma2(acc[0][1], a0, w.y);
            fma2(acc[1][0], a1, w.x); fma2(acc[1][1], a1, w.y);
            fma2(acc[2][0], a2, w.x); fma2(acc[2][1], a2, w.y);
            fma2(acc[3][0], a3, w.x); fma2(acc[3][1], a3, w.y);
        }
        __syncthreads();
    }
#pragma unroll
    for (int i = 0; i < 4; i++)
#pragma unroll
        for (int p = 0; p < 2; p++) {
            float2 v = unpack2(acc[i][p]);
            o[i][p * 2]     = v.x;
            o[i][p * 2 + 1] = v.y;
        }
}

// ---------------------------------------------------------------------------
#define SMN_A  0
#define SMN_W  4096
#define SMN_H  12288
#define SMN_IX 20480
#define SMN_FLOATS (20480 + 64)

__global__ void __launch_bounds__(256, 2)
node_kernel(const int* __restrict__ batch,
            const float* __restrict__ Wn1, const float* __restrict__ Wn2,
            const float* __restrict__ bn2,
            float* __restrict__ x_out)
{
    extern __shared__ float smem[];
    float* A  = smem + SMN_A;
    float* sW = smem + SMN_W;
    float* Hs = smem + SMN_H;
    int* gid  = (int*)(smem + SMN_IX);
    const int t = threadIdx.x;
    const int nb = blockIdx.x * 64;

    if (t < 64) {
        int r = nb + t; if (r >= Nn) r = Nn - 1;
        gid[t] = batch[r];
    }
    __syncthreads();

    for (int i = t; i < 1024; i += 256) {
        int m = i >> 4, k4 = (i & 15) << 2;
        int r = nb + m; if (r >= Nn) r = Nn - 1;
        int c = ((((m >> 2) ^ (k4 >> 2)) & 15) << 2) | (m & 3);
        float4 v = *(const float4*)&g_agg[(size_t)r * 64 + k4];
        A[k4 * 64 + c] = v.x; A[(k4 + 1) * 64 + c] = v.y;
        A[(k4 + 2) * 64 + c] = v.z; A[(k4 + 3) * 64 + c] = v.w;
    }

    const int tx = t & 15, ty = t >> 4;
    uint64_t ini[4][4];
#pragma unroll
    for (int i = 0; i < 4; i++) {
        int row = ty * 4 + i;
        int r = nb + row; if (r >= Nn) r = Nn - 1;
        const float* up = g_U1n + gid[row] * 128 + tx * 8;
        const float* xn = g_Xn + (size_t)r * 128 + tx * 8;
#pragma unroll
        for (int p = 0; p < 4; p++)
            ini[i][p] = add2(*(const uint64_t*)(up + p * 2),
                             *(const uint64_t*)(xn + p * 2));
    }
    __syncthreads();

    gemm_h<64>(A, Wn1 + 64 * 128, ini, Hs, sW, t);
    float xo[4][4];
    gemm_o(Hs, Wn2, bn2, sW, t, xo);
    __syncthreads();

    float* nagg = Hs;
#pragma unroll
    for (int i = 0; i < 4; i++) nagg[t + i * 256] = 0.f;
    __syncthreads();

#pragma unroll
    for (int i = 0; i < 4; i++) {
        int row = ty * 4 + i;
        int r = nb + row;
        if (r < Nn) {
            *(float4*)&x_out[(size_t)r * 64 + tx * 4] =
                make_float4(xo[i][0], xo[i][1], xo[i][2], xo[i][3]);
            int g = gid[row];
#pragma unroll
            for (int j = 0; j < 4; j++)
                atomicAdd(&nagg[g * 64 + tx * 4 + j], xo[i][j]);
        }
    }
    __syncthreads();
    {
        int g = t >> 4, c4 = (t & 15) << 2;
        const float* p = &nagg[g * 64 + c4];
        red4(&g_nagg[g * 64 + c4], p[0], p[1], p[2], p[3]);
    }
}

// ---------------------------------------------------------------------------
#define SPT_FLOATS 12288

__global__ void __launch_bounds__(256, 2)
prep_tables(const float* __restrict__ x,
            const float* __restrict__ We1, const float* __restrict__ Wa1,
            const float* __restrict__ Wn1)
{
    extern __shared__ float smem[];
    float* A  = smem;
    float* sW = smem + 4096;
    const int t = threadIdx.x;
    const int nb = blockIdx.x * 64;
    const int tx = t & 15, ty = t >> 4;

    for (int i = t; i < 1024; i += 256) {
        int m = i >> 4, k4 = (i & 15) << 2;
        int r = nb + m; if (r >= Nn) r = Nn - 1;
        int c = ((((m >> 2) ^ (k4 >> 2)) & 15) << 2) | (m & 3);
        float4 v = *(const float4*)&x[(size_t)r * 64 + k4];
        A[k4 * 64 + c] = v.x; A[(k4 + 1) * 64 + c] = v.y;
        A[(k4 + 2) * 64 + c] = v.z; A[(k4 + 3) * 64 + c] = v.w;
    }
    __syncthreads();

    const float* Ws[5] = { We1, Wa1, We1 + 64 * 128, Wa1 + 64 * 128, Wn1 };
    const int stride[5] = { 256, 256, 256, 256, 128 };

#pragma unroll 1
    for (int seg = 0; seg < 5; seg++) {
        const float* W = Ws[seg];
        stage_w1(W, 0, sW, t);
        stage_w1(W, 1, sW + 4096, t);
        cp_commit();
        cp_wait<0>();
        __syncthreads();
        uint64_t acc[4][4];
#pragma unroll
        for (int i = 0; i < 4; i++)
#pragma unroll
            for (int p = 0; p < 4; p++) acc[i][p] = 0ull;
#pragma unroll
        for (int kt = 0; kt < 2; kt++) {
            const float* Wp = sW + kt * 4096;
#pragma unroll
            for (int kk = 0; kk < 32; kk++) {
                int k = kt * 32 + kk;
                float4 a = *(const float4*)(A + k * 64 + ((ty ^ ((k >> 2) & 15)) << 2));
                ulonglong2 w01 = *(const ulonglong2*)(Wp + kk * 128 + tx * 8);
                ulonglong2 w23 = *(const ulonglong2*)(Wp + kk * 128 + tx * 8 + 4);
                uint64_t a0 = rep2(a.x), a1 = rep2(a.y), a2 = rep2(a.z), a3 = rep2(a.w);
                fma2(acc[0][0], a0, w01.x); fma2(acc[0][1], a0, w01.y);
                fma2(acc[0][2], a0, w23.x); fma2(acc[0][3], a0, w23.y);
                fma2(acc[1][0], a1, w01.x); fma2(acc[1][1], a1, w01.y);
                fma2(acc[1][2], a1, w23.x); fma2(acc[1][3], a1, w23.y);
                fma2(acc[2][0], a2, w01.x); fma2(acc[2][1], a2, w01.y);
                fma2(acc[2][2], a2, w23.x); fma2(acc[2][3], a2, w23.y);
                fma2(acc[3][0], a3, w01.x); fma2(acc[3][1], a3, w01.y);
                fma2(acc[3][2], a3, w23.x); fma2(acc[3][3], a3, w23.y);
            }
        }
#pragma unroll
        for (int i = 0; i < 4; i++) {
            int r = nb + ty * 4 + i;
            if (r < Nn) {
                float2 v0 = unpack2(acc[i][0]), v1 = unpack2(acc[i][1]);
                float2 v2 = unpack2(acc[i][2]), v3 = unpack2(acc[i][3]);
                if (seg < 4) {
                    // fp16 tables: Xs (segs 0,1), Xd (segs 2,3); +128 for the a-half
                    __half* base = (seg < 2) ? g_Xs : g_Xd;
                    int half_off = (seg & 1) * 128;
                    __half* op = base + (size_t)r * 256 + half_off + tx * 8;
                    uint4 pw;
                    pw.x = pack_h2(v0.x, v0.y);
                    pw.y = pack_h2(v1.x, v1.y);
                    pw.z = pack_h2(v2.x, v2.y);
                    pw.w = pack_h2(v3.x, v3.y);
                    *(uint4*)op = pw;
                } else {
                    float* op = g_Xn + (size_t)r * 128 + tx * 8;
                    *(float4*)op       = make_float4(v0.x, v0.y, v1.x, v1.y);
                    *(float4*)(op + 4) = make_float4(v2.x, v2.y, v3.x, v3.y);
                }
            }
        }
        __syncthreads();
    }
}

// ---------------------------------------------------------------------------
__global__ void __launch_bounds__(128)
global_kernel(const float* __restrict__ u,
              const float* __restrict__ Wg1, const float* __restrict__ bg1,
              const float* __restrict__ Wg2, const float* __restrict__ bg2,
              float* __restrict__ u_out)
{
    __shared__ float in[192];
    __shared__ float hid[128];
    const int g = blockIdx.x, t = threadIdx.x;
    if (t < 64) {
        in[t]       = u[g * 64 + t];
        in[64 + t]  = g_nagg[g * 64 + t];
        in[128 + t] = g_eagg[g * 64 + t];
    }
    __syncthreads();
    float acc = bg1[t];
#pragma unroll 8
    for (int k = 0; k < 192; k++) acc += in[k] * Wg1[(size_t)k * 128 + t];
    hid[t] = fmaxf(acc, 0.f);
    __syncthreads();
    if (t < 64) {
        float a2 = bg2[t];
#pragma unroll 8
        for (int k = 0; k < 128; k++) a2 += hid[k] * Wg2[(size_t)k * 64 + t];
        u_out[g * 64 + t] = a2;
    }
}

// ---------------------------------------------------------------------------
// Prep: zero aggregates, U1 tables, fp16 fragment-packed weight tiles
// ---------------------------------------------------------------------------
__global__ void __launch_bounds__(256)
prep_kernel(const float* __restrict__ u,
            const float* __restrict__ We1, const float* __restrict__ be1,
            const float* __restrict__ Wa1, const float* __restrict__ ba1,
            const float* __restrict__ Wn1, const float* __restrict__ bn1,
            const float* __restrict__ We2, const float* __restrict__ Wa2)
{
    const int b = blockIdx.x, t = threadIdx.x;
    size_t idx = (size_t)b * 256 + t;
    const size_t n4 = (size_t)Nn * Dd / 4;
    float4 z = make_float4(0.f, 0.f, 0.f, 0.f);
    for (size_t i = idx; i < n4; i += (size_t)gridDim.x * 256) ((float4*)g_agg)[i] = z;
    if (idx < 256) { ((float4*)g_nagg)[idx] = z; ((float4*)g_eagg)[idx] = z; }
    if (b < 3) {
        const float* W    = (b == 0) ? We1 + 192 * 128 : (b == 1) ? Wa1 + 192 * 128 : Wn1 + 128 * 128;
        const float* bias = (b == 0) ? be1 : (b == 1) ? ba1 : bn1;
        float* out        = (b == 0) ? g_U1e : (b == 1) ? g_U1a : g_U1n;
        for (int i = t; i < Gg * Hh; i += 256) {
            int g = i >> 7, h = i & 127;
            float acc = bias[h];
#pragma unroll 8
            for (int k = 0; k < 64; k++) acc += u[g * 64 + k] * W[(size_t)k * 128 + h];
            out[i] = acc;
        }
    } else if (b < 5) {
        // B1 pack (K=64, N=128): src row 128+k, col n of W1
        const float* src = (b == 3) ? We1 : Wa1;
        __half* dst = (b == 3) ? g_B1e : g_B1a;
        for (int i = t; i < 8192; i += 256) {
            int n = i >> 6, k = i & 63;
            float v = src[(size_t)(128 + k) * 128 + n];
            int kl = k & 15;
            int reg = kl >> 3, lq = (kl & 7) >> 1, hw = kl & 1;
            int lane = (n & 7) * 4 + lq;
            int pos = (((n >> 3) * 4 + (k >> 4)) << 6) + 2 * lane + reg;
            dst[2 * pos + hw] = __float2half_rn(v);
        }
    } else if (b < 7) {
        // B2 pack (K=128, N=64): src W2[k][n]
        const float* src = (b == 5) ? We2 : Wa2;
        __half* dst = (b == 5) ? g_B2e : g_B2a;
        for (int i = t; i < 8192; i += 256) {
            int k = i >> 6, n = i & 63;
            float v = src[(size_t)k * 64 + n];
            int kl = k & 15;
            int reg = kl >> 3, lq = (kl & 7) >> 1, hw = kl & 1;
            int lane = (n & 7) * 4 + lq;
            int pos = (((n >> 3) * 8 + (k >> 4)) << 6) + 2 * lane + reg;
            dst[2 * pos + hw] = __float2half_rn(v);
        }
    }
}

extern "C" void kernel_launch(void* const* d_in, const int* in_sizes, int n_in,
                              void* d_out, int out_size)
{
    const float* x     = (const float*)d_in[0];
    const int*   ei    = (const int*)d_in[1];
    const float* e     = (const float*)d_in[2];
    const float* u     = (const float*)d_in[3];
    const int*   batch = (const int*)d_in[4];
    const float* We1 = (const float*)d_in[5];
    const float* be1 = (const float*)d_in[6];
    const float* We2 = (const float*)d_in[7];
    const float* be2 = (const float*)d_in[8];
    const float* Wa1 = (const float*)d_in[9];
    const float* ba1 = (const float*)d_in[10];
    const float* Wa2 = (const float*)d_in[11];
    const float* ba2 = (const float*)d_in[12];
    const float* Wn1 = (const float*)d_in[13];
    const float* bn1 = (const float*)d_in[14];
    const float* Wn2 = (const float*)d_in[15];
    const float* bn2 = (const float*)d_in[16];
    const float* Wg1 = (const float*)d_in[17];
    const float* bg1 = (const float*)d_in[18];
    const float* Wg2 = (const float*)d_in[19];
    const float* bg2 = (const float*)d_in[20];

    float* out   = (float*)d_out;
    float* x_out = out;
    float* e_out = out + (size_t)Nn * Dd;
    float* u_out = out + (size_t)Nn * Dd + (size_t)Ee * Dd;

    cudaFuncSetAttribute(edge_kernel, cudaFuncAttributeMaxDynamicSharedMemorySize,
                         E_FLOATS * 4);
    cudaFuncSetAttribute(node_kernel, cudaFuncAttributeMaxDynamicSharedMemorySize,
                         SMN_FLOATS * 4);
    cudaFuncSetAttribute(prep_tables, cudaFuncAttributeMaxDynamicSharedMemorySize,
                         SPT_FLOATS * 4);

    prep_kernel<<<3125, 256>>>(u, We1, be1, Wa1, ba1, Wn1, bn1, We2, Wa2);
    prep_tables<<<(Nn + 63) / 64, 256, SPT_FLOATS * 4>>>(x, We1, Wa1, Wn1);
    edge_kernel<<<Ee / 64, 256, E_FLOATS * 4>>>(ei, e, batch, be2, ba2, e_out);
    node_kernel<<<(Nn + 63) / 64, 256, SMN_FLOATS * 4>>>(batch, Wn1, Wn2, bn2, x_out);
    global_kernel<<<Gg, 128>>>(u, Wg1, bg1, Wg2, bg2, u_out);
}